// round 11
// baseline (speedup 1.0000x reference)
#include <cuda_runtime.h>
#include <cuda_bf16.h>
#include <math.h>
#include <stdint.h>

#define SS 64      // source length
#define BB 32      // batch
#define UU 512     // hidden
#define GG 1536    // 3*U
#define EE 300     // embed dim
#define AD 512     // attention dim
#define VTT 30000  // target vocab
#define TT 32      // target length
#define TM1 31     // T-1 decode steps
#define FF 1836    // 3U + E  (logits feature dim)
#define KX 1324    // 2U + E  (decoder GRU input dim)
#define H2 1024    // 2U
#define MTOT (TM1*BB)   // 992

// logits GEMM padded dims
#define KP 1856         // 29 * 64 (A bf16 row stride)
#define NP 30080        // 235 * 128
#define MP 1024         // 8 * 128
#define KITER 29

// ---------------- device scratch (static, no allocation) ----------------
__device__ float g_emb_s[SS*BB*EE];
__device__ float g_gi_f[SS*BB*GG];
__device__ float g_gi_b[SS*BB*GG];
__device__ float g_outs_f[SS*BB*UU];
__device__ float g_outs_b[SS*BB*UU];
__device__ float g_h[2][2][BB*UU];          // [dir][parity]
__device__ float g_ghp[2][4][BB*GG];        // encoder gh split-K partials
__device__ float g_enc[BB*SS*H2];           // enc_bt (b,s,2U)
__device__ float g_hfb[BB*H2];
__device__ float g_state[2][BB*UU];         // decoder state ping-pong
__device__ float g_encproj[BB*SS*AD];
__device__ float g_embt[TM1*BB*EE];
__device__ float g_ctx[BB*H2];
__device__ float g_dgp[2][4][BB*GG];        // decoder gi/gh split-K partials
__device__ float g_feat[(long)TM1*BB*FF];

// pre-split bf16 A operand (A is tiny; W is converted in-kernel)
__device__ __nv_bfloat16 g_ahi[(long)MP*KP];
__device__ __nv_bfloat16 g_alo[(long)MP*KP];

__device__ __forceinline__ float sigm(float x) { return 1.0f / (1.0f + expf(-x)); }

// ---- packed f32x2 helpers (FFMA2 only reachable via PTX) ----
__device__ __forceinline__ unsigned long long pk2(float x, float y) {
    unsigned long long r;
    asm("mov.b64 %0, {%1, %2};" : "=l"(r) : "f"(x), "f"(y));
    return r;
}
__device__ __forceinline__ void fma2(unsigned long long& d, unsigned long long a, unsigned long long b) {
    asm("fma.rn.f32x2 %0, %1, %2, %0;" : "+l"(d) : "l"(a), "l"(b));
}
__device__ __forceinline__ float2 upk2(unsigned long long v) {
    float2 f;
    asm("mov.b64 {%0, %1}, %2;" : "=f"(f.x), "=f"(f.y) : "l"(v));
    return f;
}

// ---- bf16 split: hi = bf16(a,b), lo = bf16 of residuals; low 16 bits = first elem ----
__device__ __forceinline__ void split2(float a, float b, uint32_t& hi, uint32_t& lo) {
    uint32_t h;
    asm("cvt.rn.bf16x2.f32 %0, %1, %2;" : "=r"(h) : "f"(b), "f"(a)); // hi16=b, lo16=a
    float ha = __uint_as_float(h << 16);
    float hb = __uint_as_float(h & 0xFFFF0000u);
    float la = a - ha, lb = b - hb;
    uint32_t l;
    asm("cvt.rn.bf16x2.f32 %0, %1, %2;" : "=r"(l) : "f"(lb), "f"(la));
    hi = h; lo = l;
}

// ---------------- tiny utility kernels ----------------
__global__ void k_zero(float* p, int n) {
    int i = blockIdx.x * blockDim.x + threadIdx.x;
    if (i < n) p[i] = 0.0f;
}

__global__ void k_gather_src(const float* __restrict__ emb, const int* __restrict__ src) {
    int idx = blockIdx.x * blockDim.x + threadIdx.x;
    if (idx >= SS*BB*EE) return;
    int e = idx % EE; int tb = idx / EE;
    g_emb_s[idx] = emb[(long)src[tb]*EE + e];
}

__global__ void k_gather_trg(const float* __restrict__ emb, const int* __restrict__ trg) {
    int idx = blockIdx.x * blockDim.x + threadIdx.x;
    if (idx >= TM1*BB*EE) return;
    int e = idx % EE; int tb = idx / EE;
    g_embt[idx] = emb[(long)trg[tb]*EE + e];
}

__global__ void k_concat_enc() {
    int idx = blockIdx.x * blockDim.x + threadIdx.x;
    if (idx >= BB*SS*H2) return;
    int h = idx % H2; int bs = idx / H2;
    int s = bs % SS, b = bs / SS;
    float v = (h < UU) ? g_outs_f[((long)s*BB + b)*UU + h]
                       : g_outs_b[((long)s*BB + b)*UU + h - UU];
    g_enc[idx] = v;
}

__global__ void k_concat_hfb() {
    int idx = blockIdx.x * blockDim.x + threadIdx.x;
    if (idx >= BB*H2) return;
    int h = idx % H2; int b = idx / H2;
    float v = (h < UU) ? g_outs_f[((long)(SS-1)*BB + b)*UU + h]
                       : g_outs_b[(long)b*UU + h - UU];
    g_hfb[idx] = v;
}

// split feat (full FF, zero-padded to KP) into bf16 hi/lo
__global__ void k_split_a() {
    long idx = (long)blockIdx.x * blockDim.x + threadIdx.x;
    if (idx >= (long)MP*KP) return;
    int k = (int)(idx % KP); int m = (int)(idx / KP);
    float x = (m < MTOT && k < FF) ? g_feat[(long)m*FF + k] : 0.0f;
    __nv_bfloat16 h = __float2bfloat16(x);
    g_ahi[idx] = h;
    g_alo[idx] = __float2bfloat16(x - __bfloat162float(h));
}

// ---------------- fp32x2 tiled GEMM: C = act(A @ W^T + bias) ----------------
__global__ void __launch_bounds__(256, 2)
k_gemm(const float* __restrict__ Ap, int lda,
       const float* __restrict__ Wp, int ldw, int woff,
       const float* __restrict__ bias,
       float* __restrict__ Cp, int ldc,
       int M, int N, int K, int act)
{
    __shared__ float sA[16][128];
    __shared__ float sW[16][128];
    int tid = threadIdx.x;
    int m0 = blockIdx.y * 128, n0 = blockIdx.x * 128;
    int tr = tid & 15, tc = tid >> 4;

    unsigned long long acc[8][4];
    #pragma unroll
    for (int i = 0; i < 8; i++)
        #pragma unroll
        for (int j = 0; j < 4; j++) acc[i][j] = 0ull;

    int r  = tid >> 2;
    int kq = (tid & 3) * 4;

    for (int k0 = 0; k0 < K; k0 += 16) {
        bool kok = (k0 + kq) < K;
        #pragma unroll
        for (int h = 0; h < 2; h++) {
            int row = r + h * 64;
            float4 va = make_float4(0.f, 0.f, 0.f, 0.f);
            int m = m0 + row;
            if (kok && m < M) va = *reinterpret_cast<const float4*>(&Ap[(long)m*lda + k0 + kq]);
            sA[kq+0][row] = va.x; sA[kq+1][row] = va.y;
            sA[kq+2][row] = va.z; sA[kq+3][row] = va.w;

            float4 vw = make_float4(0.f, 0.f, 0.f, 0.f);
            int n = n0 + row;
            if (kok && n < N) vw = *reinterpret_cast<const float4*>(&Wp[(long)n*ldw + woff + k0 + kq]);
            sW[kq+0][row] = vw.x; sW[kq+1][row] = vw.y;
            sW[kq+2][row] = vw.z; sW[kq+3][row] = vw.w;
        }
        __syncthreads();

        #pragma unroll
        for (int kk = 0; kk < 16; kk++) {
            float4 a0 = *reinterpret_cast<const float4*>(&sA[kk][tr*8]);
            float4 a1 = *reinterpret_cast<const float4*>(&sA[kk][tr*8 + 4]);
            unsigned long long bp[4];
            #pragma unroll
            for (int j = 0; j < 4; j++)
                bp[j] = *reinterpret_cast<const unsigned long long*>(&sW[kk][tc*8 + 2*j]);
            float av[8] = {a0.x, a0.y, a0.z, a0.w, a1.x, a1.y, a1.z, a1.w};
            #pragma unroll
            for (int i = 0; i < 8; i++) {
                unsigned long long ap = pk2(av[i], av[i]);
                #pragma unroll
                for (int j = 0; j < 4; j++) fma2(acc[i][j], ap, bp[j]);
            }
        }
        __syncthreads();
    }

    #pragma unroll
    for (int i = 0; i < 8; i++) {
        int m = m0 + tr*8 + i;
        if (m >= M) continue;
        #pragma unroll
        for (int j = 0; j < 4; j++) {
            float2 v = upk2(acc[i][j]);
            int n = n0 + tc*8 + 2*j;
            if (n < N) {
                float c = v.x + (bias ? bias[n] : 0.0f);
                if (act) c = tanhf(c);
                Cp[(long)m*ldc + n] = c;
            }
            if (n + 1 < N) {
                float c = v.y + (bias ? bias[n+1] : 0.0f);
                if (act) c = tanhf(c);
                Cp[(long)m*ldc + n + 1] = c;
            }
        }
    }
}

// ================= mma.sync bf16 logits GEMM (W converted in-kernel) =================
__device__ __forceinline__ uint32_t smem_u32(const void* p) {
    uint32_t a;
    asm("{ .reg .u64 t; cvta.to.shared.u64 t, %1; cvt.u32.u64 %0, t; }" : "=r"(a) : "l"(p));
    return a;
}
__device__ __forceinline__ void cpa16(uint32_t dst, const void* src) {
    asm volatile("cp.async.cg.shared.global [%0], [%1], 16;" :: "r"(dst), "l"(src) : "memory");
}
__device__ __forceinline__ void cpa_commit() {
    asm volatile("cp.async.commit_group;" ::: "memory");
}
__device__ __forceinline__ void ldsm4(uint32_t* r, uint32_t addr) {
    asm volatile("ldmatrix.sync.aligned.m8n8.x4.shared.b16 {%0,%1,%2,%3}, [%4];"
        : "=r"(r[0]), "=r"(r[1]), "=r"(r[2]), "=r"(r[3]) : "r"(addr));
}
__device__ __forceinline__ void mma16816(float* d, const uint32_t* a, const uint32_t* b) {
    asm volatile("mma.sync.aligned.m16n8k16.row.col.f32.bf16.bf16.f32 "
        "{%0,%1,%2,%3}, {%4,%5,%6,%7}, {%8,%9}, {%0,%1,%2,%3};"
        : "+f"(d[0]), "+f"(d[1]), "+f"(d[2]), "+f"(d[3])
        : "r"(a[0]), "r"(a[1]), "r"(a[2]), "r"(a[3]), "r"(b[0]), "r"(b[1]));
}

// stage: Ahi 16K | Alo 16K | Whi 16K | Wlo 16K = 64KB; 2 stages = 128KB smem.
#define LSTG 65536
#define LOG_SMEM (2*LSTG)

__global__ void __launch_bounds__(256, 1)
k_logits_mma(const float* __restrict__ W, const float* __restrict__ bias,
             float* __restrict__ outp)
{
    extern __shared__ __align__(128) char smem[];
    uint32_t sb = smem_u32(smem);
    int tid = threadIdx.x;
    int wid = tid >> 5, lane = tid & 31;
    int wm = wid >> 2, wn = wid & 3;
    int grp = lane >> 3, lr = lane & 7;
    int m0 = blockIdx.x * 128;
    int n0 = blockIdx.y * 128;

    float acc[4][4][4];
    #pragma unroll
    for (int i = 0; i < 4; i++)
        #pragma unroll
        for (int j = 0; j < 4; j++)
            #pragma unroll
            for (int c = 0; c < 4; c++) acc[i][j][c] = 0.0f;

    // register-staged fp32 W tile (128 n-rows x 64 k per stage)
    float4 wbuf[2][8];

    auto loadW = [&](int it, float4* wr) {
        int k0 = it * 64;
        #pragma unroll
        for (int q = 0; q < 4; q++) {
            int u = tid + q * 256;
            int row = u >> 3, c = u & 7;
            int n = n0 + row;
            int k = k0 + c * 8;
            float4 v0 = make_float4(0.f,0.f,0.f,0.f), v1 = v0;
            if (n < VTT && k < FF) {
                const float* src = W + (long)n*FF + k;
                if (k + 8 <= FF) {
                    v0 = *reinterpret_cast<const float4*>(src);
                    v1 = *reinterpret_cast<const float4*>(src + 4);
                } else {
                    float tmp[8] = {0,0,0,0,0,0,0,0};
                    #pragma unroll
                    for (int j = 0; j < 8; j++) if (k + j < FF) tmp[j] = src[j];
                    v0 = make_float4(tmp[0],tmp[1],tmp[2],tmp[3]);
                    v1 = make_float4(tmp[4],tmp[5],tmp[6],tmp[7]);
                }
            }
            wr[2*q]   = v0;
            wr[2*q+1] = v1;
        }
    };

    auto stsW = [&](int s, const float4* wr) {
        char* base = smem + s * LSTG;
        #pragma unroll
        for (int q = 0; q < 4; q++) {
            int u = tid + q * 256;
            int row = u >> 3, c = u & 7;
            uint32_t off = row * 128 + (((uint32_t)(c ^ (row & 7))) << 4);
            float4 v0 = wr[2*q], v1 = wr[2*q+1];
            uint4 hi, lo;
            split2(v0.x, v0.y, hi.x, lo.x);
            split2(v0.z, v0.w, hi.y, lo.y);
            split2(v1.x, v1.y, hi.z, lo.z);
            split2(v1.z, v1.w, hi.w, lo.w);
            *reinterpret_cast<uint4*>(base + 32768 + off) = hi;
            *reinterpret_cast<uint4*>(base + 49152 + off) = lo;
        }
    };

    auto loadA = [&](int it, int s) {
        int k0 = it * 64;
        uint32_t base = sb + s * LSTG;
        #pragma unroll
        for (int q = 0; q < 4; q++) {
            int u = tid + q * 256;
            int row = u >> 3, c = u & 7;
            uint32_t off = row * 128 + (((uint32_t)(c ^ (row & 7))) << 4);
            long ga = (long)(m0 + row) * KP + k0 + c * 8;
            cpa16(base + off,          g_ahi + ga);
            cpa16(base + 16384 + off,  g_alo + ga);
        }
    };

    loadW(0, wbuf[0]);
    loadA(0, 0);
    cpa_commit();

    for (int it = 0; it < KITER; it++) {
        int s = it & 1;
        asm volatile("cp.async.wait_group 0;" ::: "memory");
        __syncthreads();                  // prior compute done + A(it) visible
        stsW(s, wbuf[it & 1]);
        if (it + 1 < KITER) {
            loadW(it + 1, wbuf[(it + 1) & 1]);   // LDG latency hidden by compute
            loadA(it + 1, s ^ 1);
            cpa_commit();
        }
        __syncthreads();                  // W smem visible

        uint32_t aAhi = sb + s*LSTG;
        uint32_t aAlo = aAhi + 16384;
        uint32_t aBhi = aAhi + 32768;
        uint32_t aBlo = aAhi + 49152;

        #pragma unroll
        for (int ks = 0; ks < 4; ks++) {
            uint32_t fa_hi[4][4], fa_lo[4][4];
            #pragma unroll
            for (int mt = 0; mt < 4; mt++) {
                int row = wm*64 + mt*16 + lr + (grp & 1) * 8;
                int c = 2*ks + (grp >> 1);
                uint32_t off = row * 128 + (((uint32_t)(c ^ (row & 7))) << 4);
                ldsm4(fa_hi[mt], aAhi + off);
                ldsm4(fa_lo[mt], aAlo + off);
            }
            uint32_t fb_hi[2][4], fb_lo[2][4];
            #pragma unroll
            for (int p = 0; p < 2; p++) {
                int nrow = wn*32 + p*16 + lr + (grp >> 1) * 8;
                int c = 2*ks + (grp & 1);
                uint32_t off = nrow * 128 + (((uint32_t)(c ^ (nrow & 7))) << 4);
                ldsm4(fb_hi[p], aBhi + off);
                ldsm4(fb_lo[p], aBlo + off);
            }
            #pragma unroll
            for (int mt = 0; mt < 4; mt++)
                #pragma unroll
                for (int nt = 0; nt < 4; nt++)
                    mma16816(acc[mt][nt], fa_hi[mt], &fb_hi[nt >> 1][(nt & 1) * 2]);
            #pragma unroll
            for (int mt = 0; mt < 4; mt++)
                #pragma unroll
                for (int nt = 0; nt < 4; nt++)
                    mma16816(acc[mt][nt], fa_lo[mt], &fb_hi[nt >> 1][(nt & 1) * 2]);
            #pragma unroll
            for (int mt = 0; mt < 4; mt++)
                #pragma unroll
                for (int nt = 0; nt < 4; nt++)
                    mma16816(acc[mt][nt], fa_hi[mt], &fb_lo[nt >> 1][(nt & 1) * 2]);
        }
    }

    int mrow = (lane >> 2);
    int ncol = (lane & 3) * 2;
    #pragma unroll
    for (int mt = 0; mt < 4; mt++) {
        #pragma unroll
        for (int nt = 0; nt < 4; nt++) {
            int n = n0 + wn*32 + nt*8 + ncol;
            if (n >= VTT) continue;
            float2 bv = *reinterpret_cast<const float2*>(&bias[n]);
            int m1 = m0 + wm*64 + mt*16 + mrow;
            int m2 = m1 + 8;
            if (m1 < MTOT) {
                float2 v = make_float2(acc[mt][nt][0] + bv.x, acc[mt][nt][1] + bv.y);
                *reinterpret_cast<float2*>(&outp[(long)m1*VTT + n]) = v;
            }
            if (m2 < MTOT) {
                float2 v = make_float2(acc[mt][nt][2] + bv.x, acc[mt][nt][3] + bv.y);
                *reinterpret_cast<float2*>(&outp[(long)m2*VTT + n]) = v;
            }
        }
    }
}

// ---------------- encoder recurrent step: gh partials (split-K) ----------------
__global__ void k_enc_gh(const float* __restrict__ Whh_f, const float* __restrict__ Whh_b, int par)
{
    __shared__ float sA[16][32];
    __shared__ float sW[16][64];
    int dir = blockIdx.z, kc = blockIdx.y;
    int n0 = blockIdx.x * 64;
    const float* W = dir ? Whh_b : Whh_f;
    const float* h = g_h[dir][par];
    int tid = threadIdx.x;
    int tm = tid & 15, tn = tid >> 4;
    float acc[2][4] = {};
    int kbase = kc * 128;

    for (int k0 = 0; k0 < 128; k0 += 16) {
        if (tid < 128) {
            int r = tid >> 2, kq = (tid & 3) * 4;
            #pragma unroll
            for (int j = 0; j < 4; j++)
                sA[kq+j][r] = h[r*UU + kbase + k0 + kq + j];
        }
        {
            int r = tid >> 2, kq = (tid & 3) * 4;
            #pragma unroll
            for (int j = 0; j < 4; j++)
                sW[kq+j][r] = W[(long)(n0+r)*UU + kbase + k0 + kq + j];
        }
        __syncthreads();
        #pragma unroll
        for (int kk = 0; kk < 16; kk++) {
            float2 a2 = *reinterpret_cast<const float2*>(&sA[kk][tm*2]);
            float4 b4 = *reinterpret_cast<const float4*>(&sW[kk][tn*4]);
            acc[0][0] = fmaf(a2.x, b4.x, acc[0][0]);
            acc[0][1] = fmaf(a2.x, b4.y, acc[0][1]);
            acc[0][2] = fmaf(a2.x, b4.z, acc[0][2]);
            acc[0][3] = fmaf(a2.x, b4.w, acc[0][3]);
            acc[1][0] = fmaf(a2.y, b4.x, acc[1][0]);
            acc[1][1] = fmaf(a2.y, b4.y, acc[1][1]);
            acc[1][2] = fmaf(a2.y, b4.z, acc[1][2]);
            acc[1][3] = fmaf(a2.y, b4.w, acc[1][3]);
        }
        __syncthreads();
    }
    float* out = &g_ghp[dir][kc][0];
    #pragma unroll
    for (int i = 0; i < 2; i++) {
        int b = tm*2 + i;
        #pragma unroll
        for (int j = 0; j < 4; j++)
            out[b*GG + n0 + tn*4 + j] = acc[i][j];
    }
}

__global__ void k_enc_gate(int tf, int tb, int par,
                           const float* __restrict__ bhh_f, const float* __restrict__ bhh_b)
{
    int idx = blockIdx.x * blockDim.x + threadIdx.x;
    if (idx >= 2*BB*UU) return;
    int u = idx & 511;
    int b = (idx >> 9) & 31;
    int dir = idx >> 14;
    const float* gi = dir ? (g_gi_b + (long)tb*BB*GG) : (g_gi_f + (long)tf*BB*GG);
    const float* bhh = dir ? bhh_b : bhh_f;
    float ghr = bhh[u], ghz = bhh[u+UU], ghn = bhh[u+2*UU];
    #pragma unroll
    for (int kc = 0; kc < 4; kc++) {
        const float* p = &g_ghp[dir][kc][b*GG];
        ghr += p[u]; ghz += p[u+UU]; ghn += p[u+2*UU];
    }
    float ir = gi[b*GG + u], iz = gi[b*GG + u + UU], inn = gi[b*GG + u + 2*UU];
    float r = sigm(ir + ghr);
    float z = sigm(iz + ghz);
    float n = tanhf(inn + r*ghn);
    float hp = g_h[dir][par][b*UU + u];
    float hn_ = (1.0f - z)*n + z*hp;
    g_h[dir][par^1][b*UU + u] = hn_;
    float* outs = dir ? (g_outs_b + (long)tb*BB*UU) : (g_outs_f + (long)tf*BB*UU);
    outs[b*UU + u] = hn_;
}

// ---------------- decoder attention (fused per batch element) ----------------
__global__ void k_dec_attn(int spar, const float* __restrict__ attn_W)
{
    int b = blockIdx.x;
    int tid = threadIdx.x;
    __shared__ float s_st[UU];
    __shared__ float s_tp[AD];
    __shared__ float s_sc[SS];
    __shared__ float s_red[2];

    const float* st = &g_state[spar][b*UU];
    for (int i = tid; i < UU; i += 256) s_st[i] = st[i];
    __syncthreads();

    for (int a = tid; a < AD; a += 256) {
        const float* w = attn_W + (long)a*GG;
        float acc = 0.0f;
        #pragma unroll 4
        for (int k = 0; k < UU; k += 4) {
            float4 wv = *reinterpret_cast<const float4*>(w + k);
            acc = fmaf(s_st[k],   wv.x, acc);
            acc = fmaf(s_st[k+1], wv.y, acc);
            acc = fmaf(s_st[k+2], wv.z, acc);
            acc = fmaf(s_st[k+3], wv.w, acc);
        }
        s_tp[a] = acc;
    }
    __syncthreads();

    {
        int s = tid >> 2, q = tid & 3;
        const float* ep = g_encproj + ((long)b*SS + s)*AD + q*128;
        const float* tp = s_tp + q*128;
        float partial = 0.0f;
        for (int a = 0; a < 128; a++) partial += tanhf(tp[a] + ep[a]);
        partial += __shfl_down_sync(0xffffffffu, partial, 2);
        partial += __shfl_down_sync(0xffffffffu, partial, 1);
        if (q == 0) s_sc[s] = partial;
    }
    __syncthreads();
    if (tid == 0) {
        float mx = s_sc[0];
        for (int s = 1; s < SS; s++) mx = fmaxf(mx, s_sc[s]);
        s_red[0] = mx;
    }
    __syncthreads();
    if (tid < SS) s_sc[tid] = expf(s_sc[tid] - s_red[0]);
    __syncthreads();
    if (tid == 0) {
        float sm = 0.0f;
        for (int s = 0; s < SS; s++) sm += s_sc[s];
        s_red[1] = 1.0f / sm;
    }
    __syncthreads();
    float inv = s_red[1];
    for (int h = tid; h < H2; h += 256) {
        const float* e = g_enc + (long)b*SS*H2 + h;
        float acc = 0.0f;
        #pragma unroll 8
        for (int s = 0; s < SS; s++) acc = fmaf(s_sc[s], e[(long)s*H2], acc);
        g_ctx[b*H2 + h] = acc * inv;
    }
}

// ---------------- decoder GRU matmuls (split-K) ----------------
__global__ void k_dec_gemm(int spar, int t,
                           const float* __restrict__ Wih, const float* __restrict__ Whh)
{
    __shared__ float sA[16][32];
    __shared__ float sW[16][64];
    int z = blockIdx.z, kc = blockIdx.y;
    int n0 = blockIdx.x * 64;
    int tid = threadIdx.x;
    int tm = tid & 15, tn = tid >> 4;
    float acc[2][4] = {};
    int K = z ? UU : KX;
    const float* W = z ? Whh : Wih;
    int kchunk = z ? 128 : 332;
    int kbeg = kc * kchunk;
    int kend = min(K, kbeg + kchunk);
    const float* st = g_state[spar];
    const float* em = g_embt + (long)t*BB*EE;

    for (int k0 = kbeg; k0 < kend; k0 += 16) {
        if (tid < 128) {
            int r = tid >> 2, kq = (tid & 3) * 4;
            #pragma unroll
            for (int j = 0; j < 4; j++) {
                int k = k0 + kq + j;
                float v = 0.0f;
                if (k < kend) {
                    if (z) v = st[r*UU + k];
                    else   v = (k < EE) ? em[r*EE + k] : g_ctx[r*H2 + k - EE];
                }
                sA[kq+j][r] = v;
            }
        }
        {
            int r = tid >> 2, kq = (tid & 3) * 4;
            #pragma unroll
            for (int j = 0; j < 4; j++) {
                int k = k0 + kq + j;
                sW[kq+j][r] = (k < kend) ? W[(long)(n0+r)*K + k] : 0.0f;
            }
        }
        __syncthreads();
        #pragma unroll
        for (int kk = 0; kk < 16; kk++) {
            float2 a2 = *reinterpret_cast<const float2*>(&sA[kk][tm*2]);
            float4 b4 = *reinterpret_cast<const float4*>(&sW[kk][tn*4]);
            acc[0][0] = fmaf(a2.x, b4.x, acc[0][0]);
            acc[0][1] = fmaf(a2.x, b4.y, acc[0][1]);
            acc[0][2] = fmaf(a2.x, b4.z, acc[0][2]);
            acc[0][3] = fmaf(a2.x, b4.w, acc[0][3]);
            acc[1][0] = fmaf(a2.y, b4.x, acc[1][0]);
            acc[1][1] = fmaf(a2.y, b4.y, acc[1][1]);
            acc[1][2] = fmaf(a2.y, b4.z, acc[1][2]);
            acc[1][3] = fmaf(a2.y, b4.w, acc[1][3]);
        }
        __syncthreads();
    }
    float* out = &g_dgp[z][kc][0];
    #pragma unroll
    for (int i = 0; i < 2; i++) {
        int b = tm*2 + i;
        #pragma unroll
        for (int j = 0; j < 4; j++)
            out[b*GG + n0 + tn*4 + j] = acc[i][j];
    }
}

__global__ void k_dec_gate(int spar, int t,
                           const float* __restrict__ bih, const float* __restrict__ bhh)
{
    int idx = blockIdx.x * blockDim.x + threadIdx.x;
    if (idx >= BB*FF) return;
    int f = idx % FF; int b = idx / FF;
    float* feat = g_feat + ((long)t*BB + b)*FF;
    if (f < UU) {
        int u = f;
        float gir = bih[u], giz = bih[u+UU], gin = bih[u+2*UU];
        float ghr = bhh[u], ghz = bhh[u+UU], ghn = bhh[u+2*UU];
        #pragma unroll
        for (int kc = 0; kc < 4; kc++) {
            const float* pi = &g_dgp[0][kc][b*GG];
            const float* ph = &g_dgp[1][kc][b*GG];
            gir += pi[u]; giz += pi[u+UU]; gin += pi[u+2*UU];
            ghr += ph[u]; ghz += ph[u+UU]; ghn += ph[u+2*UU];
        }
        float r = sigm(gir + ghr);
        float z = sigm(giz + ghz);
        float n = tanhf(gin + r*ghn);
        float hp = g_state[spar][b*UU + u];
        float h2 = (1.0f - z)*n + z*hp;
        g_state[spar^1][b*UU + u] = h2;
        feat[u] = h2;
    } else if (f < UU + H2) {
        feat[f] = g_ctx[b*H2 + f - UU];
    } else {
        feat[f] = g_embt[((long)t*BB + b)*EE + f - UU - H2];
    }
}

// ---------------- host launch ----------------
static float* symaddr(const void* sym) {
    void* p = nullptr;
    cudaGetSymbolAddress(&p, sym);
    return (float*)p;
}

extern "C" void kernel_launch(void* const* d_in, const int* in_sizes, int n_in,
                              void* d_out, int out_size)
{
    const float* emb_src   = (const float*)d_in[0];
    const float* emb_trg   = (const float*)d_in[1];
    const float* enc_Wih_f = (const float*)d_in[2];
    const float* enc_Whh_f = (const float*)d_in[3];
    const float* enc_bih_f = (const float*)d_in[4];
    const float* enc_bhh_f = (const float*)d_in[5];
    const float* enc_Wih_b = (const float*)d_in[6];
    const float* enc_Whh_b = (const float*)d_in[7];
    const float* enc_bih_b = (const float*)d_in[8];
    const float* enc_bhh_b = (const float*)d_in[9];
    const float* enc_Wfc   = (const float*)d_in[10];
    const float* enc_bfc   = (const float*)d_in[11];
    const float* attn_W    = (const float*)d_in[12];
    const float* attn_b    = (const float*)d_in[13];
    const float* dec_Wih   = (const float*)d_in[14];
    const float* dec_Whh   = (const float*)d_in[15];
    const float* dec_bih   = (const float*)d_in[16];
    const float* dec_bhh   = (const float*)d_in[17];
    const float* dec_Wfc   = (const float*)d_in[18];
    const float* dec_bfc   = (const float*)d_in[19];
    const int*   source    = (const int*)d_in[20];
    const int*   target    = (const int*)d_in[21];
    float* out = (float*)d_out;

    float* p_emb_s   = symaddr(g_emb_s);
    float* p_gi_f    = symaddr(g_gi_f);
    float* p_gi_b    = symaddr(g_gi_b);
    float* p_h       = symaddr(g_h);
    float* p_enc     = symaddr(g_enc);
    float* p_hfb     = symaddr(g_hfb);
    float* p_state   = symaddr(g_state);
    float* p_encproj = symaddr(g_encproj);

    static int attr_set = 0;
    if (!attr_set) {
        cudaFuncSetAttribute(k_logits_mma, cudaFuncAttributeMaxDynamicSharedMemorySize, LOG_SMEM);
        attr_set = 1;
    }

    // init h = 0 (both dirs, both parities)
    k_zero<<<(2*2*BB*UU + 255)/256, 256>>>(p_h, 2*2*BB*UU);

    // gather source embeddings
    k_gather_src<<<(SS*BB*EE + 255)/256, 256>>>(emb_src, source);

    // gi_f / gi_b : (2048 x 300) @ (300 x 1536)^T + bih
    {
        dim3 grid(GG/128, (SS*BB)/128);
        k_gemm<<<grid, 256>>>(p_emb_s, EE, enc_Wih_f, EE, 0, enc_bih_f,
                              p_gi_f, GG, SS*BB, GG, EE, 0);
        k_gemm<<<grid, 256>>>(p_emb_s, EE, enc_Wih_b, EE, 0, enc_bih_b,
                              p_gi_b, GG, SS*BB, GG, EE, 0);
    }

    // encoder recurrence
    for (int i = 0; i < SS; i++) {
        int par = i & 1;
        dim3 grid(GG/64, 4, 2);
        k_enc_gh<<<grid, 256>>>(enc_Whh_f, enc_Whh_b, par);
        k_enc_gate<<<(2*BB*UU)/256, 256>>>(i, SS-1-i, par, enc_bhh_f, enc_bhh_b);
    }

    k_concat_enc<<<(BB*SS*H2 + 255)/256, 256>>>();
    k_concat_hfb<<<(BB*H2 + 255)/256, 256>>>();

    // decoder init state
    {
        dim3 grid((UU + 127)/128, 1);
        k_gemm<<<grid, 256>>>(p_hfb, H2, enc_Wfc, H2, 0, enc_bfc,
                              p_state, UU, BB, UU, H2, 1);
    }

    // enc_proj = enc_bt @ attn_W[:, U:3U]^T + attn_b
    {
        dim3 grid(AD/128, (BB*SS)/128);
        k_gemm<<<grid, 256>>>(p_enc, H2, attn_W, GG, UU, attn_b,
                              p_encproj, AD, BB*SS, AD, H2, 0);
    }

    k_gather_trg<<<(TM1*BB*EE + 255)/256, 256>>>(emb_trg, target);

    // decoder recurrence
    for (int t = 0; t < TM1; t++) {
        int spar = t & 1;
        k_dec_attn<<<BB, 256>>>(spar, attn_W);
        dim3 grid(GG/64, 4, 2);
        k_dec_gemm<<<grid, 256>>>(spar, t, dec_Wih, dec_Whh);
        k_dec_gate<<<(BB*FF + 255)/256, 256>>>(spar, t, dec_bih, dec_bhh);
    }

    // split features into bf16 hi/lo (full FF, padded to KP)
    {
        long na = (long)MP*KP;
        k_split_a<<<(unsigned)((na + 255)/256), 256>>>();
    }

    // output row 0 = zeros
    k_zero<<<(BB*VTT + 255)/256, 256>>>(out, BB*VTT);

    // logits on tensor cores: W converted fp32->bf16 hi/lo inside the kernel
    {
        dim3 grid(MP/128, NP/128);
        k_logits_mma<<<grid, 256, LOG_SMEM>>>(dec_Wfc, dec_bfc, out + (long)BB*VTT);
    }
}

// round 12
// speedup vs baseline: 1.1153x; 1.1153x over previous
#include <cuda_runtime.h>
#include <cuda_bf16.h>
#include <math.h>
#include <stdint.h>

#define SS 64      // source length
#define BB 32      // batch
#define UU 512     // hidden
#define GG 1536    // 3*U
#define EE 300     // embed dim
#define AD 512     // attention dim
#define VTT 30000  // target vocab
#define TT 32      // target length
#define TM1 31     // T-1 decode steps
#define FF 1836    // 3U + E  (logits feature dim)
#define KX 1324    // 2U + E  (decoder GRU input dim)
#define H2 1024    // 2U
#define MTOT (TM1*BB)   // 992
#define PBLK 96    // step-kernel block count (< 148 SMs -> all resident)

// logits GEMM padded dims
#define KP 1856         // 29 * 64
#define NP 30080        // 235 * 128
#define MP 1024         // 8 * 128
#define KITER 29

// ---------------- device scratch (static, no allocation) ----------------
__device__ float g_emb_s[SS*BB*EE];
__device__ float g_gi_f[SS*BB*GG];
__device__ float g_gi_b[SS*BB*GG];
__device__ float g_outs_f[SS*BB*UU];
__device__ float g_outs_b[SS*BB*UU];
__device__ float g_h[2][2][BB*UU];          // [dir][parity]
__device__ float g_ghp[2][2][BB*GG];        // encoder gh split-K partials (2 chunks)
__device__ float g_enc[BB*SS*H2];           // enc_bt (b,s,2U)
__device__ float g_hfb[BB*H2];
__device__ float g_state[2][BB*UU];         // decoder state ping-pong
__device__ float g_encproj[BB*SS*AD];
__device__ float g_embt[TM1*BB*EE];
__device__ float g_ctx[BB*H2];
__device__ float g_dgp[2][4][BB*GG];        // decoder gi(4)/gh(2) split-K partials
__device__ float g_feat[(long)TM1*BB*FF];
__device__ int   g_ectr[SS];                // per-step barrier counters (encoder)
__device__ int   g_dctr[2*TM1];             // per-step barrier counters (decoder)

// split-bf16 operands for the logits GEMM
__device__ __nv_bfloat16 g_whi[(long)NP*KP];
__device__ __nv_bfloat16 g_wlo[(long)NP*KP];
__device__ __nv_bfloat16 g_ahi[(long)MP*KP];
__device__ __nv_bfloat16 g_alo[(long)MP*KP];

__device__ __forceinline__ float sigm(float x) { return 1.0f / (1.0f + expf(-x)); }

// ---- software grid barrier (per-step counter slot, zeroed once per replay) ----
__device__ __forceinline__ void gbar(int* ctr, int target) {
    __syncthreads();
    if (threadIdx.x == 0) {
        __threadfence();
        atomicAdd(ctr, 1);
        volatile int* v = ctr;
        while (*v < target) { }
    }
    __syncthreads();
}

// ---- packed f32x2 helpers ----
__device__ __forceinline__ unsigned long long pk2(float x, float y) {
    unsigned long long r;
    asm("mov.b64 %0, {%1, %2};" : "=l"(r) : "f"(x), "f"(y));
    return r;
}
__device__ __forceinline__ void fma2(unsigned long long& d, unsigned long long a, unsigned long long b) {
    asm("fma.rn.f32x2 %0, %1, %2, %0;" : "+l"(d) : "l"(a), "l"(b));
}
__device__ __forceinline__ float2 upk2(unsigned long long v) {
    float2 f;
    asm("mov.b64 {%0, %1}, %2;" : "=f"(f.x), "=f"(f.y) : "l"(v));
    return f;
}

// ---------------- tiny utility kernels ----------------
__global__ void k_zero(float* p, int n) {
    int i = blockIdx.x * blockDim.x + threadIdx.x;
    if (i < n) p[i] = 0.0f;
}

__global__ void k_gather_src(const float* __restrict__ emb, const int* __restrict__ src) {
    int idx = blockIdx.x * blockDim.x + threadIdx.x;
    if (idx >= SS*BB*EE) return;
    int e = idx % EE; int tb = idx / EE;
    g_emb_s[idx] = emb[(long)src[tb]*EE + e];
}

__global__ void k_gather_trg(const float* __restrict__ emb, const int* __restrict__ trg) {
    int idx = blockIdx.x * blockDim.x + threadIdx.x;
    if (idx >= TM1*BB*EE) return;
    int e = idx % EE; int tb = idx / EE;
    g_embt[idx] = emb[(long)trg[tb]*EE + e];
}

__global__ void k_concat_enc() {
    int idx = blockIdx.x * blockDim.x + threadIdx.x;
    if (idx >= BB*SS*H2) return;
    int h = idx % H2; int bs = idx / H2;
    int s = bs % SS, b = bs / SS;
    float v = (h < UU) ? g_outs_f[((long)s*BB + b)*UU + h]
                       : g_outs_b[((long)s*BB + b)*UU + h - UU];
    g_enc[idx] = v;
}

__global__ void k_concat_hfb() {
    int idx = blockIdx.x * blockDim.x + threadIdx.x;
    if (idx >= BB*H2) return;
    int h = idx % H2; int b = idx / H2;
    float v = (h < UU) ? g_outs_f[((long)(SS-1)*BB + b)*UU + h]
                       : g_outs_b[(long)b*UU + h - UU];
    g_hfb[idx] = v;
}

// ---------------- split kernels: fp32 -> bf16 hi/lo ----------------
// vectorized: 4 elems per thread (KP % 4 == 0)
__global__ void k_split_w4(const float* __restrict__ W) {
    long idx = (long)blockIdx.x * blockDim.x + threadIdx.x;
    long total = (long)NP * (KP/4);
    if (idx >= total) return;
    int kq = (int)(idx % (KP/4)) * 4;
    int n  = (int)(idx / (KP/4));
    float4 x = make_float4(0.f, 0.f, 0.f, 0.f);
    if (n < VTT) {
        if (kq + 4 <= FF) {
            x = *reinterpret_cast<const float4*>(&W[(long)n*FF + kq]);
        } else if (kq < FF) {
            const float* src = &W[(long)n*FF + kq];
            float t[4] = {0,0,0,0};
            for (int j = 0; j < 4; j++) if (kq + j < FF) t[j] = src[j];
            x = make_float4(t[0], t[1], t[2], t[3]);
        }
    }
    __nv_bfloat16 h0 = __float2bfloat16(x.x), h1 = __float2bfloat16(x.y);
    __nv_bfloat16 h2 = __float2bfloat16(x.z), h3 = __float2bfloat16(x.w);
    __nv_bfloat16 l0 = __float2bfloat16(x.x - __bfloat162float(h0));
    __nv_bfloat16 l1 = __float2bfloat16(x.y - __bfloat162float(h1));
    __nv_bfloat16 l2 = __float2bfloat16(x.z - __bfloat162float(h2));
    __nv_bfloat16 l3 = __float2bfloat16(x.w - __bfloat162float(h3));
    long o = (long)n*KP + kq;
    __nv_bfloat162 hA; hA.x = h0; hA.y = h1;
    __nv_bfloat162 hB; hB.x = h2; hB.y = h3;
    __nv_bfloat162 lA; lA.x = l0; lA.y = l1;
    __nv_bfloat162 lB; lB.x = l2; lB.y = l3;
    *reinterpret_cast<__nv_bfloat162*>(&g_whi[o])   = hA;
    *reinterpret_cast<__nv_bfloat162*>(&g_whi[o+2]) = hB;
    *reinterpret_cast<__nv_bfloat162*>(&g_wlo[o])   = lA;
    *reinterpret_cast<__nv_bfloat162*>(&g_wlo[o+2]) = lB;
}

__global__ void k_split_a() {
    long idx = (long)blockIdx.x * blockDim.x + threadIdx.x;
    if (idx >= (long)MP*KP) return;
    int k = (int)(idx % KP); int m = (int)(idx / KP);
    float x = (m < MTOT && k < FF) ? g_feat[(long)m*FF + k] : 0.0f;
    __nv_bfloat16 h = __float2bfloat16(x);
    g_ahi[idx] = h;
    g_alo[idx] = __float2bfloat16(x - __bfloat162float(h));
}

// ---------------- fp32x2 tiled GEMM: C = act(A @ W^T + bias) ----------------
__global__ void __launch_bounds__(256, 2)
k_gemm(const float* __restrict__ Ap, int lda,
       const float* __restrict__ Wp, int ldw, int woff,
       const float* __restrict__ bias,
       float* __restrict__ Cp, int ldc,
       int M, int N, int K, int act)
{
    __shared__ float sA[16][128];
    __shared__ float sW[16][128];
    int tid = threadIdx.x;
    int m0 = blockIdx.y * 128, n0 = blockIdx.x * 128;
    int tr = tid & 15, tc = tid >> 4;

    unsigned long long acc[8][4];
    #pragma unroll
    for (int i = 0; i < 8; i++)
        #pragma unroll
        for (int j = 0; j < 4; j++) acc[i][j] = 0ull;

    int r  = tid >> 2;
    int kq = (tid & 3) * 4;

    for (int k0 = 0; k0 < K; k0 += 16) {
        bool kok = (k0 + kq) < K;
        #pragma unroll
        for (int h = 0; h < 2; h++) {
            int row = r + h * 64;
            float4 va = make_float4(0.f, 0.f, 0.f, 0.f);
            int m = m0 + row;
            if (kok && m < M) va = *reinterpret_cast<const float4*>(&Ap[(long)m*lda + k0 + kq]);
            sA[kq+0][row] = va.x; sA[kq+1][row] = va.y;
            sA[kq+2][row] = va.z; sA[kq+3][row] = va.w;

            float4 vw = make_float4(0.f, 0.f, 0.f, 0.f);
            int n = n0 + row;
            if (kok && n < N) vw = *reinterpret_cast<const float4*>(&Wp[(long)n*ldw + woff + k0 + kq]);
            sW[kq+0][row] = vw.x; sW[kq+1][row] = vw.y;
            sW[kq+2][row] = vw.z; sW[kq+3][row] = vw.w;
        }
        __syncthreads();

        #pragma unroll
        for (int kk = 0; kk < 16; kk++) {
            float4 a0 = *reinterpret_cast<const float4*>(&sA[kk][tr*8]);
            float4 a1 = *reinterpret_cast<const float4*>(&sA[kk][tr*8 + 4]);
            unsigned long long bp[4];
            #pragma unroll
            for (int j = 0; j < 4; j++)
                bp[j] = *reinterpret_cast<const unsigned long long*>(&sW[kk][tc*8 + 2*j]);
            float av[8] = {a0.x, a0.y, a0.z, a0.w, a1.x, a1.y, a1.z, a1.w};
            #pragma unroll
            for (int i = 0; i < 8; i++) {
                unsigned long long ap = pk2(av[i], av[i]);
                #pragma unroll
                for (int j = 0; j < 4; j++) fma2(acc[i][j], ap, bp[j]);
            }
        }
        __syncthreads();
    }

    #pragma unroll
    for (int i = 0; i < 8; i++) {
        int m = m0 + tr*8 + i;
        if (m >= M) continue;
        #pragma unroll
        for (int j = 0; j < 4; j++) {
            float2 v = upk2(acc[i][j]);
            int n = n0 + tc*8 + 2*j;
            if (n < N) {
                float c = v.x + (bias ? bias[n] : 0.0f);
                if (act) c = tanhf(c);
                Cp[(long)m*ldc + n] = c;
            }
            if (n + 1 < N) {
                float c = v.y + (bias ? bias[n+1] : 0.0f);
                if (act) c = tanhf(c);
                Cp[(long)m*ldc + n + 1] = c;
            }
        }
    }
}

// ================= mma.sync bf16 logits GEMM (R4-best form) =================
__device__ __forceinline__ uint32_t smem_u32(const void* p) {
    uint32_t a;
    asm("{ .reg .u64 t; cvta.to.shared.u64 t, %1; cvt.u32.u64 %0, t; }" : "=r"(a) : "l"(p));
    return a;
}
__device__ __forceinline__ void cpa16(uint32_t dst, const void* src) {
    asm volatile("cp.async.cg.shared.global [%0], [%1], 16;" :: "r"(dst), "l"(src) : "memory");
}
__device__ __forceinline__ void cpa_commit() {
    asm volatile("cp.async.commit_group;" ::: "memory");
}
__device__ __forceinline__ void ldsm4(uint32_t* r, uint32_t addr) {
    asm volatile("ldmatrix.sync.aligned.m8n8.x4.shared.b16 {%0,%1,%2,%3}, [%4];"
        : "=r"(r[0]), "=r"(r[1]), "=r"(r[2]), "=r"(r[3]) : "r"(addr));
}
__device__ __forceinline__ void mma16816(float* d, const uint32_t* a, const uint32_t* b) {
    asm volatile("mma.sync.aligned.m16n8k16.row.col.f32.bf16.bf16.f32 "
        "{%0,%1,%2,%3}, {%4,%5,%6,%7}, {%8,%9}, {%0,%1,%2,%3};"
        : "+f"(d[0]), "+f"(d[1]), "+f"(d[2]), "+f"(d[3])
        : "r"(a[0]), "r"(a[1]), "r"(a[2]), "r"(a[3]), "r"(b[0]), "r"(b[1]));
}

#define LSTG 65536
#define LOG_SMEM (2*LSTG)

__global__ void __launch_bounds__(256, 1)
k_logits_mma(const float* __restrict__ bias, float* __restrict__ outp)
{
    extern __shared__ __align__(128) char smem[];
    uint32_t sb = smem_u32(smem);
    int tid = threadIdx.x;
    int wid = tid >> 5, lane = tid & 31;
    int wm = wid >> 2, wn = wid & 3;
    int grp = lane >> 3, lr = lane & 7;
    int m0 = blockIdx.x * 128;
    int n0 = blockIdx.y * 128;

    float acc[4][4][4];
    #pragma unroll
    for (int i = 0; i < 4; i++)
        #pragma unroll
        for (int j = 0; j < 4; j++)
            #pragma unroll
            for (int c = 0; c < 4; c++) acc[i][j][c] = 0.0f;

    auto load_stage = [&](int it, int s) {
        int k0 = it * 64;
        uint32_t base = sb + s * LSTG;
        #pragma unroll
        for (int q = 0; q < 4; q++) {
            int u = tid + q * 256;
            int row = u >> 3, c = u & 7;
            uint32_t off = row * 128 + (((uint32_t)(c ^ (row & 7))) << 4);
            long ga = (long)(m0 + row) * KP + k0 + c * 8;
            cpa16(base + off,          g_ahi + ga);
            cpa16(base + 16384 + off,  g_alo + ga);
            long gb = (long)(n0 + row) * KP + k0 + c * 8;
            cpa16(base + 32768 + off,  g_whi + gb);
            cpa16(base + 49152 + off,  g_wlo + gb);
        }
    };

    load_stage(0, 0);
    cpa_commit();

    for (int it = 0; it < KITER; it++) {
        int s = it & 1;
        if (it < KITER - 1) {
            load_stage(it + 1, s ^ 1);
            cpa_commit();
            asm volatile("cp.async.wait_group 1;" ::: "memory");
        } else {
            asm volatile("cp.async.wait_group 0;" ::: "memory");
        }
        __syncthreads();

        uint32_t aAhi = sb + s*LSTG;
        uint32_t aAlo = aAhi + 16384;
        uint32_t aBhi = aAhi + 32768;
        uint32_t aBlo = aAhi + 49152;

        #pragma unroll
        for (int ks = 0; ks < 4; ks++) {
            uint32_t fa_hi[4][4], fa_lo[4][4];
            #pragma unroll
            for (int mt = 0; mt < 4; mt++) {
                int row = wm*64 + mt*16 + lr + (grp & 1) * 8;
                int c = 2*ks + (grp >> 1);
                uint32_t off = row * 128 + (((uint32_t)(c ^ (row & 7))) << 4);
                ldsm4(fa_hi[mt], aAhi + off);
                ldsm4(fa_lo[mt], aAlo + off);
            }
            uint32_t fb_hi[2][4], fb_lo[2][4];
            #pragma unroll
            for (int p = 0; p < 2; p++) {
                int nrow = wn*32 + p*16 + lr + (grp >> 1) * 8;
                int c = 2*ks + (grp & 1);
                uint32_t off = nrow * 128 + (((uint32_t)(c ^ (nrow & 7))) << 4);
                ldsm4(fb_hi[p], aBhi + off);
                ldsm4(fb_lo[p], aBlo + off);
            }
            #pragma unroll
            for (int mt = 0; mt < 4; mt++) {
                #pragma unroll
                for (int nt = 0; nt < 4; nt++) {
                    const uint32_t* bh = &fb_hi[nt >> 1][(nt & 1) * 2];
                    const uint32_t* bl = &fb_lo[nt >> 1][(nt & 1) * 2];
                    mma16816(acc[mt][nt], fa_hi[mt], bh);
                    mma16816(acc[mt][nt], fa_lo[mt], bh);
                    mma16816(acc[mt][nt], fa_hi[mt], bl);
                }
            }
        }
        __syncthreads();
    }

    int mrow = (lane >> 2);
    int ncol = (lane & 3) * 2;
    #pragma unroll
    for (int mt = 0; mt < 4; mt++) {
        #pragma unroll
        for (int nt = 0; nt < 4; nt++) {
            int n = n0 + wn*32 + nt*8 + ncol;
            if (n >= VTT) continue;
            float2 bv = *reinterpret_cast<const float2*>(&bias[n]);
            int m1 = m0 + wm*64 + mt*16 + mrow;
            int m2 = m1 + 8;
            if (m1 < MTOT) {
                float2 v = make_float2(acc[mt][nt][0] + bv.x, acc[mt][nt][1] + bv.y);
                *reinterpret_cast<float2*>(&outp[(long)m1*VTT + n]) = v;
            }
            if (m2 < MTOT) {
                float2 v = make_float2(acc[mt][nt][2] + bv.x, acc[mt][nt][3] + bv.y);
                *reinterpret_cast<float2*>(&outp[(long)m2*VTT + n]) = v;
            }
        }
    }
}

// ================= encoder step kernel (gh GEMM + barrier + gate) =================
// 96 blocks: dir(2) x ntile(24) x kc(2), K=256 per chunk.
__global__ void __launch_bounds__(256, 1)
k_enc_step(int step,
           const float* __restrict__ Whh_f, const float* __restrict__ Whh_b,
           const float* __restrict__ bhh_f, const float* __restrict__ bhh_b)
{
    __shared__ float sA[16][32];
    __shared__ float sW[16][64];
    int blk = blockIdx.x, tid = threadIdx.x;
    int par = step & 1;
    int dir = blk >= 48;
    int rem = dir ? blk - 48 : blk;
    int ntile = rem >> 1;
    int kc = rem & 1;
    int n0 = ntile * 64;
    int kbase = kc * 256;
    const float* W = dir ? Whh_b : Whh_f;
    const float* h = g_h[dir][par];
    int tm = tid & 15, tn = tid >> 4;
    float acc[2][4] = {};

    for (int k0 = 0; k0 < 256; k0 += 16) {
        int r = tid >> 2, kq = (tid & 3) * 4;
        if (tid < 128) {
            float4 v = *(const float4*)&h[r*UU + kbase + k0 + kq];
            sA[kq+0][r] = v.x; sA[kq+1][r] = v.y;
            sA[kq+2][r] = v.z; sA[kq+3][r] = v.w;
        }
        {
            float4 v = *(const float4*)&W[(long)(n0+r)*UU + kbase + k0 + kq];
            sW[kq+0][r] = v.x; sW[kq+1][r] = v.y;
            sW[kq+2][r] = v.z; sW[kq+3][r] = v.w;
        }
        __syncthreads();
        #pragma unroll
        for (int kk = 0; kk < 16; kk++) {
            float2 a2 = *reinterpret_cast<const float2*>(&sA[kk][tm*2]);
            float4 b4 = *reinterpret_cast<const float4*>(&sW[kk][tn*4]);
            acc[0][0] = fmaf(a2.x, b4.x, acc[0][0]);
            acc[0][1] = fmaf(a2.x, b4.y, acc[0][1]);
            acc[0][2] = fmaf(a2.x, b4.z, acc[0][2]);
            acc[0][3] = fmaf(a2.x, b4.w, acc[0][3]);
            acc[1][0] = fmaf(a2.y, b4.x, acc[1][0]);
            acc[1][1] = fmaf(a2.y, b4.y, acc[1][1]);
            acc[1][2] = fmaf(a2.y, b4.z, acc[1][2]);
            acc[1][3] = fmaf(a2.y, b4.w, acc[1][3]);
        }
        __syncthreads();
    }
    float* outp = &g_ghp[dir][kc][0];
    #pragma unroll
    for (int i = 0; i < 2; i++) {
        int b = tm*2 + i;
        #pragma unroll
        for (int j = 0; j < 4; j++)
            outp[b*GG + n0 + tn*4 + j] = acc[i][j];
    }

    gbar(&g_ectr[step], PBLK);

    // fused gate for both directions (cross-block reads via __ldcg)
    int tf = step, tb = SS-1-step;
    for (int idx = blk*256 + tid; idx < 2*BB*UU; idx += PBLK*256) {
        int u = idx & 511;
        int b = (idx >> 9) & 31;
        int d2 = idx >> 14;
        const float* gi = d2 ? (g_gi_b + (long)tb*BB*GG) : (g_gi_f + (long)tf*BB*GG);
        const float* bhh = d2 ? bhh_b : bhh_f;
        float ghr = bhh[u]      + __ldcg(&g_ghp[d2][0][b*GG+u])      + __ldcg(&g_ghp[d2][1][b*GG+u]);
        float ghz = bhh[u+UU]   + __ldcg(&g_ghp[d2][0][b*GG+u+UU])   + __ldcg(&g_ghp[d2][1][b*GG+u+UU]);
        float ghn = bhh[u+2*UU] + __ldcg(&g_ghp[d2][0][b*GG+u+2*UU]) + __ldcg(&g_ghp[d2][1][b*GG+u+2*UU]);
        float ir = gi[b*GG + u], iz = gi[b*GG + u + UU], inn = gi[b*GG + u + 2*UU];
        float r = sigm(ir + ghr);
        float z = sigm(iz + ghz);
        float n = tanhf(inn + r*ghn);
        float hp = g_h[d2][par][b*UU + u];
        float hn_ = (1.0f - z)*n + z*hp;
        g_h[d2][par^1][b*UU + u] = hn_;
        float* outs = d2 ? (g_outs_b + (long)tb*BB*UU) : (g_outs_f + (long)tf*BB*UU);
        outs[b*UU + u] = hn_;
    }
}

// ================= decoder step kernel (attn||gh + gi + gate, 2 barriers) =================
__global__ void __launch_bounds__(256, 1)
k_dec_step(int t,
           const float* __restrict__ attn_W,
           const float* __restrict__ Wih, const float* __restrict__ Whh,
           const float* __restrict__ bih, const float* __restrict__ bhh)
{
    __shared__ float sA[16][32];
    __shared__ float sW[16][64];
    __shared__ float s_st[UU];
    __shared__ float s_tp[AD];
    __shared__ float s_sc[SS];
    __shared__ float s_red[2];

    int blk = blockIdx.x, tid = threadIdx.x;
    int tm = tid & 15, tn = tid >> 4;
    int spar = t & 1;
    const float* st_g = g_state[spar];

    // ---------- Phase 1: attention (blk 0-31) || gh GEMM (blk 32-79) ----------
    if (blk < 32) {
        int b = blk;
        const float* st = &st_g[b*UU];
        for (int i = tid; i < UU; i += 256) s_st[i] = st[i];
        __syncthreads();
        for (int a = tid; a < AD; a += 256) {
            const float* w = attn_W + (long)a*GG;
            float acc = 0.0f;
            #pragma unroll 4
            for (int k = 0; k < UU; k += 4) {
                float4 wv = *reinterpret_cast<const float4*>(w + k);
                acc = fmaf(s_st[k],   wv.x, acc);
                acc = fmaf(s_st[k+1], wv.y, acc);
                acc = fmaf(s_st[k+2], wv.z, acc);
                acc = fmaf(s_st[k+3], wv.w, acc);
            }
            s_tp[a] = acc;
        }
        __syncthreads();
        {
            int s = tid >> 2, q = tid & 3;
            const float* ep = g_encproj + ((long)b*SS + s)*AD + q*128;
            const float* tp = s_tp + q*128;
            float partial = 0.0f;
            for (int a = 0; a < 128; a++) partial += tanhf(tp[a] + ep[a]);
            partial += __shfl_down_sync(0xffffffffu, partial, 2);
            partial += __shfl_down_sync(0xffffffffu, partial, 1);
            if (q == 0) s_sc[s] = partial;
        }
        __syncthreads();
        if (tid == 0) {
            float mx = s_sc[0];
            for (int s = 1; s < SS; s++) mx = fmaxf(mx, s_sc[s]);
            s_red[0] = mx;
        }
        __syncthreads();
        if (tid < SS) s_sc[tid] = expf(s_sc[tid] - s_red[0]);
        __syncthreads();
        if (tid == 0) {
            float sm = 0.0f;
            for (int s = 0; s < SS; s++) sm += s_sc[s];
            s_red[1] = 1.0f / sm;
        }
        __syncthreads();
        float inv = s_red[1];
        for (int h = tid; h < H2; h += 256) {
            const float* e = g_enc + (long)b*SS*H2 + h;
            float acc = 0.0f;
            #pragma unroll 8
            for (int s = 0; s < SS; s++) acc = fmaf(s_sc[s], e[(long)s*H2], acc);
            g_ctx[b*H2 + h] = acc * inv;
        }
    } else if (blk < 80) {
        int idx2 = blk - 32;
        int ntile = idx2 >> 1;
        int kc = idx2 & 1;
        int n0 = ntile * 64;
        int kbase = kc * 256;
        float acc[2][4] = {};
        for (int k0 = 0; k0 < 256; k0 += 16) {
            int r = tid >> 2, kq = (tid & 3) * 4;
            if (tid < 128) {
                float4 v = *(const float4*)&st_g[r*UU + kbase + k0 + kq];
                sA[kq+0][r] = v.x; sA[kq+1][r] = v.y;
                sA[kq+2][r] = v.z; sA[kq+3][r] = v.w;
            }
            {
                float4 v = *(const float4*)&Whh[(long)(n0+r)*UU + kbase + k0 + kq];
                sW[kq+0][r] = v.x; sW[kq+1][r] = v.y;
                sW[kq+2][r] = v.z; sW[kq+3][r] = v.w;
            }
            __syncthreads();
            #pragma unroll
            for (int kk = 0; kk < 16; kk++) {
                float2 a2 = *reinterpret_cast<const float2*>(&sA[kk][tm*2]);
                float4 b4 = *reinterpret_cast<const float4*>(&sW[kk][tn*4]);
                acc[0][0] = fmaf(a2.x, b4.x, acc[0][0]);
                acc[0][1] = fmaf(a2.x, b4.y, acc[0][1]);
                acc[0][2] = fmaf(a2.x, b4.z, acc[0][2]);
                acc[0][3] = fmaf(a2.x, b4.w, acc[0][3]);
                acc[1][0] = fmaf(a2.y, b4.x, acc[1][0]);
                acc[1][1] = fmaf(a2.y, b4.y, acc[1][1]);
                acc[1][2] = fmaf(a2.y, b4.z, acc[1][2]);
                acc[1][3] = fmaf(a2.y, b4.w, acc[1][3]);
            }
            __syncthreads();
        }
        float* outp = &g_dgp[1][kc][0];
        #pragma unroll
        for (int i = 0; i < 2; i++) {
            int b = tm*2 + i;
            #pragma unroll
            for (int j = 0; j < 4; j++)
                outp[b*GG + n0 + tn*4 + j] = acc[i][j];
        }
    }
    gbar(&g_dctr[2*t], PBLK);

    // ---------- Phase 2: gi GEMM, all 96 blocks (24 ntiles x 4 kc, K=331) ----------
    {
        int ntile = blk >> 2;
        int kc = blk & 3;
        int n0 = ntile * 64;
        int kbeg = kc * 331;
        int kend = kbeg + 331;
        const float* em = g_embt + (long)t*BB*EE;
        float acc[2][4] = {};
        for (int k0 = kbeg; k0 < kend; k0 += 16) {
            int r = tid >> 2, kq = (tid & 3) * 4;
            if (tid < 128) {
                #pragma unroll
                for (int j = 0; j < 4; j++) {
                    int k = k0 + kq + j;
                    float v = 0.0f;
                    if (k < kend)
                        v = (k < EE) ? em[r*EE + k] : __ldcg(&g_ctx[r*H2 + k - EE]);
                    sA[kq+j][r] = v;
                }
            }
            {
                #pragma unroll
                for (int j = 0; j < 4; j++) {
                    int k = k0 + kq + j;
                    sW[kq+j][r] = (k < kend) ? Wih[(long)(n0+r)*KX + k] : 0.0f;
                }
            }
            __syncthreads();
            #pragma unroll
            for (int kk = 0; kk < 16; kk++) {
                float2 a2 = *reinterpret_cast<const float2*>(&sA[kk][tm*2]);
                float4 b4 = *reinterpret_cast<const float4*>(&sW[kk][tn*4]);
                acc[0][0] = fmaf(a2.x, b4.x, acc[0][0]);
                acc[0][1] = fmaf(a2.x, b4.y, acc[0][1]);
                acc[0][2] = fmaf(a2.x, b4.z, acc[0][2]);
                acc[0][3] = fmaf(a2.x, b4.w, acc[0][3]);
                acc[1][0] = fmaf(a2.y, b4.x, acc[1][0]);
                acc[1][1] = fmaf(a2.y, b4.y, acc[1][1]);
                acc[1][2] = fmaf(a2.y, b4.z, acc[1][2]);
                acc[1][3] = fmaf(a2.y, b4.w, acc[1][3]);
            }
            __syncthreads();
        }
        float* outp = &g_dgp[0][kc][0];
        #pragma unroll
        for (int i = 0; i < 2; i++) {
            int b = tm*2 + i;
            #pragma unroll
            for (int j = 0; j < 4; j++)
                outp[b*GG + n0 + tn*4 + j] = acc[i][j];
        }
    }
    gbar(&g_dctr[2*t+1], PBLK);

    // ---------- Phase 3: gate + feature assembly ----------
    for (int idx = blk*256 + tid; idx < BB*FF; idx += PBLK*256) {
        int f = idx % FF; int b = idx / FF;
        float* feat = g_feat + ((long)t*BB + b)*FF;
        if (f < UU) {
            int u = f;
            float gir = bih[u], giz = bih[u+UU], gin = bih[u+2*UU];
            float ghr = bhh[u], ghz = bhh[u+UU], ghn = bhh[u+2*UU];
            #pragma unroll
            for (int kc = 0; kc < 4; kc++) {
                const float* pi = &g_dgp[0][kc][b*GG];
                gir += __ldcg(&pi[u]); giz += __ldcg(&pi[u+UU]); gin += __ldcg(&pi[u+2*UU]);
            }
            #pragma unroll
            for (int kc = 0; kc < 2; kc++) {
                const float* ph = &g_dgp[1][kc][b*GG];
                ghr += __ldcg(&ph[u]); ghz += __ldcg(&ph[u+UU]); ghn += __ldcg(&ph[u+2*UU]);
            }
            float r = sigm(gir + ghr);
            float z = sigm(giz + ghz);
            float n = tanhf(gin + r*ghn);
            float hp = st_g[b*UU + u];
            float h2 = (1.0f - z)*n + z*hp;
            g_state[spar^1][b*UU + u] = h2;
            feat[u] = h2;
        } else if (f < UU + H2) {
            feat[f] = __ldcg(&g_ctx[b*H2 + f - UU]);
        } else {
            feat[f] = g_embt[((long)t*BB + b)*EE + f - UU - H2];
        }
    }
}

// ---------------- host launch ----------------
static float* symaddr(const void* sym) {
    void* p = nullptr;
    cudaGetSymbolAddress(&p, sym);
    return (float*)p;
}

extern "C" void kernel_launch(void* const* d_in, const int* in_sizes, int n_in,
                              void* d_out, int out_size)
{
    const float* emb_src   = (const float*)d_in[0];
    const float* emb_trg   = (const float*)d_in[1];
    const float* enc_Wih_f = (const float*)d_in[2];
    const float* enc_Whh_f = (const float*)d_in[3];
    const float* enc_bih_f = (const float*)d_in[4];
    const float* enc_bhh_f = (const float*)d_in[5];
    const float* enc_Wih_b = (const float*)d_in[6];
    const float* enc_Whh_b = (const float*)d_in[7];
    const float* enc_bih_b = (const float*)d_in[8];
    const float* enc_bhh_b = (const float*)d_in[9];
    const float* enc_Wfc   = (const float*)d_in[10];
    const float* enc_bfc   = (const float*)d_in[11];
    const float* attn_W    = (const float*)d_in[12];
    const float* attn_b    = (const float*)d_in[13];
    const float* dec_Wih   = (const float*)d_in[14];
    const float* dec_Whh   = (const float*)d_in[15];
    const float* dec_bih   = (const float*)d_in[16];
    const float* dec_bhh   = (const float*)d_in[17];
    const float* dec_Wfc   = (const float*)d_in[18];
    const float* dec_bfc   = (const float*)d_in[19];
    const int*   source    = (const int*)d_in[20];
    const int*   target    = (const int*)d_in[21];
    float* out = (float*)d_out;

    float* p_emb_s   = symaddr(g_emb_s);
    float* p_gi_f    = symaddr(g_gi_f);
    float* p_gi_b    = symaddr(g_gi_b);
    float* p_h       = symaddr(g_h);
    float* p_enc     = symaddr(g_enc);
    float* p_hfb     = symaddr(g_hfb);
    float* p_state   = symaddr(g_state);
    float* p_encproj = symaddr(g_encproj);
    float* p_ectr    = symaddr(g_ectr);
    float* p_dctr    = symaddr(g_dctr);

    static int attr_set = 0;
    if (!attr_set) {
        cudaFuncSetAttribute(k_logits_mma, cudaFuncAttributeMaxDynamicSharedMemorySize, LOG_SMEM);
        attr_set = 1;
    }

    // reset per-step barrier counters (once per replay)
    k_zero<<<1, 128>>>(p_ectr, SS);
    k_zero<<<1, 128>>>(p_dctr, 2*TM1);

    // split dec_Wfc into bf16 hi/lo (vectorized)
    {
        long total = (long)NP * (KP/4);
        k_split_w4<<<(unsigned)((total + 255)/256), 256>>>(dec_Wfc);
    }

    // init h = 0 (both dirs, both parities)
    k_zero<<<(2*2*BB*UU + 255)/256, 256>>>(p_h, 2*2*BB*UU);

    // gather source embeddings
    k_gather_src<<<(SS*BB*EE + 255)/256, 256>>>(emb_src, source);

    // gi_f / gi_b : (2048 x 300) @ (300 x 1536)^T + bih
    {
        dim3 grid(GG/128, (SS*BB)/128);
        k_gemm<<<grid, 256>>>(p_emb_s, EE, enc_Wih_f, EE, 0, enc_bih_f,
                              p_gi_f, GG, SS*BB, GG, EE, 0);
        k_gemm<<<grid, 256>>>(p_emb_s, EE, enc_Wih_b, EE, 0, enc_bih_b,
                              p_gi_b, GG, SS*BB, GG, EE, 0);
    }

    // encoder recurrence: one fused kernel per step
    for (int i = 0; i < SS; i++) {
        k_enc_step<<<PBLK, 256>>>(i, enc_Whh_f, enc_Whh_b, enc_bhh_f, enc_bhh_b);
    }

    k_concat_enc<<<(BB*SS*H2 + 255)/256, 256>>>();
    k_concat_hfb<<<(BB*H2 + 255)/256, 256>>>();

    // decoder init state
    {
        dim3 grid((UU + 127)/128, 1);
        k_gemm<<<grid, 256>>>(p_hfb, H2, enc_Wfc, H2, 0, enc_bfc,
                              p_state, UU, BB, UU, H2, 1);
    }

    // enc_proj = enc_bt @ attn_W[:, U:3U]^T + attn_b
    {
        dim3 grid(AD/128, (BB*SS)/128);
        k_gemm<<<grid, 256>>>(p_enc, H2, attn_W, GG, UU, attn_b,
                              p_encproj, AD, BB*SS, AD, H2, 0);
    }

    k_gather_trg<<<(TM1*BB*EE + 255)/256, 256>>>(emb_trg, target);

    // decoder recurrence: one fused kernel per step
    for (int t = 0; t < TM1; t++) {
        k_dec_step<<<PBLK, 256>>>(t, attn_W, dec_Wih, dec_Whh, dec_bih, dec_bhh);
    }

    // split features into bf16 hi/lo
    {
        long na = (long)MP*KP;
        k_split_a<<<(unsigned)((na + 255)/256), 256>>>();
    }

    // output row 0 = zeros
    k_zero<<<(BB*VTT + 255)/256, 256>>>(out, BB*VTT);

    // logits on tensor cores (mma.sync bf16, split hi/lo): rows 1..31 of out
    {
        dim3 grid(MP/128, NP/128);
        k_logits_mma<<<grid, 256, LOG_SMEM>>>(dec_bfc, out + (long)BB*VTT);
    }
}

// round 13
// speedup vs baseline: 1.1275x; 1.0109x over previous
#include <cuda_runtime.h>
#include <cuda_bf16.h>
#include <math.h>
#include <stdint.h>

#define SS 64      // source length
#define BB 32      // batch
#define UU 512     // hidden
#define GG 1536    // 3*U
#define EE 300     // embed dim
#define AD 512     // attention dim
#define VTT 30000  // target vocab
#define TT 32      // target length
#define TM1 31     // T-1 decode steps
#define FF 1836    // 3U + E  (logits feature dim)
#define KX 1324    // 2U + E  (decoder GRU input dim)
#define H2 1024    // 2U
#define MTOT (TM1*BB)   // 992
#define PBLK 96    // step-kernel block count (< 148 SMs -> all resident)

// logits GEMM padded dims
#define KP 1856         // 29 * 64
#define NP 30080        // 235 * 128
#define MP 1024         // 16 * 64
#define KITER 29

// ---------------- device scratch (static, no allocation) ----------------
__device__ float g_emb_s[SS*BB*EE];
__device__ float g_gi_f[SS*BB*GG];
__device__ float g_gi_b[SS*BB*GG];
__device__ float g_outs_f[SS*BB*UU];
__device__ float g_outs_b[SS*BB*UU];
__device__ float g_h[2][2][BB*UU];          // [dir][parity]
__device__ float g_ghp[2][2][BB*GG];        // encoder gh split-K partials (2 chunks)
__device__ float g_enc[BB*SS*H2];           // enc_bt (b,s,2U)
__device__ float g_hfb[BB*H2];
__device__ float g_state[2][BB*UU];         // decoder state ping-pong
__device__ float g_encproj[BB*SS*AD];
__device__ float g_embt[TM1*BB*EE];
__device__ float g_ctx[BB*H2];
__device__ float g_dgp[2][4][BB*GG];        // decoder gi(4)/gh(2) split-K partials
__device__ float g_feat[(long)TM1*BB*FF];
__device__ int   g_ectr[SS];                // per-step barrier counters (encoder)
__device__ int   g_dctr[2*TM1];             // per-step barrier counters (decoder)

// split-bf16 operands for the logits GEMM
__device__ __nv_bfloat16 g_whi[(long)NP*KP];
__device__ __nv_bfloat16 g_wlo[(long)NP*KP];
__device__ __nv_bfloat16 g_ahi[(long)MP*KP];
__device__ __nv_bfloat16 g_alo[(long)MP*KP];

__device__ __forceinline__ float sigm(float x) { return 1.0f / (1.0f + expf(-x)); }

// ---- software grid barrier with backoff (per-step counter slot) ----
__device__ __forceinline__ void gbar(int* ctr, int target) {
    __syncthreads();
    if (threadIdx.x == 0) {
        __threadfence();
        atomicAdd(ctr, 1);
        volatile int* v = ctr;
        while (*v < target) { __nanosleep(64); }
    }
    __syncthreads();
}

// ---- packed f32x2 helpers ----
__device__ __forceinline__ unsigned long long pk2(float x, float y) {
    unsigned long long r;
    asm("mov.b64 %0, {%1, %2};" : "=l"(r) : "f"(x), "f"(y));
    return r;
}
__device__ __forceinline__ void fma2(unsigned long long& d, unsigned long long a, unsigned long long b) {
    asm("fma.rn.f32x2 %0, %1, %2, %0;" : "+l"(d) : "l"(a), "l"(b));
}
__device__ __forceinline__ float2 upk2(unsigned long long v) {
    float2 f;
    asm("mov.b64 {%0, %1}, %2;" : "=f"(f.x), "=f"(f.y) : "l"(v));
    return f;
}

// ---------------- tiny utility kernels ----------------
__global__ void k_zero(float* p, int n) {
    int i = blockIdx.x * blockDim.x + threadIdx.x;
    if (i < n) p[i] = 0.0f;
}

__global__ void k_gather_src(const float* __restrict__ emb, const int* __restrict__ src) {
    int idx = blockIdx.x * blockDim.x + threadIdx.x;
    if (idx >= SS*BB*EE) return;
    int e = idx % EE; int tb = idx / EE;
    g_emb_s[idx] = emb[(long)src[tb]*EE + e];
}

__global__ void k_gather_trg(const float* __restrict__ emb, const int* __restrict__ trg) {
    int idx = blockIdx.x * blockDim.x + threadIdx.x;
    if (idx >= TM1*BB*EE) return;
    int e = idx % EE; int tb = idx / EE;
    g_embt[idx] = emb[(long)trg[tb]*EE + e];
}

__global__ void k_concat_enc() {
    int idx = blockIdx.x * blockDim.x + threadIdx.x;
    if (idx >= BB*SS*H2) return;
    int h = idx % H2; int bs = idx / H2;
    int s = bs % SS, b = bs / SS;
    float v = (h < UU) ? g_outs_f[((long)s*BB + b)*UU + h]
                       : g_outs_b[((long)s*BB + b)*UU + h - UU];
    g_enc[idx] = v;
}

__global__ void k_concat_hfb() {
    int idx = blockIdx.x * blockDim.x + threadIdx.x;
    if (idx >= BB*H2) return;
    int h = idx % H2; int b = idx / H2;
    float v = (h < UU) ? g_outs_f[((long)(SS-1)*BB + b)*UU + h]
                       : g_outs_b[(long)b*UU + h - UU];
    g_hfb[idx] = v;
}

// ---------------- split kernels: fp32 -> bf16 hi/lo ----------------
__global__ void k_split_w4(const float* __restrict__ W) {
    long idx = (long)blockIdx.x * blockDim.x + threadIdx.x;
    long total = (long)NP * (KP/4);
    if (idx >= total) return;
    int kq = (int)(idx % (KP/4)) * 4;
    int n  = (int)(idx / (KP/4));
    float4 x = make_float4(0.f, 0.f, 0.f, 0.f);
    if (n < VTT) {
        if (kq + 4 <= FF) {
            x = *reinterpret_cast<const float4*>(&W[(long)n*FF + kq]);
        } else if (kq < FF) {
            const float* src = &W[(long)n*FF + kq];
            float t[4] = {0,0,0,0};
            for (int j = 0; j < 4; j++) if (kq + j < FF) t[j] = src[j];
            x = make_float4(t[0], t[1], t[2], t[3]);
        }
    }
    __nv_bfloat16 h0 = __float2bfloat16(x.x), h1 = __float2bfloat16(x.y);
    __nv_bfloat16 h2 = __float2bfloat16(x.z), h3 = __float2bfloat16(x.w);
    __nv_bfloat16 l0 = __float2bfloat16(x.x - __bfloat162float(h0));
    __nv_bfloat16 l1 = __float2bfloat16(x.y - __bfloat162float(h1));
    __nv_bfloat16 l2 = __float2bfloat16(x.z - __bfloat162float(h2));
    __nv_bfloat16 l3 = __float2bfloat16(x.w - __bfloat162float(h3));
    long o = (long)n*KP + kq;
    __nv_bfloat162 hA; hA.x = h0; hA.y = h1;
    __nv_bfloat162 hB; hB.x = h2; hB.y = h3;
    __nv_bfloat162 lA; lA.x = l0; lA.y = l1;
    __nv_bfloat162 lB; lB.x = l2; lB.y = l3;
    *reinterpret_cast<__nv_bfloat162*>(&g_whi[o])   = hA;
    *reinterpret_cast<__nv_bfloat162*>(&g_whi[o+2]) = hB;
    *reinterpret_cast<__nv_bfloat162*>(&g_wlo[o])   = lA;
    *reinterpret_cast<__nv_bfloat162*>(&g_wlo[o+2]) = lB;
}

__global__ void k_split_a() {
    long idx = (long)blockIdx.x * blockDim.x + threadIdx.x;
    if (idx >= (long)MP*KP) return;
    int k = (int)(idx % KP); int m = (int)(idx / KP);
    float x = (m < MTOT && k < FF) ? g_feat[(long)m*FF + k] : 0.0f;
    __nv_bfloat16 h = __float2bfloat16(x);
    g_ahi[idx] = h;
    g_alo[idx] = __float2bfloat16(x - __bfloat162float(h));
}

// ---------------- fp32x2 tiled GEMM: C = act(A @ W^T + bias) ----------------
__global__ void __launch_bounds__(256, 2)
k_gemm(const float* __restrict__ Ap, int lda,
       const float* __restrict__ Wp, int ldw, int woff,
       const float* __restrict__ bias,
       float* __restrict__ Cp, int ldc,
       int M, int N, int K, int act)
{
    __shared__ float sA[16][128];
    __shared__ float sW[16][128];
    int tid = threadIdx.x;
    int m0 = blockIdx.y * 128, n0 = blockIdx.x * 128;
    int tr = tid & 15, tc = tid >> 4;

    unsigned long long acc[8][4];
    #pragma unroll
    for (int i = 0; i < 8; i++)
        #pragma unroll
        for (int j = 0; j < 4; j++) acc[i][j] = 0ull;

    int r  = tid >> 2;
    int kq = (tid & 3) * 4;

    for (int k0 = 0; k0 < K; k0 += 16) {
        bool kok = (k0 + kq) < K;
        #pragma unroll
        for (int h = 0; h < 2; h++) {
            int row = r + h * 64;
            float4 va = make_float4(0.f, 0.f, 0.f, 0.f);
            int m = m0 + row;
            if (kok && m < M) va = *reinterpret_cast<const float4*>(&Ap[(long)m*lda + k0 + kq]);
            sA[kq+0][row] = va.x; sA[kq+1][row] = va.y;
            sA[kq+2][row] = va.z; sA[kq+3][row] = va.w;

            float4 vw = make_float4(0.f, 0.f, 0.f, 0.f);
            int n = n0 + row;
            if (kok && n < N) vw = *reinterpret_cast<const float4*>(&Wp[(long)n*ldw + woff + k0 + kq]);
            sW[kq+0][row] = vw.x; sW[kq+1][row] = vw.y;
            sW[kq+2][row] = vw.z; sW[kq+3][row] = vw.w;
        }
        __syncthreads();

        #pragma unroll
        for (int kk = 0; kk < 16; kk++) {
            float4 a0 = *reinterpret_cast<const float4*>(&sA[kk][tr*8]);
            float4 a1 = *reinterpret_cast<const float4*>(&sA[kk][tr*8 + 4]);
            unsigned long long bp[4];
            #pragma unroll
            for (int j = 0; j < 4; j++)
                bp[j] = *reinterpret_cast<const unsigned long long*>(&sW[kk][tc*8 + 2*j]);
            float av[8] = {a0.x, a0.y, a0.z, a0.w, a1.x, a1.y, a1.z, a1.w};
            #pragma unroll
            for (int i = 0; i < 8; i++) {
                unsigned long long ap = pk2(av[i], av[i]);
                #pragma unroll
                for (int j = 0; j < 4; j++) fma2(acc[i][j], ap, bp[j]);
            }
        }
        __syncthreads();
    }

    #pragma unroll
    for (int i = 0; i < 8; i++) {
        int m = m0 + tr*8 + i;
        if (m >= M) continue;
        #pragma unroll
        for (int j = 0; j < 4; j++) {
            float2 v = upk2(acc[i][j]);
            int n = n0 + tc*8 + 2*j;
            if (n < N) {
                float c = v.x + (bias ? bias[n] : 0.0f);
                if (act) c = tanhf(c);
                Cp[(long)m*ldc + n] = c;
            }
            if (n + 1 < N) {
                float c = v.y + (bias ? bias[n+1] : 0.0f);
                if (act) c = tanhf(c);
                Cp[(long)m*ldc + n + 1] = c;
            }
        }
    }
}

// ================= mma.sync bf16 logits GEMM (64x128 tile, 2 CTAs/SM) =================
__device__ __forceinline__ uint32_t smem_u32(const void* p) {
    uint32_t a;
    asm("{ .reg .u64 t; cvta.to.shared.u64 t, %1; cvt.u32.u64 %0, t; }" : "=r"(a) : "l"(p));
    return a;
}
__device__ __forceinline__ void cpa16(uint32_t dst, const void* src) {
    asm volatile("cp.async.cg.shared.global [%0], [%1], 16;" :: "r"(dst), "l"(src) : "memory");
}
__device__ __forceinline__ void cpa_commit() {
    asm volatile("cp.async.commit_group;" ::: "memory");
}
__device__ __forceinline__ void ldsm4(uint32_t* r, uint32_t addr) {
    asm volatile("ldmatrix.sync.aligned.m8n8.x4.shared.b16 {%0,%1,%2,%3}, [%4];"
        : "=r"(r[0]), "=r"(r[1]), "=r"(r[2]), "=r"(r[3]) : "r"(addr));
}
__device__ __forceinline__ void mma16816(float* d, const uint32_t* a, const uint32_t* b) {
    asm volatile("mma.sync.aligned.m16n8k16.row.col.f32.bf16.bf16.f32 "
        "{%0,%1,%2,%3}, {%4,%5,%6,%7}, {%8,%9}, {%0,%1,%2,%3};"
        : "+f"(d[0]), "+f"(d[1]), "+f"(d[2]), "+f"(d[3])
        : "r"(a[0]), "r"(a[1]), "r"(a[2]), "r"(a[3]), "r"(b[0]), "r"(b[1]));
}

// stage: Ahi 8K | Alo 8K | Whi 16K | Wlo 16K = 48KB; 2 stages = 96KB -> 2 CTAs/SM
#define LSTG 49152
#define LOG_SMEM (2*LSTG)

__global__ void __launch_bounds__(256, 2)
k_logits_mma(const float* __restrict__ bias, float* __restrict__ outp)
{
    extern __shared__ __align__(128) char smem[];
    uint32_t sb = smem_u32(smem);
    int tid = threadIdx.x;
    int wid = tid >> 5, lane = tid & 31;
    int wm = wid >> 2, wn = wid & 3;       // 2M x 4N warps; warp tile 32x32
    int grp = lane >> 3, lr = lane & 7;
    int m0 = blockIdx.x * 64;
    int n0 = blockIdx.y * 128;

    float acc[2][4][4];
    #pragma unroll
    for (int i = 0; i < 2; i++)
        #pragma unroll
        for (int j = 0; j < 4; j++)
            #pragma unroll
            for (int c = 0; c < 4; c++) acc[i][j][c] = 0.0f;

    auto load_stage = [&](int it, int s) {
        int k0 = it * 64;
        uint32_t base = sb + s * LSTG;
        // A: 64 rows x 128B (hi at 0, lo at 8192)
        #pragma unroll
        for (int q = 0; q < 2; q++) {
            int u = tid + q * 256;
            int row = u >> 3, c = u & 7;
            uint32_t off = row * 128 + (((uint32_t)(c ^ (row & 7))) << 4);
            long ga = (long)(m0 + row) * KP + k0 + c * 8;
            cpa16(base + off,         g_ahi + ga);
            cpa16(base + 8192 + off,  g_alo + ga);
        }
        // W: 128 rows x 128B (hi at 16384, lo at 32768)
        #pragma unroll
        for (int q = 0; q < 4; q++) {
            int u = tid + q * 256;
            int row = u >> 3, c = u & 7;
            uint32_t off = row * 128 + (((uint32_t)(c ^ (row & 7))) << 4);
            long gb = (long)(n0 + row) * KP + k0 + c * 8;
            cpa16(base + 16384 + off, g_whi + gb);
            cpa16(base + 32768 + off, g_wlo + gb);
        }
    };

    load_stage(0, 0);
    cpa_commit();

    for (int it = 0; it < KITER; it++) {
        int s = it & 1;
        if (it < KITER - 1) {
            load_stage(it + 1, s ^ 1);
            cpa_commit();
            asm volatile("cp.async.wait_group 1;" ::: "memory");
        } else {
            asm volatile("cp.async.wait_group 0;" ::: "memory");
        }
        __syncthreads();

        uint32_t aAhi = sb + s*LSTG;
        uint32_t aAlo = aAhi + 8192;
        uint32_t aBhi = aAhi + 16384;
        uint32_t aBlo = aAhi + 32768;

        #pragma unroll
        for (int ks = 0; ks < 4; ks++) {
            uint32_t fa_hi[2][4], fa_lo[2][4];
            #pragma unroll
            for (int mt = 0; mt < 2; mt++) {
                int row = wm*32 + mt*16 + lr + (grp & 1) * 8;
                int c = 2*ks + (grp >> 1);
                uint32_t off = row * 128 + (((uint32_t)(c ^ (row & 7))) << 4);
                ldsm4(fa_hi[mt], aAhi + off);
                ldsm4(fa_lo[mt], aAlo + off);
            }
            uint32_t fb_hi[2][4], fb_lo[2][4];
            #pragma unroll
            for (int p = 0; p < 2; p++) {
                int nrow = wn*32 + p*16 + lr + (grp >> 1) * 8;
                int c = 2*ks + (grp & 1);
                uint32_t off = nrow * 128 + (((uint32_t)(c ^ (nrow & 7))) << 4);
                ldsm4(fb_hi[p], aBhi + off);
                ldsm4(fb_lo[p], aBlo + off);
            }
            #pragma unroll
            for (int mt = 0; mt < 2; mt++) {
                #pragma unroll
                for (int nt = 0; nt < 4; nt++) {
                    const uint32_t* bh = &fb_hi[nt >> 1][(nt & 1) * 2];
                    const uint32_t* bl = &fb_lo[nt >> 1][(nt & 1) * 2];
                    mma16816(acc[mt][nt], fa_hi[mt], bh);
                    mma16816(acc[mt][nt], fa_lo[mt], bh);
                    mma16816(acc[mt][nt], fa_hi[mt], bl);
                }
            }
        }
        __syncthreads();
    }

    int mrow = (lane >> 2);
    int ncol = (lane & 3) * 2;
    #pragma unroll
    for (int mt = 0; mt < 2; mt++) {
        #pragma unroll
        for (int nt = 0; nt < 4; nt++) {
            int n = n0 + wn*32 + nt*8 + ncol;
            if (n >= VTT) continue;
            float2 bv = *reinterpret_cast<const float2*>(&bias[n]);
            int m1 = m0 + wm*32 + mt*16 + mrow;
            int m2 = m1 + 8;
            if (m1 < MTOT) {
                float2 v = make_float2(acc[mt][nt][0] + bv.x, acc[mt][nt][1] + bv.y);
                *reinterpret_cast<float2*>(&outp[(long)m1*VTT + n]) = v;
            }
            if (m2 < MTOT) {
                float2 v = make_float2(acc[mt][nt][2] + bv.x, acc[mt][nt][3] + bv.y);
                *reinterpret_cast<float2*>(&outp[(long)m2*VTT + n]) = v;
            }
        }
    }
}

// ================= encoder step kernel (gh GEMM + barrier + gate) =================
__global__ void __launch_bounds__(256, 1)
k_enc_step(int step,
           const float* __restrict__ Whh_f, const float* __restrict__ Whh_b,
           const float* __restrict__ bhh_f, const float* __restrict__ bhh_b)
{
    __shared__ float sA[16][32];
    __shared__ float sW[16][64];
    int blk = blockIdx.x, tid = threadIdx.x;
    int par = step & 1;
    int dir = blk >= 48;
    int rem = dir ? blk - 48 : blk;
    int ntile = rem >> 1;
    int kc = rem & 1;
    int n0 = ntile * 64;
    int kbase = kc * 256;
    const float* W = dir ? Whh_b : Whh_f;
    const float* h = g_h[dir][par];
    int tm = tid & 15, tn = tid >> 4;
    float acc[2][4] = {};

    for (int k0 = 0; k0 < 256; k0 += 16) {
        int r = tid >> 2, kq = (tid & 3) * 4;
        if (tid < 128) {
            float4 v = *(const float4*)&h[r*UU + kbase + k0 + kq];
            sA[kq+0][r] = v.x; sA[kq+1][r] = v.y;
            sA[kq+2][r] = v.z; sA[kq+3][r] = v.w;
        }
        {
            float4 v = *(const float4*)&W[(long)(n0+r)*UU + kbase + k0 + kq];
            sW[kq+0][r] = v.x; sW[kq+1][r] = v.y;
            sW[kq+2][r] = v.z; sW[kq+3][r] = v.w;
        }
        __syncthreads();
        #pragma unroll
        for (int kk = 0; kk < 16; kk++) {
            float2 a2 = *reinterpret_cast<const float2*>(&sA[kk][tm*2]);
            float4 b4 = *reinterpret_cast<const float4*>(&sW[kk][tn*4]);
            acc[0][0] = fmaf(a2.x, b4.x, acc[0][0]);
            acc[0][1] = fmaf(a2.x, b4.y, acc[0][1]);
            acc[0][2] = fmaf(a2.x, b4.z, acc[0][2]);
            acc[0][3] = fmaf(a2.x, b4.w, acc[0][3]);
            acc[1][0] = fmaf(a2.y, b4.x, acc[1][0]);
            acc[1][1] = fmaf(a2.y, b4.y, acc[1][1]);
            acc[1][2] = fmaf(a2.y, b4.z, acc[1][2]);
            acc[1][3] = fmaf(a2.y, b4.w, acc[1][3]);
        }
        __syncthreads();
    }
    float* outp = &g_ghp[dir][kc][0];
    #pragma unroll
    for (int i = 0; i < 2; i++) {
        int b = tm*2 + i;
        #pragma unroll
        for (int j = 0; j < 4; j++)
            outp[b*GG + n0 + tn*4 + j] = acc[i][j];
    }

    gbar(&g_ectr[step], PBLK);

    int tf = step, tb = SS-1-step;
    for (int idx = blk*256 + tid; idx < 2*BB*UU; idx += PBLK*256) {
        int u = idx & 511;
        int b = (idx >> 9) & 31;
        int d2 = idx >> 14;
        const float* gi = d2 ? (g_gi_b + (long)tb*BB*GG) : (g_gi_f + (long)tf*BB*GG);
        const float* bhh = d2 ? bhh_b : bhh_f;
        float ghr = bhh[u]      + __ldcg(&g_ghp[d2][0][b*GG+u])      + __ldcg(&g_ghp[d2][1][b*GG+u]);
        float ghz = bhh[u+UU]   + __ldcg(&g_ghp[d2][0][b*GG+u+UU])   + __ldcg(&g_ghp[d2][1][b*GG+u+UU]);
        float ghn = bhh[u+2*UU] + __ldcg(&g_ghp[d2][0][b*GG+u+2*UU]) + __ldcg(&g_ghp[d2][1][b*GG+u+2*UU]);
        float ir = gi[b*GG + u], iz = gi[b*GG + u + UU], inn = gi[b*GG + u + 2*UU];
        float r = sigm(ir + ghr);
        float z = sigm(iz + ghz);
        float n = tanhf(inn + r*ghn);
        float hp = g_h[d2][par][b*UU + u];
        float hn_ = (1.0f - z)*n + z*hp;
        g_h[d2][par^1][b*UU + u] = hn_;
        float* outs = d2 ? (g_outs_b + (long)tb*BB*UU) : (g_outs_f + (long)tf*BB*UU);
        outs[b*UU + u] = hn_;
    }
}

// ================= decoder step kernel (attn||gh + gi + gate, 2 barriers) =================
__global__ void __launch_bounds__(256, 1)
k_dec_step(int t,
           const float* __restrict__ attn_W,
           const float* __restrict__ Wih, const float* __restrict__ Whh,
           const float* __restrict__ bih, const float* __restrict__ bhh)
{
    __shared__ float sA[16][32];
    __shared__ float sW[16][64];
    __shared__ float s_st[UU];
    __shared__ float s_tp[AD];
    __shared__ float s_sc[SS];
    __shared__ float s_red[2];

    int blk = blockIdx.x, tid = threadIdx.x;
    int tm = tid & 15, tn = tid >> 4;
    int spar = t & 1;
    const float* st_g = g_state[spar];

    if (blk < 32) {
        int b = blk;
        const float* st = &st_g[b*UU];
        for (int i = tid; i < UU; i += 256) s_st[i] = st[i];
        __syncthreads();
        for (int a = tid; a < AD; a += 256) {
            const float* w = attn_W + (long)a*GG;
            float acc = 0.0f;
            #pragma unroll 4
            for (int k = 0; k < UU; k += 4) {
                float4 wv = *reinterpret_cast<const float4*>(w + k);
                acc = fmaf(s_st[k],   wv.x, acc);
                acc = fmaf(s_st[k+1], wv.y, acc);
                acc = fmaf(s_st[k+2], wv.z, acc);
                acc = fmaf(s_st[k+3], wv.w, acc);
            }
            s_tp[a] = acc;
        }
        __syncthreads();
        {
            int s = tid >> 2, q = tid & 3;
            const float* ep = g_encproj + ((long)b*SS + s)*AD + q*128;
            const float* tp = s_tp + q*128;
            float partial = 0.0f;
            for (int a = 0; a < 128; a++) partial += tanhf(tp[a] + ep[a]);
            partial += __shfl_down_sync(0xffffffffu, partial, 2);
            partial += __shfl_down_sync(0xffffffffu, partial, 1);
            if (q == 0) s_sc[s] = partial;
        }
        __syncthreads();
        if (tid == 0) {
            float mx = s_sc[0];
            for (int s = 1; s < SS; s++) mx = fmaxf(mx, s_sc[s]);
            s_red[0] = mx;
        }
        __syncthreads();
        if (tid < SS) s_sc[tid] = expf(s_sc[tid] - s_red[0]);
        __syncthreads();
        if (tid == 0) {
            float sm = 0.0f;
            for (int s = 0; s < SS; s++) sm += s_sc[s];
            s_red[1] = 1.0f / sm;
        }
        __syncthreads();
        float inv = s_red[1];
        for (int h = tid; h < H2; h += 256) {
            const float* e = g_enc + (long)b*SS*H2 + h;
            float acc = 0.0f;
            #pragma unroll 8
            for (int s = 0; s < SS; s++) acc = fmaf(s_sc[s], e[(long)s*H2], acc);
            g_ctx[b*H2 + h] = acc * inv;
        }
    } else if (blk < 80) {
        int idx2 = blk - 32;
        int ntile = idx2 >> 1;
        int kc = idx2 & 1;
        int n0 = ntile * 64;
        int kbase = kc * 256;
        float acc[2][4] = {};
        for (int k0 = 0; k0 < 256; k0 += 16) {
            int r = tid >> 2, kq = (tid & 3) * 4;
            if (tid < 128) {
                float4 v = *(const float4*)&st_g[r*UU + kbase + k0 + kq];
                sA[kq+0][r] = v.x; sA[kq+1][r] = v.y;
                sA[kq+2][r] = v.z; sA[kq+3][r] = v.w;
            }
            {
                float4 v = *(const float4*)&Whh[(long)(n0+r)*UU + kbase + k0 + kq];
                sW[kq+0][r] = v.x; sW[kq+1][r] = v.y;
                sW[kq+2][r] = v.z; sW[kq+3][r] = v.w;
            }
            __syncthreads();
            #pragma unroll
            for (int kk = 0; kk < 16; kk++) {
                float2 a2 = *reinterpret_cast<const float2*>(&sA[kk][tm*2]);
                float4 b4 = *reinterpret_cast<const float4*>(&sW[kk][tn*4]);
                acc[0][0] = fmaf(a2.x, b4.x, acc[0][0]);
                acc[0][1] = fmaf(a2.x, b4.y, acc[0][1]);
                acc[0][2] = fmaf(a2.x, b4.z, acc[0][2]);
                acc[0][3] = fmaf(a2.x, b4.w, acc[0][3]);
                acc[1][0] = fmaf(a2.y, b4.x, acc[1][0]);
                acc[1][1] = fmaf(a2.y, b4.y, acc[1][1]);
                acc[1][2] = fmaf(a2.y, b4.z, acc[1][2]);
                acc[1][3] = fmaf(a2.y, b4.w, acc[1][3]);
            }
            __syncthreads();
        }
        float* outp = &g_dgp[1][kc][0];
        #pragma unroll
        for (int i = 0; i < 2; i++) {
            int b = tm*2 + i;
            #pragma unroll
            for (int j = 0; j < 4; j++)
                outp[b*GG + n0 + tn*4 + j] = acc[i][j];
        }
    }
    gbar(&g_dctr[2*t], PBLK);

    {
        int ntile = blk >> 2;
        int kc = blk & 3;
        int n0 = ntile * 64;
        int kbeg = kc * 331;
        int kend = kbeg + 331;
        const float* em = g_embt + (long)t*BB*EE;
        float acc[2][4] = {};
        for (int k0 = kbeg; k0 < kend; k0 += 16) {
            int r = tid >> 2, kq = (tid & 3) * 4;
            if (tid < 128) {
                #pragma unroll
                for (int j = 0; j < 4; j++) {
                    int k = k0 + kq + j;
                    float v = 0.0f;
                    if (k < kend)
                        v = (k < EE) ? em[r*EE + k] : __ldcg(&g_ctx[r*H2 + k - EE]);
                    sA[kq+j][r] = v;
                }
            }
            {
                #pragma unroll
                for (int j = 0; j < 4; j++) {
                    int k = k0 + kq + j;
                    sW[kq+j][r] = (k < kend) ? Wih[(long)(n0+r)*KX + k] : 0.0f;
                }
            }
            __syncthreads();
            #pragma unroll
            for (int kk = 0; kk < 16; kk++) {
                float2 a2 = *reinterpret_cast<const float2*>(&sA[kk][tm*2]);
                float4 b4 = *reinterpret_cast<const float4*>(&sW[kk][tn*4]);
                acc[0][0] = fmaf(a2.x, b4.x, acc[0][0]);
                acc[0][1] = fmaf(a2.x, b4.y, acc[0][1]);
                acc[0][2] = fmaf(a2.x, b4.z, acc[0][2]);
                acc[0][3] = fmaf(a2.x, b4.w, acc[0][3]);
                acc[1][0] = fmaf(a2.y, b4.x, acc[1][0]);
                acc[1][1] = fmaf(a2.y, b4.y, acc[1][1]);
                acc[1][2] = fmaf(a2.y, b4.z, acc[1][2]);
                acc[1][3] = fmaf(a2.y, b4.w, acc[1][3]);
            }
            __syncthreads();
        }
        float* outp = &g_dgp[0][kc][0];
        #pragma unroll
        for (int i = 0; i < 2; i++) {
            int b = tm*2 + i;
            #pragma unroll
            for (int j = 0; j < 4; j++)
                outp[b*GG + n0 + tn*4 + j] = acc[i][j];
        }
    }
    gbar(&g_dctr[2*t+1], PBLK);

    for (int idx = blk*256 + tid; idx < BB*FF; idx += PBLK*256) {
        int f = idx % FF; int b = idx / FF;
        float* feat = g_feat + ((long)t*BB + b)*FF;
        if (f < UU) {
            int u = f;
            float gir = bih[u], giz = bih[u+UU], gin = bih[u+2*UU];
            float ghr = bhh[u], ghz = bhh[u+UU], ghn = bhh[u+2*UU];
            #pragma unroll
            for (int kc = 0; kc < 4; kc++) {
                const float* pi = &g_dgp[0][kc][b*GG];
                gir += __ldcg(&pi[u]); giz += __ldcg(&pi[u+UU]); gin += __ldcg(&pi[u+2*UU]);
            }
            #pragma unroll
            for (int kc = 0; kc < 2; kc++) {
                const float* ph = &g_dgp[1][kc][b*GG];
                ghr += __ldcg(&ph[u]); ghz += __ldcg(&ph[u+UU]); ghn += __ldcg(&ph[u+2*UU]);
            }
            float r = sigm(gir + ghr);
            float z = sigm(giz + ghz);
            float n = tanhf(gin + r*ghn);
            float hp = st_g[b*UU + u];
            float h2 = (1.0f - z)*n + z*hp;
            g_state[spar^1][b*UU + u] = h2;
            feat[u] = h2;
        } else if (f < UU + H2) {
            feat[f] = __ldcg(&g_ctx[b*H2 + f - UU]);
        } else {
            feat[f] = g_embt[((long)t*BB + b)*EE + f - UU - H2];
        }
    }
}

// ---------------- host launch ----------------
static float* symaddr(const void* sym) {
    void* p = nullptr;
    cudaGetSymbolAddress(&p, sym);
    return (float*)p;
}

extern "C" void kernel_launch(void* const* d_in, const int* in_sizes, int n_in,
                              void* d_out, int out_size)
{
    const float* emb_src   = (const float*)d_in[0];
    const float* emb_trg   = (const float*)d_in[1];
    const float* enc_Wih_f = (const float*)d_in[2];
    const float* enc_Whh_f = (const float*)d_in[3];
    const float* enc_bih_f = (const float*)d_in[4];
    const float* enc_bhh_f = (const float*)d_in[5];
    const float* enc_Wih_b = (const float*)d_in[6];
    const float* enc_Whh_b = (const float*)d_in[7];
    const float* enc_bih_b = (const float*)d_in[8];
    const float* enc_bhh_b = (const float*)d_in[9];
    const float* enc_Wfc   = (const float*)d_in[10];
    const float* enc_bfc   = (const float*)d_in[11];
    const float* attn_W    = (const float*)d_in[12];
    const float* attn_b    = (const float*)d_in[13];
    const float* dec_Wih   = (const float*)d_in[14];
    const float* dec_Whh   = (const float*)d_in[15];
    const float* dec_bih   = (const float*)d_in[16];
    const float* dec_bhh   = (const float*)d_in[17];
    const float* dec_Wfc   = (const float*)d_in[18];
    const float* dec_bfc   = (const float*)d_in[19];
    const int*   source    = (const int*)d_in[20];
    const int*   target    = (const int*)d_in[21];
    float* out = (float*)d_out;

    float* p_emb_s   = symaddr(g_emb_s);
    float* p_gi_f    = symaddr(g_gi_f);
    float* p_gi_b    = symaddr(g_gi_b);
    float* p_h       = symaddr(g_h);
    float* p_enc     = symaddr(g_enc);
    float* p_hfb     = symaddr(g_hfb);
    float* p_state   = symaddr(g_state);
    float* p_encproj = symaddr(g_encproj);
    float* p_ectr    = symaddr(g_ectr);
    float* p_dctr    = symaddr(g_dctr);

    static int attr_set = 0;
    if (!attr_set) {
        cudaFuncSetAttribute(k_logits_mma, cudaFuncAttributeMaxDynamicSharedMemorySize, LOG_SMEM);
        attr_set = 1;
    }

    // reset per-step barrier counters (once per replay)
    k_zero<<<1, 128>>>(p_ectr, SS);
    k_zero<<<1, 128>>>(p_dctr, 2*TM1);

    // split dec_Wfc into bf16 hi/lo (vectorized)
    {
        long total = (long)NP * (KP/4);
        k_split_w4<<<(unsigned)((total + 255)/256), 256>>>(dec_Wfc);
    }

    // init h = 0
    k_zero<<<(2*2*BB*UU + 255)/256, 256>>>(p_h, 2*2*BB*UU);

    // gather source embeddings
    k_gather_src<<<(SS*BB*EE + 255)/256, 256>>>(emb_src, source);

    // gi_f / gi_b
    {
        dim3 grid(GG/128, (SS*BB)/128);
        k_gemm<<<grid, 256>>>(p_emb_s, EE, enc_Wih_f, EE, 0, enc_bih_f,
                              p_gi_f, GG, SS*BB, GG, EE, 0);
        k_gemm<<<grid, 256>>>(p_emb_s, EE, enc_Wih_b, EE, 0, enc_bih_b,
                              p_gi_b, GG, SS*BB, GG, EE, 0);
    }

    // encoder recurrence: one fused kernel per step
    for (int i = 0; i < SS; i++) {
        k_enc_step<<<PBLK, 256>>>(i, enc_Whh_f, enc_Whh_b, enc_bhh_f, enc_bhh_b);
    }

    k_concat_enc<<<(BB*SS*H2 + 255)/256, 256>>>();
    k_concat_hfb<<<(BB*H2 + 255)/256, 256>>>();

    // decoder init state
    {
        dim3 grid((UU + 127)/128, 1);
        k_gemm<<<grid, 256>>>(p_hfb, H2, enc_Wfc, H2, 0, enc_bfc,
                              p_state, UU, BB, UU, H2, 1);
    }

    // enc_proj
    {
        dim3 grid(AD/128, (BB*SS)/128);
        k_gemm<<<grid, 256>>>(p_enc, H2, attn_W, GG, UU, attn_b,
                              p_encproj, AD, BB*SS, AD, H2, 0);
    }

    k_gather_trg<<<(TM1*BB*EE + 255)/256, 256>>>(emb_trg, target);

    // decoder recurrence: one fused kernel per step
    for (int t = 0; t < TM1; t++) {
        k_dec_step<<<PBLK, 256>>>(t, attn_W, dec_Wih, dec_Whh, dec_bih, dec_bhh);
    }

    // split features into bf16 hi/lo
    {
        long na = (long)MP*KP;
        k_split_a<<<(unsigned)((na + 255)/256), 256>>>();
    }

    // output row 0 = zeros
    k_zero<<<(BB*VTT + 255)/256, 256>>>(out, BB*VTT);

    // logits on tensor cores (64x128 tiles, 2 CTAs/SM)
    {
        dim3 grid(MP/64, NP/128);
        k_logits_mma<<<grid, 256, LOG_SMEM>>>(dec_bfc, out + (long)BB*VTT);
    }
}

// round 14
// speedup vs baseline: 1.2640x; 1.1211x over previous
#include <cuda_runtime.h>
#include <cuda_bf16.h>
#include <math.h>
#include <stdint.h>

#define SS 64      // source length
#define BB 32      // batch
#define UU 512     // hidden
#define GG 1536    // 3*U
#define EE 300     // embed dim
#define AD 512     // attention dim
#define VTT 30000  // target vocab
#define TT 32      // target length
#define TM1 31     // T-1 decode steps
#define FF 1836    // 3U + E
#define KX 1324    // 2U + E
#define H2 1024    // 2U
#define MTOT (TM1*BB)   // 992
#define PBLK 192   // step-kernel block count (2 CTAs/SM co-resident)

// logits GEMM padded dims
#define KP 1856
#define NP 30080
#define MP 1024
#define KITER 29

// ---------------- device scratch ----------------
__device__ float g_emb_s[SS*BB*EE];
__device__ float g_gi_f[SS*BB*GG];
__device__ float g_gi_b[SS*BB*GG];
__device__ float g_outs_f[SS*BB*UU];
__device__ float g_outs_b[SS*BB*UU];
__device__ float g_h[2][2][BB*UU];
__device__ float g_ghp[2][4][BB*GG];        // encoder gh split-K partials (4 chunks)
__device__ float g_enc[BB*SS*H2];
__device__ float g_hfb[BB*H2];
__device__ float g_state[2][BB*UU];
__device__ float g_encproj[BB*SS*AD];
__device__ float g_embt[TM1*BB*EE];
__device__ float g_ctx[BB*H2];
__device__ float g_dgi[8][BB*GG];           // decoder gi partials (8 chunks)
__device__ float g_dgh[4][BB*GG];           // decoder gh partials (4 chunks)
__device__ float g_feat[(long)TM1*BB*FF];
__device__ int   g_ctr[SS + 2*TM1];         // per-phase barrier counters

// split-bf16 operands for the logits GEMM
__device__ __nv_bfloat16 g_whi[(long)NP*KP];
__device__ __nv_bfloat16 g_wlo[(long)NP*KP];
__device__ __nv_bfloat16 g_ahi[(long)MP*KP];
__device__ __nv_bfloat16 g_alo[(long)MP*KP];

__device__ __forceinline__ float sigm(float x) { return 1.0f / (1.0f + expf(-x)); }

__device__ __forceinline__ void gbar(int* ctr, int target) {
    __syncthreads();
    if (threadIdx.x == 0) {
        __threadfence();
        atomicAdd(ctr, 1);
        volatile int* v = ctr;
        while (*v < target) { __nanosleep(64); }
    }
    __syncthreads();
}

// ---- packed f32x2 helpers ----
__device__ __forceinline__ unsigned long long pk2(float x, float y) {
    unsigned long long r;
    asm("mov.b64 %0, {%1, %2};" : "=l"(r) : "f"(x), "f"(y));
    return r;
}
__device__ __forceinline__ void fma2(unsigned long long& d, unsigned long long a, unsigned long long b) {
    asm("fma.rn.f32x2 %0, %1, %2, %0;" : "+l"(d) : "l"(a), "l"(b));
}
__device__ __forceinline__ float2 upk2(unsigned long long v) {
    float2 f;
    asm("mov.b64 {%0, %1}, %2;" : "=f"(f.x), "=f"(f.y) : "l"(v));
    return f;
}

// ---------------- tiny utility kernels ----------------
__global__ void k_zero(float* p, int n) {
    int i = blockIdx.x * blockDim.x + threadIdx.x;
    if (i < n) p[i] = 0.0f;
}

__global__ void k_gather_src(const float* __restrict__ emb, const int* __restrict__ src) {
    int idx = blockIdx.x * blockDim.x + threadIdx.x;
    if (idx >= SS*BB*EE) return;
    int e = idx % EE; int tb = idx / EE;
    g_emb_s[idx] = emb[(long)src[tb]*EE + e];
}

__global__ void k_gather_trg(const float* __restrict__ emb, const int* __restrict__ trg) {
    int idx = blockIdx.x * blockDim.x + threadIdx.x;
    if (idx >= TM1*BB*EE) return;
    int e = idx % EE; int tb = idx / EE;
    g_embt[idx] = emb[(long)trg[tb]*EE + e];
}

__global__ void k_concat_enc() {
    int idx = blockIdx.x * blockDim.x + threadIdx.x;
    if (idx >= BB*SS*H2) return;
    int h = idx % H2; int bs = idx / H2;
    int s = bs % SS, b = bs / SS;
    float v = (h < UU) ? g_outs_f[((long)s*BB + b)*UU + h]
                       : g_outs_b[((long)s*BB + b)*UU + h - UU];
    g_enc[idx] = v;
}

__global__ void k_concat_hfb() {
    int idx = blockIdx.x * blockDim.x + threadIdx.x;
    if (idx >= BB*H2) return;
    int h = idx % H2; int b = idx / H2;
    float v = (h < UU) ? g_outs_f[((long)(SS-1)*BB + b)*UU + h]
                       : g_outs_b[(long)b*UU + h - UU];
    g_hfb[idx] = v;
}

// ---------------- split kernels ----------------
__global__ void k_split_w4(const float* __restrict__ W) {
    long idx = (long)blockIdx.x * blockDim.x + threadIdx.x;
    long total = (long)NP * (KP/4);
    if (idx >= total) return;
    int kq = (int)(idx % (KP/4)) * 4;
    int n  = (int)(idx / (KP/4));
    float4 x = make_float4(0.f, 0.f, 0.f, 0.f);
    if (n < VTT) {
        if (kq + 4 <= FF) {
            x = *reinterpret_cast<const float4*>(&W[(long)n*FF + kq]);
        } else if (kq < FF) {
            const float* src = &W[(long)n*FF + kq];
            float t[4] = {0,0,0,0};
            for (int j = 0; j < 4; j++) if (kq + j < FF) t[j] = src[j];
            x = make_float4(t[0], t[1], t[2], t[3]);
        }
    }
    __nv_bfloat16 h0 = __float2bfloat16(x.x), h1 = __float2bfloat16(x.y);
    __nv_bfloat16 h2 = __float2bfloat16(x.z), h3 = __float2bfloat16(x.w);
    __nv_bfloat16 l0 = __float2bfloat16(x.x - __bfloat162float(h0));
    __nv_bfloat16 l1 = __float2bfloat16(x.y - __bfloat162float(h1));
    __nv_bfloat16 l2 = __float2bfloat16(x.z - __bfloat162float(h2));
    __nv_bfloat16 l3 = __float2bfloat16(x.w - __bfloat162float(h3));
    long o = (long)n*KP + kq;
    __nv_bfloat162 hA; hA.x = h0; hA.y = h1;
    __nv_bfloat162 hB; hB.x = h2; hB.y = h3;
    __nv_bfloat162 lA; lA.x = l0; lA.y = l1;
    __nv_bfloat162 lB; lB.x = l2; lB.y = l3;
    *reinterpret_cast<__nv_bfloat162*>(&g_whi[o])   = hA;
    *reinterpret_cast<__nv_bfloat162*>(&g_whi[o+2]) = hB;
    *reinterpret_cast<__nv_bfloat162*>(&g_wlo[o])   = lA;
    *reinterpret_cast<__nv_bfloat162*>(&g_wlo[o+2]) = lB;
}

__global__ void k_split_a() {
    long idx = (long)blockIdx.x * blockDim.x + threadIdx.x;
    if (idx >= (long)MP*KP) return;
    int k = (int)(idx % KP); int m = (int)(idx / KP);
    float x = (m < MTOT && k < FF) ? g_feat[(long)m*FF + k] : 0.0f;
    __nv_bfloat16 h = __float2bfloat16(x);
    g_ahi[idx] = h;
    g_alo[idx] = __float2bfloat16(x - __bfloat162float(h));
}

// ---------------- fp32x2 tiled GEMM ----------------
__global__ void __launch_bounds__(256, 2)
k_gemm(const float* __restrict__ Ap, int lda,
       const float* __restrict__ Wp, int ldw, int woff,
       const float* __restrict__ bias,
       float* __restrict__ Cp, int ldc,
       int M, int N, int K, int act)
{
    __shared__ float sA[16][128];
    __shared__ float sW[16][128];
    int tid = threadIdx.x;
    int m0 = blockIdx.y * 128, n0 = blockIdx.x * 128;
    int tr = tid & 15, tc = tid >> 4;

    unsigned long long acc[8][4];
    #pragma unroll
    for (int i = 0; i < 8; i++)
        #pragma unroll
        for (int j = 0; j < 4; j++) acc[i][j] = 0ull;

    int r  = tid >> 2;
    int kq = (tid & 3) * 4;

    for (int k0 = 0; k0 < K; k0 += 16) {
        bool kok = (k0 + kq) < K;
        #pragma unroll
        for (int h = 0; h < 2; h++) {
            int row = r + h * 64;
            float4 va = make_float4(0.f, 0.f, 0.f, 0.f);
            int m = m0 + row;
            if (kok && m < M) va = *reinterpret_cast<const float4*>(&Ap[(long)m*lda + k0 + kq]);
            sA[kq+0][row] = va.x; sA[kq+1][row] = va.y;
            sA[kq+2][row] = va.z; sA[kq+3][row] = va.w;

            float4 vw = make_float4(0.f, 0.f, 0.f, 0.f);
            int n = n0 + row;
            if (kok && n < N) vw = *reinterpret_cast<const float4*>(&Wp[(long)n*ldw + woff + k0 + kq]);
            sW[kq+0][row] = vw.x; sW[kq+1][row] = vw.y;
            sW[kq+2][row] = vw.z; sW[kq+3][row] = vw.w;
        }
        __syncthreads();

        #pragma unroll
        for (int kk = 0; kk < 16; kk++) {
            float4 a0 = *reinterpret_cast<const float4*>(&sA[kk][tr*8]);
            float4 a1 = *reinterpret_cast<const float4*>(&sA[kk][tr*8 + 4]);
            unsigned long long bp[4];
            #pragma unroll
            for (int j = 0; j < 4; j++)
                bp[j] = *reinterpret_cast<const unsigned long long*>(&sW[kk][tc*8 + 2*j]);
            float av[8] = {a0.x, a0.y, a0.z, a0.w, a1.x, a1.y, a1.z, a1.w};
            #pragma unroll
            for (int i = 0; i < 8; i++) {
                unsigned long long ap = pk2(av[i], av[i]);
                #pragma unroll
                for (int j = 0; j < 4; j++) fma2(acc[i][j], ap, bp[j]);
            }
        }
        __syncthreads();
    }

    #pragma unroll
    for (int i = 0; i < 8; i++) {
        int m = m0 + tr*8 + i;
        if (m >= M) continue;
        #pragma unroll
        for (int j = 0; j < 4; j++) {
            float2 v = upk2(acc[i][j]);
            int n = n0 + tc*8 + 2*j;
            if (n < N) {
                float c = v.x + (bias ? bias[n] : 0.0f);
                if (act) c = tanhf(c);
                Cp[(long)m*ldc + n] = c;
            }
            if (n + 1 < N) {
                float c = v.y + (bias ? bias[n+1] : 0.0f);
                if (act) c = tanhf(c);
                Cp[(long)m*ldc + n + 1] = c;
            }
        }
    }
}

// ================= mma.sync bf16 logits GEMM (64x128 tile, 2 CTAs/SM) =================
__device__ __forceinline__ uint32_t smem_u32(const void* p) {
    uint32_t a;
    asm("{ .reg .u64 t; cvta.to.shared.u64 t, %1; cvt.u32.u64 %0, t; }" : "=r"(a) : "l"(p));
    return a;
}
__device__ __forceinline__ void cpa16(uint32_t dst, const void* src) {
    asm volatile("cp.async.cg.shared.global [%0], [%1], 16;" :: "r"(dst), "l"(src) : "memory");
}
__device__ __forceinline__ void cpa_commit() {
    asm volatile("cp.async.commit_group;" ::: "memory");
}
__device__ __forceinline__ void ldsm4(uint32_t* r, uint32_t addr) {
    asm volatile("ldmatrix.sync.aligned.m8n8.x4.shared.b16 {%0,%1,%2,%3}, [%4];"
        : "=r"(r[0]), "=r"(r[1]), "=r"(r[2]), "=r"(r[3]) : "r"(addr));
}
__device__ __forceinline__ void mma16816(float* d, const uint32_t* a, const uint32_t* b) {
    asm volatile("mma.sync.aligned.m16n8k16.row.col.f32.bf16.bf16.f32 "
        "{%0,%1,%2,%3}, {%4,%5,%6,%7}, {%8,%9}, {%0,%1,%2,%3};"
        : "+f"(d[0]), "+f"(d[1]), "+f"(d[2]), "+f"(d[3])
        : "r"(a[0]), "r"(a[1]), "r"(a[2]), "r"(a[3]), "r"(b[0]), "r"(b[1]));
}

#define LSTG 49152
#define LOG_SMEM (2*LSTG)

__global__ void __launch_bounds__(256, 2)
k_logits_mma(const float* __restrict__ bias, float* __restrict__ outp)
{
    extern __shared__ __align__(128) char smem[];
    uint32_t sb = smem_u32(smem);
    int tid = threadIdx.x;
    int wid = tid >> 5, lane = tid & 31;
    int wm = wid >> 2, wn = wid & 3;
    int grp = lane >> 3, lr = lane & 7;
    int m0 = blockIdx.x * 64;
    int n0 = blockIdx.y * 128;

    float acc[2][4][4];
    #pragma unroll
    for (int i = 0; i < 2; i++)
        #pragma unroll
        for (int j = 0; j < 4; j++)
            #pragma unroll
            for (int c = 0; c < 4; c++) acc[i][j][c] = 0.0f;

    auto load_stage = [&](int it, int s) {
        int k0 = it * 64;
        uint32_t base = sb + s * LSTG;
        #pragma unroll
        for (int q = 0; q < 2; q++) {
            int u = tid + q * 256;
            int row = u >> 3, c = u & 7;
            uint32_t off = row * 128 + (((uint32_t)(c ^ (row & 7))) << 4);
            long ga = (long)(m0 + row) * KP + k0 + c * 8;
            cpa16(base + off,         g_ahi + ga);
            cpa16(base + 8192 + off,  g_alo + ga);
        }
        #pragma unroll
        for (int q = 0; q < 4; q++) {
            int u = tid + q * 256;
            int row = u >> 3, c = u & 7;
            uint32_t off = row * 128 + (((uint32_t)(c ^ (row & 7))) << 4);
            long gb = (long)(n0 + row) * KP + k0 + c * 8;
            cpa16(base + 16384 + off, g_whi + gb);
            cpa16(base + 32768 + off, g_wlo + gb);
        }
    };

    load_stage(0, 0);
    cpa_commit();

    for (int it = 0; it < KITER; it++) {
        int s = it & 1;
        if (it < KITER - 1) {
            load_stage(it + 1, s ^ 1);
            cpa_commit();
            asm volatile("cp.async.wait_group 1;" ::: "memory");
        } else {
            asm volatile("cp.async.wait_group 0;" ::: "memory");
        }
        __syncthreads();

        uint32_t aAhi = sb + s*LSTG;
        uint32_t aAlo = aAhi + 8192;
        uint32_t aBhi = aAhi + 16384;
        uint32_t aBlo = aAhi + 32768;

        #pragma unroll
        for (int ks = 0; ks < 4; ks++) {
            uint32_t fa_hi[2][4], fa_lo[2][4];
            #pragma unroll
            for (int mt = 0; mt < 2; mt++) {
                int row = wm*32 + mt*16 + lr + (grp & 1) * 8;
                int c = 2*ks + (grp >> 1);
                uint32_t off = row * 128 + (((uint32_t)(c ^ (row & 7))) << 4);
                ldsm4(fa_hi[mt], aAhi + off);
                ldsm4(fa_lo[mt], aAlo + off);
            }
            uint32_t fb_hi[2][4], fb_lo[2][4];
            #pragma unroll
            for (int p = 0; p < 2; p++) {
                int nrow = wn*32 + p*16 + lr + (grp >> 1) * 8;
                int c = 2*ks + (grp & 1);
                uint32_t off = nrow * 128 + (((uint32_t)(c ^ (nrow & 7))) << 4);
                ldsm4(fb_hi[p], aBhi + off);
                ldsm4(fb_lo[p], aBlo + off);
            }
            #pragma unroll
            for (int mt = 0; mt < 2; mt++) {
                #pragma unroll
                for (int nt = 0; nt < 4; nt++) {
                    const uint32_t* bh = &fb_hi[nt >> 1][(nt & 1) * 2];
                    const uint32_t* bl = &fb_lo[nt >> 1][(nt & 1) * 2];
                    mma16816(acc[mt][nt], fa_hi[mt], bh);
                    mma16816(acc[mt][nt], fa_lo[mt], bh);
                    mma16816(acc[mt][nt], fa_hi[mt], bl);
                }
            }
        }
        __syncthreads();
    }

    int mrow = (lane >> 2);
    int ncol = (lane & 3) * 2;
    #pragma unroll
    for (int mt = 0; mt < 2; mt++) {
        #pragma unroll
        for (int nt = 0; nt < 4; nt++) {
            int n = n0 + wn*32 + nt*8 + ncol;
            if (n >= VTT) continue;
            float2 bv = *reinterpret_cast<const float2*>(&bias[n]);
            int m1 = m0 + wm*32 + mt*16 + mrow;
            int m2 = m1 + 8;
            if (m1 < MTOT) {
                float2 v = make_float2(acc[mt][nt][0] + bv.x, acc[mt][nt][1] + bv.y);
                *reinterpret_cast<float2*>(&outp[(long)m1*VTT + n]) = v;
            }
            if (m2 < MTOT) {
                float2 v = make_float2(acc[mt][nt][2] + bv.x, acc[mt][nt][3] + bv.y);
                *reinterpret_cast<float2*>(&outp[(long)m2*VTT + n]) = v;
            }
        }
    }
}

// ================= encoder step kernel: 192 blocks, pipelined gh GEMM =================
// blocks: dir(2) x ntile(24) x kc(4), K=128 per chunk, 8 iters, dbuf smem.
__global__ void __launch_bounds__(256, 2)
k_enc_step(int step,
           const float* __restrict__ Whh_f, const float* __restrict__ Whh_b,
           const float* __restrict__ bhh_f, const float* __restrict__ bhh_b)
{
    __shared__ float sA[2][16][32];
    __shared__ float sW[2][16][64];
    int blk = blockIdx.x, tid = threadIdx.x;
    int par = step & 1;
    int dir = blk >= 96;
    int rem = dir ? blk - 96 : blk;
    int ntile = rem >> 2;
    int kc = rem & 3;
    int n0 = ntile * 64;
    int kbase = kc * 128;
    const float* W = dir ? Whh_b : Whh_f;
    const float* h = g_h[dir][par];
    int tm = tid & 15, tn = tid >> 4;
    int r = tid >> 2, kq = (tid & 3) * 4;
    float acc[2][4] = {};
    float4 ra = make_float4(0,0,0,0), rw;

    if (tid < 128) ra = *(const float4*)&h[r*UU + kbase + kq];
    rw = *(const float4*)&W[(long)(n0+r)*UU + kbase + kq];

    int s = 0;
    #pragma unroll
    for (int it = 0; it < 8; it++) {
        if (tid < 128) {
            sA[s][kq+0][r] = ra.x; sA[s][kq+1][r] = ra.y;
            sA[s][kq+2][r] = ra.z; sA[s][kq+3][r] = ra.w;
        }
        sW[s][kq+0][r] = rw.x; sW[s][kq+1][r] = rw.y;
        sW[s][kq+2][r] = rw.z; sW[s][kq+3][r] = rw.w;
        __syncthreads();
        if (it < 7) {
            int k0 = kbase + (it + 1) * 16;
            if (tid < 128) ra = *(const float4*)&h[r*UU + k0 + kq];
            rw = *(const float4*)&W[(long)(n0+r)*UU + k0 + kq];
        }
        #pragma unroll
        for (int kk = 0; kk < 16; kk++) {
            float2 a2 = *reinterpret_cast<const float2*>(&sA[s][kk][tm*2]);
            float4 b4 = *reinterpret_cast<const float4*>(&sW[s][kk][tn*4]);
            acc[0][0] = fmaf(a2.x, b4.x, acc[0][0]);
            acc[0][1] = fmaf(a2.x, b4.y, acc[0][1]);
            acc[0][2] = fmaf(a2.x, b4.z, acc[0][2]);
            acc[0][3] = fmaf(a2.x, b4.w, acc[0][3]);
            acc[1][0] = fmaf(a2.y, b4.x, acc[1][0]);
            acc[1][1] = fmaf(a2.y, b4.y, acc[1][1]);
            acc[1][2] = fmaf(a2.y, b4.z, acc[1][2]);
            acc[1][3] = fmaf(a2.y, b4.w, acc[1][3]);
        }
        s ^= 1;
    }
    float* outp = &g_ghp[dir][kc][0];
    #pragma unroll
    for (int i = 0; i < 2; i++) {
        int b = tm*2 + i;
        #pragma unroll
        for (int j = 0; j < 4; j++)
            outp[b*GG + n0 + tn*4 + j] = acc[i][j];
    }

    gbar(&g_ctr[step], PBLK);

    int tf = step, tb = SS-1-step;
    for (int idx = blk*256 + tid; idx < 2*BB*UU; idx += PBLK*256) {
        int u = idx & 511;
        int b = (idx >> 9) & 31;
        int d2 = idx >> 14;
        const float* gi = d2 ? (g_gi_b + (long)tb*BB*GG) : (g_gi_f + (long)tf*BB*GG);
        const float* bhh = d2 ? bhh_b : bhh_f;
        float ghr = bhh[u], ghz = bhh[u+UU], ghn = bhh[u+2*UU];
        #pragma unroll
        for (int kc2 = 0; kc2 < 4; kc2++) {
            const float* p = &g_ghp[d2][kc2][b*GG];
            ghr += __ldcg(&p[u]); ghz += __ldcg(&p[u+UU]); ghn += __ldcg(&p[u+2*UU]);
        }
        float ir = gi[b*GG + u], iz = gi[b*GG + u + UU], inn = gi[b*GG + u + 2*UU];
        float r2 = sigm(ir + ghr);
        float z = sigm(iz + ghz);
        float n = tanhf(inn + r2*ghn);
        float hp = g_h[d2][par][b*UU + u];
        float hn_ = (1.0f - z)*n + z*hp;
        g_h[d2][par^1][b*UU + u] = hn_;
        float* outs = d2 ? (g_outs_b + (long)tb*BB*UU) : (g_outs_f + (long)tf*BB*UU);
        outs[b*UU + u] = hn_;
    }
}

// ================= decoder step kernel: 192 blocks =================
// Phase1: attn (blk 0-31) || gh (blk 32-127: 24 ntiles x 4 kc, K=128, pipelined).
// Phase2: gi (192 blocks: 24 ntiles x 8 kc, K~166). Phase3: gate+feat.
__global__ void __launch_bounds__(256, 2)
k_dec_step(int t,
           const float* __restrict__ attn_W,
           const float* __restrict__ Wih, const float* __restrict__ Whh,
           const float* __restrict__ bih, const float* __restrict__ bhh)
{
    __shared__ float sA[2][16][32];
    __shared__ float sW[2][16][64];
    __shared__ float s_st[UU];
    __shared__ float s_sc[SS];
    __shared__ float s_red[2];

    int blk = blockIdx.x, tid = threadIdx.x;
    int tm = tid & 15, tn = tid >> 4;
    int spar = t & 1;
    const float* st_g = g_state[spar];

    if (blk < 32) {
        int b = blk;
        float* s_tp = &sW[0][0][0];     // reuse 512 floats of sW as st_proj
        const float* st = &st_g[b*UU];
        for (int i = tid; i < UU; i += 256) s_st[i] = st[i];
        __syncthreads();
        for (int a = tid; a < AD; a += 256) {
            const float* w = attn_W + (long)a*GG;
            float acc = 0.0f;
            #pragma unroll 4
            for (int k = 0; k < UU; k += 4) {
                float4 wv = *reinterpret_cast<const float4*>(w + k);
                acc = fmaf(s_st[k],   wv.x, acc);
                acc = fmaf(s_st[k+1], wv.y, acc);
                acc = fmaf(s_st[k+2], wv.z, acc);
                acc = fmaf(s_st[k+3], wv.w, acc);
            }
            s_tp[a] = acc;
        }
        __syncthreads();
        {
            int s = tid >> 2, q = tid & 3;
            const float* ep = g_encproj + ((long)b*SS + s)*AD + q*128;
            const float* tp = s_tp + q*128;
            float partial = 0.0f;
            for (int a = 0; a < 128; a++) partial += tanhf(tp[a] + ep[a]);
            partial += __shfl_down_sync(0xffffffffu, partial, 2);
            partial += __shfl_down_sync(0xffffffffu, partial, 1);
            if (q == 0) s_sc[s] = partial;
        }
        __syncthreads();
        if (tid == 0) {
            float mx = s_sc[0];
            for (int s = 1; s < SS; s++) mx = fmaxf(mx, s_sc[s]);
            s_red[0] = mx;
        }
        __syncthreads();
        if (tid < SS) s_sc[tid] = expf(s_sc[tid] - s_red[0]);
        __syncthreads();
        if (tid == 0) {
            float sm = 0.0f;
            for (int s = 0; s < SS; s++) sm += s_sc[s];
            s_red[1] = 1.0f / sm;
        }
        __syncthreads();
        float inv = s_red[1];
        for (int h = tid; h < H2; h += 256) {
            const float* e = g_enc + (long)b*SS*H2 + h;
            float acc = 0.0f;
            #pragma unroll 8
            for (int s = 0; s < SS; s++) acc = fmaf(s_sc[s], e[(long)s*H2], acc);
            g_ctx[b*H2 + h] = acc * inv;
        }
    } else if (blk < 128) {
        int idx2 = blk - 32;
        int ntile = idx2 >> 2;
        int kc = idx2 & 3;
        int n0 = ntile * 64;
        int kbase = kc * 128;
        int r = tid >> 2, kq = (tid & 3) * 4;
        float acc[2][4] = {};
        float4 ra = make_float4(0,0,0,0), rw;
        if (tid < 128) ra = *(const float4*)&st_g[r*UU + kbase + kq];
        rw = *(const float4*)&Whh[(long)(n0+r)*UU + kbase + kq];
        int s = 0;
        #pragma unroll
        for (int it = 0; it < 8; it++) {
            if (tid < 128) {
                sA[s][kq+0][r] = ra.x; sA[s][kq+1][r] = ra.y;
                sA[s][kq+2][r] = ra.z; sA[s][kq+3][r] = ra.w;
            }
            sW[s][kq+0][r] = rw.x; sW[s][kq+1][r] = rw.y;
            sW[s][kq+2][r] = rw.z; sW[s][kq+3][r] = rw.w;
            __syncthreads();
            if (it < 7) {
                int k0 = kbase + (it + 1) * 16;
                if (tid < 128) ra = *(const float4*)&st_g[r*UU + k0 + kq];
                rw = *(const float4*)&Whh[(long)(n0+r)*UU + k0 + kq];
            }
            #pragma unroll
            for (int kk = 0; kk < 16; kk++) {
                float2 a2 = *reinterpret_cast<const float2*>(&sA[s][kk][tm*2]);
                float4 b4 = *reinterpret_cast<const float4*>(&sW[s][kk][tn*4]);
                acc[0][0] = fmaf(a2.x, b4.x, acc[0][0]);
                acc[0][1] = fmaf(a2.x, b4.y, acc[0][1]);
                acc[0][2] = fmaf(a2.x, b4.z, acc[0][2]);
                acc[0][3] = fmaf(a2.x, b4.w, acc[0][3]);
                acc[1][0] = fmaf(a2.y, b4.x, acc[1][0]);
                acc[1][1] = fmaf(a2.y, b4.y, acc[1][1]);
                acc[1][2] = fmaf(a2.y, b4.z, acc[1][2]);
                acc[1][3] = fmaf(a2.y, b4.w, acc[1][3]);
            }
            s ^= 1;
        }
        float* outp = &g_dgh[kc][0];
        #pragma unroll
        for (int i = 0; i < 2; i++) {
            int b = tm*2 + i;
            #pragma unroll
            for (int j = 0; j < 4; j++)
                outp[b*GG + n0 + tn*4 + j] = acc[i][j];
        }
    }
    gbar(&g_ctr[SS + 2*t], PBLK);

    // ---------- Phase 2: gi GEMM, 192 blocks (24 ntiles x 8 kc, K=166) ----------
    {
        int ntile = blk >> 3;
        int kc = blk & 7;
        int n0 = ntile * 64;
        int kbeg = kc * 166;
        int kend = min(KX, kbeg + 166);
        const float* em = g_embt + (long)t*BB*EE;
        int r = tid >> 2, kq = (tid & 3) * 4;
        float acc[2][4] = {};
        int s = 0;
        for (int k0 = kbeg; k0 < kend; k0 += 16) {
            if (tid < 128) {
                #pragma unroll
                for (int j = 0; j < 4; j++) {
                    int k = k0 + kq + j;
                    float v = 0.0f;
                    if (k < kend)
                        v = (k < EE) ? em[r*EE + k] : __ldcg(&g_ctx[r*H2 + k - EE]);
                    sA[s][kq+j][r] = v;
                }
            }
            {
                #pragma unroll
                for (int j = 0; j < 4; j++) {
                    int k = k0 + kq + j;
                    sW[s][kq+j][r] = (k < kend) ? Wih[(long)(n0+r)*KX + k] : 0.0f;
                }
            }
            __syncthreads();
            #pragma unroll
            for (int kk = 0; kk < 16; kk++) {
                float2 a2 = *reinterpret_cast<const float2*>(&sA[s][kk][tm*2]);
                float4 b4 = *reinterpret_cast<const float4*>(&sW[s][kk][tn*4]);
                acc[0][0] = fmaf(a2.x, b4.x, acc[0][0]);
                acc[0][1] = fmaf(a2.x, b4.y, acc[0][1]);
                acc[0][2] = fmaf(a2.x, b4.z, acc[0][2]);
                acc[0][3] = fmaf(a2.x, b4.w, acc[0][3]);
                acc[1][0] = fmaf(a2.y, b4.x, acc[1][0]);
                acc[1][1] = fmaf(a2.y, b4.y, acc[1][1]);
                acc[1][2] = fmaf(a2.y, b4.z, acc[1][2]);
                acc[1][3] = fmaf(a2.y, b4.w, acc[1][3]);
            }
            s ^= 1;   // alternate buffers -> only one sync per iter needed
        }
        float* outp = &g_dgi[kc][0];
        #pragma unroll
        for (int i = 0; i < 2; i++) {
            int b = tm*2 + i;
            #pragma unroll
            for (int j = 0; j < 4; j++)
                outp[b*GG + n0 + tn*4 + j] = acc[i][j];
        }
    }
    gbar(&g_ctr[SS + 2*t + 1], PBLK);

    // ---------- Phase 3: gate + feature assembly ----------
    for (int idx = blk*256 + tid; idx < BB*FF; idx += PBLK*256) {
        int f = idx % FF; int b = idx / FF;
        float* feat = g_feat + ((long)t*BB + b)*FF;
        if (f < UU) {
            int u = f;
            float gir = bih[u], giz = bih[u+UU], gin = bih[u+2*UU];
            float ghr = bhh[u], ghz = bhh[u+UU], ghn = bhh[u+2*UU];
            #pragma unroll
            for (int kc = 0; kc < 8; kc++) {
                const float* pi = &g_dgi[kc][b*GG];
                gir += __ldcg(&pi[u]); giz += __ldcg(&pi[u+UU]); gin += __ldcg(&pi[u+2*UU]);
            }
            #pragma unroll
            for (int kc = 0; kc < 4; kc++) {
                const float* ph = &g_dgh[kc][b*GG];
                ghr += __ldcg(&ph[u]); ghz += __ldcg(&ph[u+UU]); ghn += __ldcg(&ph[u+2*UU]);
            }
            float r = sigm(gir + ghr);
            float z = sigm(giz + ghz);
            float n = tanhf(gin + r*ghn);
            float hp = st_g[b*UU + u];
            float h2 = (1.0f - z)*n + z*hp;
            g_state[spar^1][b*UU + u] = h2;
            feat[u] = h2;
        } else if (f < UU + H2) {
            feat[f] = __ldcg(&g_ctx[b*H2 + f - UU]);
        } else {
            feat[f] = g_embt[((long)t*BB + b)*EE + f - UU - H2];
        }
    }
}

// ---------------- host launch ----------------
static float* symaddr(const void* sym) {
    void* p = nullptr;
    cudaGetSymbolAddress(&p, sym);
    return (float*)p;
}

extern "C" void kernel_launch(void* const* d_in, const int* in_sizes, int n_in,
                              void* d_out, int out_size)
{
    const float* emb_src   = (const float*)d_in[0];
    const float* emb_trg   = (const float*)d_in[1];
    const float* enc_Wih_f = (const float*)d_in[2];
    const float* enc_Whh_f = (const float*)d_in[3];
    const float* enc_bih_f = (const float*)d_in[4];
    const float* enc_bhh_f = (const float*)d_in[5];
    const float* enc_Wih_b = (const float*)d_in[6];
    const float* enc_Whh_b = (const float*)d_in[7];
    const float* enc_bih_b = (const float*)d_in[8];
    const float* enc_bhh_b = (const float*)d_in[9];
    const float* enc_Wfc   = (const float*)d_in[10];
    const float* enc_bfc   = (const float*)d_in[11];
    const float* attn_W    = (const float*)d_in[12];
    const float* attn_b    = (const float*)d_in[13];
    const float* dec_Wih   = (const float*)d_in[14];
    const float* dec_Whh   = (const float*)d_in[15];
    const float* dec_bih   = (const float*)d_in[16];
    const float* dec_bhh   = (const float*)d_in[17];
    const float* dec_Wfc   = (const float*)d_in[18];
    const float* dec_bfc   = (const float*)d_in[19];
    const int*   source    = (const int*)d_in[20];
    const int*   target    = (const int*)d_in[21];
    float* out = (float*)d_out;

    float* p_emb_s   = symaddr(g_emb_s);
    float* p_gi_f    = symaddr(g_gi_f);
    float* p_gi_b    = symaddr(g_gi_b);
    float* p_h       = symaddr(g_h);
    float* p_enc     = symaddr(g_enc);
    float* p_hfb     = symaddr(g_hfb);
    float* p_state   = symaddr(g_state);
    float* p_encproj = symaddr(g_encproj);
    float* p_ctr     = symaddr(g_ctr);

    static int attr_set = 0;
    if (!attr_set) {
        cudaFuncSetAttribute(k_logits_mma, cudaFuncAttributeMaxDynamicSharedMemorySize, LOG_SMEM);
        attr_set = 1;
    }

    // launches 1-5 (so k_enc_step is the 6th, for ncu -s 5 -c 1)
    k_zero<<<1, 128>>>((float*)p_ctr, SS + 2*TM1);
    k_zero<<<(2*2*BB*UU + 255)/256, 256>>>(p_h, 2*2*BB*UU);
    k_gather_src<<<(SS*BB*EE + 255)/256, 256>>>(emb_src, source);
    {
        dim3 grid(GG/128, (SS*BB)/128);
        k_gemm<<<grid, 256>>>(p_emb_s, EE, enc_Wih_f, EE, 0, enc_bih_f,
                              p_gi_f, GG, SS*BB, GG, EE, 0);
        k_gemm<<<grid, 256>>>(p_emb_s, EE, enc_Wih_b, EE, 0, enc_bih_b,
                              p_gi_b, GG, SS*BB, GG, EE, 0);
    }

    // encoder recurrence: one fused kernel per step (launch #6 is step 0)
    for (int i = 0; i < SS; i++) {
        k_enc_step<<<PBLK, 256>>>(i, enc_Whh_f, enc_Whh_b, enc_bhh_f, enc_bhh_b);
    }

    k_concat_enc<<<(BB*SS*H2 + 255)/256, 256>>>();
    k_concat_hfb<<<(BB*H2 + 255)/256, 256>>>();

    {
        dim3 grid((UU + 127)/128, 1);
        k_gemm<<<grid, 256>>>(p_hfb, H2, enc_Wfc, H2, 0, enc_bfc,
                              p_state, UU, BB, UU, H2, 1);
    }
    {
        dim3 grid(AD/128, (BB*SS)/128);
        k_gemm<<<grid, 256>>>(p_enc, H2, attn_W, GG, UU, attn_b,
                              p_encproj, AD, BB*SS, AD, H2, 0);
    }

    k_gather_trg<<<(TM1*BB*EE + 255)/256, 256>>>(emb_trg, target);

    for (int t = 0; t < TM1; t++) {
        k_dec_step<<<PBLK, 256>>>(t, attn_W, dec_Wih, dec_Whh, dec_bih, dec_bhh);
    }

    // split dec_Wfc (moved here; only needed before logits)
    {
        long total = (long)NP * (KP/4);
        k_split_w4<<<(unsigned)((total + 255)/256), 256>>>(dec_Wfc);
    }
    {
        long na = (long)MP*KP;
        k_split_a<<<(unsigned)((na + 255)/256), 256>>>();
    }

    k_zero<<<(BB*VTT + 255)/256, 256>>>(out, BB*VTT);

    {
        dim3 grid(MP/64, NP/128);
        k_logits_mma<<<grid, 256, LOG_SMEM>>>(dec_bfc, out + (long)BB*VTT);
    }
}

// round 15
// speedup vs baseline: 1.3048x; 1.0323x over previous
#include <cuda_runtime.h>
#include <cuda_bf16.h>
#include <math.h>
#include <stdint.h>

#define SS 64      // source length
#define BB 32      // batch
#define UU 512     // hidden
#define GG 1536    // 3*U
#define EE 300     // embed dim
#define AD 512     // attention dim
#define VTT 30000  // target vocab
#define TT 32      // target length
#define TM1 31     // T-1 decode steps
#define FF 1836    // 3U + E
#define KX 1324    // 2U + E
#define H2 1024    // 2U
#define MTOT (TM1*BB)   // 992
#define PBLK 192   // step-kernel block count (2 CTAs/SM co-resident)

// logits GEMM padded dims
#define KP 1856
#define NP 30080
#define MP 1024
#define KITER 29

// ---------------- device scratch ----------------
__device__ float g_emb_s[SS*BB*EE];
__device__ float g_gi_f[SS*BB*GG];
__device__ float g_gi_b[SS*BB*GG];
__device__ float g_outs_f[SS*BB*UU];
__device__ float g_outs_b[SS*BB*UU];
__device__ float g_h[2][2][BB*UU];
__device__ float g_ghp[2][4][BB*GG];        // encoder gh split-K partials (4 chunks)
__device__ float g_enc[BB*SS*H2];
__device__ float g_hfb[BB*H2];
__device__ float g_state[2][BB*UU];
__device__ float g_encproj[BB*SS*AD];
__device__ float g_embt[TM1*BB*EE];
__device__ float g_ctx[BB*H2];
__device__ float g_dgi[8][BB*GG];           // decoder gi partials (8 chunks)
__device__ float g_dgh[4][BB*GG];           // decoder gh partials (4 chunks)
__device__ float g_feat[(long)TM1*BB*FF];
__device__ int   g_ctr[SS + 2*TM1];         // per-phase barrier counters

// split-bf16 operands for the logits GEMM
__device__ __nv_bfloat16 g_whi[(long)NP*KP];
__device__ __nv_bfloat16 g_wlo[(long)NP*KP];
__device__ __nv_bfloat16 g_ahi[(long)MP*KP];
__device__ __nv_bfloat16 g_alo[(long)MP*KP];

__device__ __forceinline__ float sigm(float x) { return 1.0f / (1.0f + expf(-x)); }

__device__ __forceinline__ void gbar(int* ctr, int target) {
    __syncthreads();
    if (threadIdx.x == 0) {
        __threadfence();
        atomicAdd(ctr, 1);
        volatile int* v = ctr;
        while (*v < target) { __nanosleep(64); }
    }
    __syncthreads();
}

// ---- packed f32x2 helpers ----
__device__ __forceinline__ unsigned long long pk2(float x, float y) {
    unsigned long long r;
    asm("mov.b64 %0, {%1, %2};" : "=l"(r) : "f"(x), "f"(y));
    return r;
}
__device__ __forceinline__ void fma2(unsigned long long& d, unsigned long long a, unsigned long long b) {
    asm("fma.rn.f32x2 %0, %1, %2, %0;" : "+l"(d) : "l"(a), "l"(b));
}
__device__ __forceinline__ float2 upk2(unsigned long long v) {
    float2 f;
    asm("mov.b64 {%0, %1}, %2;" : "=f"(f.x), "=f"(f.y) : "l"(v));
    return f;
}

// ---------------- tiny utility kernels ----------------
__global__ void k_zero(float* p, int n) {
    int i = blockIdx.x * blockDim.x + threadIdx.x;
    if (i < n) p[i] = 0.0f;
}

__global__ void k_gather_src(const float* __restrict__ emb, const int* __restrict__ src) {
    int idx = blockIdx.x * blockDim.x + threadIdx.x;
    if (idx >= SS*BB*EE) return;
    int e = idx % EE; int tb = idx / EE;
    g_emb_s[idx] = emb[(long)src[tb]*EE + e];
}

__global__ void k_gather_trg(const float* __restrict__ emb, const int* __restrict__ trg) {
    int idx = blockIdx.x * blockDim.x + threadIdx.x;
    if (idx >= TM1*BB*EE) return;
    int e = idx % EE; int tb = idx / EE;
    g_embt[idx] = emb[(long)trg[tb]*EE + e];
}

__global__ void k_concat_enc() {
    int idx = blockIdx.x * blockDim.x + threadIdx.x;
    if (idx >= BB*SS*H2) return;
    int h = idx % H2; int bs = idx / H2;
    int s = bs % SS, b = bs / SS;
    float v = (h < UU) ? g_outs_f[((long)s*BB + b)*UU + h]
                       : g_outs_b[((long)s*BB + b)*UU + h - UU];
    g_enc[idx] = v;
}

__global__ void k_concat_hfb() {
    int idx = blockIdx.x * blockDim.x + threadIdx.x;
    if (idx >= BB*H2) return;
    int h = idx % H2; int b = idx / H2;
    float v = (h < UU) ? g_outs_f[((long)(SS-1)*BB + b)*UU + h]
                       : g_outs_b[(long)b*UU + h - UU];
    g_hfb[idx] = v;
}

// ---------------- split kernels ----------------
__global__ void k_split_w4(const float* __restrict__ W) {
    long idx = (long)blockIdx.x * blockDim.x + threadIdx.x;
    long total = (long)NP * (KP/4);
    if (idx >= total) return;
    int kq = (int)(idx % (KP/4)) * 4;
    int n  = (int)(idx / (KP/4));
    float4 x = make_float4(0.f, 0.f, 0.f, 0.f);
    if (n < VTT) {
        if (kq + 4 <= FF) {
            x = *reinterpret_cast<const float4*>(&W[(long)n*FF + kq]);
        } else if (kq < FF) {
            const float* src = &W[(long)n*FF + kq];
            float t[4] = {0,0,0,0};
            for (int j = 0; j < 4; j++) if (kq + j < FF) t[j] = src[j];
            x = make_float4(t[0], t[1], t[2], t[3]);
        }
    }
    __nv_bfloat16 h0 = __float2bfloat16(x.x), h1 = __float2bfloat16(x.y);
    __nv_bfloat16 h2 = __float2bfloat16(x.z), h3 = __float2bfloat16(x.w);
    __nv_bfloat16 l0 = __float2bfloat16(x.x - __bfloat162float(h0));
    __nv_bfloat16 l1 = __float2bfloat16(x.y - __bfloat162float(h1));
    __nv_bfloat16 l2 = __float2bfloat16(x.z - __bfloat162float(h2));
    __nv_bfloat16 l3 = __float2bfloat16(x.w - __bfloat162float(h3));
    long o = (long)n*KP + kq;
    __nv_bfloat162 hA; hA.x = h0; hA.y = h1;
    __nv_bfloat162 hB; hB.x = h2; hB.y = h3;
    __nv_bfloat162 lA; lA.x = l0; lA.y = l1;
    __nv_bfloat162 lB; lB.x = l2; lB.y = l3;
    *reinterpret_cast<__nv_bfloat162*>(&g_whi[o])   = hA;
    *reinterpret_cast<__nv_bfloat162*>(&g_whi[o+2]) = hB;
    *reinterpret_cast<__nv_bfloat162*>(&g_wlo[o])   = lA;
    *reinterpret_cast<__nv_bfloat162*>(&g_wlo[o+2]) = lB;
}

__global__ void k_split_a() {
    long idx = (long)blockIdx.x * blockDim.x + threadIdx.x;
    if (idx >= (long)MP*KP) return;
    int k = (int)(idx % KP); int m = (int)(idx / KP);
    float x = (m < MTOT && k < FF) ? g_feat[(long)m*FF + k] : 0.0f;
    __nv_bfloat16 h = __float2bfloat16(x);
    g_ahi[idx] = h;
    g_alo[idx] = __float2bfloat16(x - __bfloat162float(h));
}

// ---------------- fp32x2 tiled GEMM ----------------
__global__ void __launch_bounds__(256, 2)
k_gemm(const float* __restrict__ Ap, int lda,
       const float* __restrict__ Wp, int ldw, int woff,
       const float* __restrict__ bias,
       float* __restrict__ Cp, int ldc,
       int M, int N, int K, int act)
{
    __shared__ float sA[16][128];
    __shared__ float sW[16][128];
    int tid = threadIdx.x;
    int m0 = blockIdx.y * 128, n0 = blockIdx.x * 128;
    int tr = tid & 15, tc = tid >> 4;

    unsigned long long acc[8][4];
    #pragma unroll
    for (int i = 0; i < 8; i++)
        #pragma unroll
        for (int j = 0; j < 4; j++) acc[i][j] = 0ull;

    int r  = tid >> 2;
    int kq = (tid & 3) * 4;

    for (int k0 = 0; k0 < K; k0 += 16) {
        bool kok = (k0 + kq) < K;
        #pragma unroll
        for (int h = 0; h < 2; h++) {
            int row = r + h * 64;
            float4 va = make_float4(0.f, 0.f, 0.f, 0.f);
            int m = m0 + row;
            if (kok && m < M) va = *reinterpret_cast<const float4*>(&Ap[(long)m*lda + k0 + kq]);
            sA[kq+0][row] = va.x; sA[kq+1][row] = va.y;
            sA[kq+2][row] = va.z; sA[kq+3][row] = va.w;

            float4 vw = make_float4(0.f, 0.f, 0.f, 0.f);
            int n = n0 + row;
            if (kok && n < N) vw = *reinterpret_cast<const float4*>(&Wp[(long)n*ldw + woff + k0 + kq]);
            sW[kq+0][row] = vw.x; sW[kq+1][row] = vw.y;
            sW[kq+2][row] = vw.z; sW[kq+3][row] = vw.w;
        }
        __syncthreads();

        #pragma unroll
        for (int kk = 0; kk < 16; kk++) {
            float4 a0 = *reinterpret_cast<const float4*>(&sA[kk][tr*8]);
            float4 a1 = *reinterpret_cast<const float4*>(&sA[kk][tr*8 + 4]);
            unsigned long long bp[4];
            #pragma unroll
            for (int j = 0; j < 4; j++)
                bp[j] = *reinterpret_cast<const unsigned long long*>(&sW[kk][tc*8 + 2*j]);
            float av[8] = {a0.x, a0.y, a0.z, a0.w, a1.x, a1.y, a1.z, a1.w};
            #pragma unroll
            for (int i = 0; i < 8; i++) {
                unsigned long long ap = pk2(av[i], av[i]);
                #pragma unroll
                for (int j = 0; j < 4; j++) fma2(acc[i][j], ap, bp[j]);
            }
        }
        __syncthreads();
    }

    #pragma unroll
    for (int i = 0; i < 8; i++) {
        int m = m0 + tr*8 + i;
        if (m >= M) continue;
        #pragma unroll
        for (int j = 0; j < 4; j++) {
            float2 v = upk2(acc[i][j]);
            int n = n0 + tc*8 + 2*j;
            if (n < N) {
                float c = v.x + (bias ? bias[n] : 0.0f);
                if (act) c = tanhf(c);
                Cp[(long)m*ldc + n] = c;
            }
            if (n + 1 < N) {
                float c = v.y + (bias ? bias[n+1] : 0.0f);
                if (act) c = tanhf(c);
                Cp[(long)m*ldc + n + 1] = c;
            }
        }
    }
}

// ================= mma.sync bf16 logits GEMM (64x128 tile, 2 CTAs/SM) =================
__device__ __forceinline__ uint32_t smem_u32(const void* p) {
    uint32_t a;
    asm("{ .reg .u64 t; cvta.to.shared.u64 t, %1; cvt.u32.u64 %0, t; }" : "=r"(a) : "l"(p));
    return a;
}
__device__ __forceinline__ void cpa16(uint32_t dst, const void* src) {
    asm volatile("cp.async.cg.shared.global [%0], [%1], 16;" :: "r"(dst), "l"(src) : "memory");
}
__device__ __forceinline__ void cpa_commit() {
    asm volatile("cp.async.commit_group;" ::: "memory");
}
__device__ __forceinline__ void ldsm4(uint32_t* r, uint32_t addr) {
    asm volatile("ldmatrix.sync.aligned.m8n8.x4.shared.b16 {%0,%1,%2,%3}, [%4];"
        : "=r"(r[0]), "=r"(r[1]), "=r"(r[2]), "=r"(r[3]) : "r"(addr));
}
__device__ __forceinline__ void mma16816(float* d, const uint32_t* a, const uint32_t* b) {
    asm volatile("mma.sync.aligned.m16n8k16.row.col.f32.bf16.bf16.f32 "
        "{%0,%1,%2,%3}, {%4,%5,%6,%7}, {%8,%9}, {%0,%1,%2,%3};"
        : "+f"(d[0]), "+f"(d[1]), "+f"(d[2]), "+f"(d[3])
        : "r"(a[0]), "r"(a[1]), "r"(a[2]), "r"(a[3]), "r"(b[0]), "r"(b[1]));
}

#define LSTG 49152
#define LOG_SMEM (2*LSTG)

__global__ void __launch_bounds__(256, 2)
k_logits_mma(const float* __restrict__ bias, float* __restrict__ outp)
{
    extern __shared__ __align__(128) char smem[];
    uint32_t sb = smem_u32(smem);
    int tid = threadIdx.x;
    int wid = tid >> 5, lane = tid & 31;
    int wm = wid >> 2, wn = wid & 3;
    int grp = lane >> 3, lr = lane & 7;
    int m0 = blockIdx.x * 64;
    int n0 = blockIdx.y * 128;

    float acc[2][4][4];
    #pragma unroll
    for (int i = 0; i < 2; i++)
        #pragma unroll
        for (int j = 0; j < 4; j++)
            #pragma unroll
            for (int c = 0; c < 4; c++) acc[i][j][c] = 0.0f;

    auto load_stage = [&](int it, int s) {
        int k0 = it * 64;
        uint32_t base = sb + s * LSTG;
        #pragma unroll
        for (int q = 0; q < 2; q++) {
            int u = tid + q * 256;
            int row = u >> 3, c = u & 7;
            uint32_t off = row * 128 + (((uint32_t)(c ^ (row & 7))) << 4);
            long ga = (long)(m0 + row) * KP + k0 + c * 8;
            cpa16(base + off,         g_ahi + ga);
            cpa16(base + 8192 + off,  g_alo + ga);
        }
        #pragma unroll
        for (int q = 0; q < 4; q++) {
            int u = tid + q * 256;
            int row = u >> 3, c = u & 7;
            uint32_t off = row * 128 + (((uint32_t)(c ^ (row & 7))) << 4);
            long gb = (long)(n0 + row) * KP + k0 + c * 8;
            cpa16(base + 16384 + off, g_whi + gb);
            cpa16(base + 32768 + off, g_wlo + gb);
        }
    };

    load_stage(0, 0);
    cpa_commit();

    for (int it = 0; it < KITER; it++) {
        int s = it & 1;
        if (it < KITER - 1) {
            load_stage(it + 1, s ^ 1);
            cpa_commit();
            asm volatile("cp.async.wait_group 1;" ::: "memory");
        } else {
            asm volatile("cp.async.wait_group 0;" ::: "memory");
        }
        __syncthreads();

        uint32_t aAhi = sb + s*LSTG;
        uint32_t aAlo = aAhi + 8192;
        uint32_t aBhi = aAhi + 16384;
        uint32_t aBlo = aAhi + 32768;

        #pragma unroll
        for (int ks = 0; ks < 4; ks++) {
            uint32_t fa_hi[2][4], fa_lo[2][4];
            #pragma unroll
            for (int mt = 0; mt < 2; mt++) {
                int row = wm*32 + mt*16 + lr + (grp & 1) * 8;
                int c = 2*ks + (grp >> 1);
                uint32_t off = row * 128 + (((uint32_t)(c ^ (row & 7))) << 4);
                ldsm4(fa_hi[mt], aAhi + off);
                ldsm4(fa_lo[mt], aAlo + off);
            }
            uint32_t fb_hi[2][4], fb_lo[2][4];
            #pragma unroll
            for (int p = 0; p < 2; p++) {
                int nrow = wn*32 + p*16 + lr + (grp >> 1) * 8;
                int c = 2*ks + (grp & 1);
                uint32_t off = nrow * 128 + (((uint32_t)(c ^ (nrow & 7))) << 4);
                ldsm4(fb_hi[p], aBhi + off);
                ldsm4(fb_lo[p], aBlo + off);
            }
            #pragma unroll
            for (int mt = 0; mt < 2; mt++) {
                #pragma unroll
                for (int nt = 0; nt < 4; nt++) {
                    const uint32_t* bh = &fb_hi[nt >> 1][(nt & 1) * 2];
                    const uint32_t* bl = &fb_lo[nt >> 1][(nt & 1) * 2];
                    mma16816(acc[mt][nt], fa_hi[mt], bh);
                    mma16816(acc[mt][nt], fa_lo[mt], bh);
                    mma16816(acc[mt][nt], fa_hi[mt], bl);
                }
            }
        }
        __syncthreads();
    }

    int mrow = (lane >> 2);
    int ncol = (lane & 3) * 2;
    #pragma unroll
    for (int mt = 0; mt < 2; mt++) {
        #pragma unroll
        for (int nt = 0; nt < 4; nt++) {
            int n = n0 + wn*32 + nt*8 + ncol;
            if (n >= VTT) continue;
            float2 bv = *reinterpret_cast<const float2*>(&bias[n]);
            int m1 = m0 + wm*32 + mt*16 + mrow;
            int m2 = m1 + 8;
            if (m1 < MTOT) {
                float2 v = make_float2(acc[mt][nt][0] + bv.x, acc[mt][nt][1] + bv.y);
                *reinterpret_cast<float2*>(&outp[(long)m1*VTT + n]) = v;
            }
            if (m2 < MTOT) {
                float2 v = make_float2(acc[mt][nt][2] + bv.x, acc[mt][nt][3] + bv.y);
                *reinterpret_cast<float2*>(&outp[(long)m2*VTT + n]) = v;
            }
        }
    }
}

// ================= encoder step kernel: 192 blocks, pipelined gh GEMM =================
__global__ void __launch_bounds__(256, 2)
k_enc_step(int step,
           const float* __restrict__ Whh_f, const float* __restrict__ Whh_b,
           const float* __restrict__ bhh_f, const float* __restrict__ bhh_b)
{
    __shared__ float sA[2][16][32];
    __shared__ float sW[2][16][64];
    int blk = blockIdx.x, tid = threadIdx.x;
    int par = step & 1;
    int dir = blk >= 96;
    int rem = dir ? blk - 96 : blk;
    int ntile = rem >> 2;
    int kc = rem & 3;
    int n0 = ntile * 64;
    int kbase = kc * 128;
    const float* W = dir ? Whh_b : Whh_f;
    const float* h = g_h[dir][par];
    int tm = tid & 15, tn = tid >> 4;
    int r = tid >> 2, kq = (tid & 3) * 4;
    float acc[2][4] = {};
    float4 ra = make_float4(0,0,0,0), rw;

    if (tid < 128) ra = *(const float4*)&h[r*UU + kbase + kq];
    rw = *(const float4*)&W[(long)(n0+r)*UU + kbase + kq];

    int s = 0;
    #pragma unroll
    for (int it = 0; it < 8; it++) {
        if (tid < 128) {
            sA[s][kq+0][r] = ra.x; sA[s][kq+1][r] = ra.y;
            sA[s][kq+2][r] = ra.z; sA[s][kq+3][r] = ra.w;
        }
        sW[s][kq+0][r] = rw.x; sW[s][kq+1][r] = rw.y;
        sW[s][kq+2][r] = rw.z; sW[s][kq+3][r] = rw.w;
        __syncthreads();
        if (it < 7) {
            int k0 = kbase + (it + 1) * 16;
            if (tid < 128) ra = *(const float4*)&h[r*UU + k0 + kq];
            rw = *(const float4*)&W[(long)(n0+r)*UU + k0 + kq];
        }
        #pragma unroll
        for (int kk = 0; kk < 16; kk++) {
            float2 a2 = *reinterpret_cast<const float2*>(&sA[s][kk][tm*2]);
            float4 b4 = *reinterpret_cast<const float4*>(&sW[s][kk][tn*4]);
            acc[0][0] = fmaf(a2.x, b4.x, acc[0][0]);
            acc[0][1] = fmaf(a2.x, b4.y, acc[0][1]);
            acc[0][2] = fmaf(a2.x, b4.z, acc[0][2]);
            acc[0][3] = fmaf(a2.x, b4.w, acc[0][3]);
            acc[1][0] = fmaf(a2.y, b4.x, acc[1][0]);
            acc[1][1] = fmaf(a2.y, b4.y, acc[1][1]);
            acc[1][2] = fmaf(a2.y, b4.z, acc[1][2]);
            acc[1][3] = fmaf(a2.y, b4.w, acc[1][3]);
        }
        s ^= 1;
    }
    float* outp = &g_ghp[dir][kc][0];
    #pragma unroll
    for (int i = 0; i < 2; i++) {
        int b = tm*2 + i;
        #pragma unroll
        for (int j = 0; j < 4; j++)
            outp[b*GG + n0 + tn*4 + j] = acc[i][j];
    }

    gbar(&g_ctr[step], PBLK);

    int tf = step, tb = SS-1-step;
    for (int idx = blk*256 + tid; idx < 2*BB*UU; idx += PBLK*256) {
        int u = idx & 511;
        int b = (idx >> 9) & 31;
        int d2 = idx >> 14;
        const float* gi = d2 ? (g_gi_b + (long)tb*BB*GG) : (g_gi_f + (long)tf*BB*GG);
        const float* bhh = d2 ? bhh_b : bhh_f;
        float ghr = bhh[u], ghz = bhh[u+UU], ghn = bhh[u+2*UU];
        #pragma unroll
        for (int kc2 = 0; kc2 < 4; kc2++) {
            const float* p = &g_ghp[d2][kc2][b*GG];
            ghr += __ldcg(&p[u]); ghz += __ldcg(&p[u+UU]); ghn += __ldcg(&p[u+2*UU]);
        }
        float ir = gi[b*GG + u], iz = gi[b*GG + u + UU], inn = gi[b*GG + u + 2*UU];
        float r2 = sigm(ir + ghr);
        float z = sigm(iz + ghz);
        float n = tanhf(inn + r2*ghn);
        float hp = g_h[d2][par][b*UU + u];
        float hn_ = (1.0f - z)*n + z*hp;
        g_h[d2][par^1][b*UU + u] = hn_;
        float* outs = d2 ? (g_outs_b + (long)tb*BB*UU) : (g_outs_f + (long)tf*BB*UU);
        outs[b*UU + u] = hn_;
    }
}

// ================= decoder step kernel: 192 blocks =================
__global__ void __launch_bounds__(256, 2)
k_dec_step(int t,
           const float* __restrict__ attn_W,
           const float* __restrict__ Wih, const float* __restrict__ Whh,
           const float* __restrict__ bih, const float* __restrict__ bhh)
{
    __shared__ float sA[2][16][32];
    __shared__ float sW[2][16][64];
    __shared__ float s_st[UU];
    __shared__ float s_sc[SS];
    __shared__ float s_red[2];

    int blk = blockIdx.x, tid = threadIdx.x;
    int tm = tid & 15, tn = tid >> 4;
    int spar = t & 1;
    const float* st_g = g_state[spar];

    if (blk < 32) {
        int b = blk;
        float* s_tp = &sW[0][0][0];
        const float* st = &st_g[b*UU];
        for (int i = tid; i < UU; i += 256) s_st[i] = st[i];
        __syncthreads();
        for (int a = tid; a < AD; a += 256) {
            const float* w = attn_W + (long)a*GG;
            float acc = 0.0f;
            #pragma unroll 4
            for (int k = 0; k < UU; k += 4) {
                float4 wv = *reinterpret_cast<const float4*>(w + k);
                acc = fmaf(s_st[k],   wv.x, acc);
                acc = fmaf(s_st[k+1], wv.y, acc);
                acc = fmaf(s_st[k+2], wv.z, acc);
                acc = fmaf(s_st[k+3], wv.w, acc);
            }
            s_tp[a] = acc;
        }
        __syncthreads();
        {
            int s = tid >> 2, q = tid & 3;
            const float* ep = g_encproj + ((long)b*SS + s)*AD + q*128;
            const float* tp = s_tp + q*128;
            float partial = 0.0f;
            for (int a = 0; a < 128; a++) partial += tanhf(tp[a] + ep[a]);
            partial += __shfl_down_sync(0xffffffffu, partial, 2);
            partial += __shfl_down_sync(0xffffffffu, partial, 1);
            if (q == 0) s_sc[s] = partial;
        }
        __syncthreads();
        if (tid == 0) {
            float mx = s_sc[0];
            for (int s = 1; s < SS; s++) mx = fmaxf(mx, s_sc[s]);
            s_red[0] = mx;
        }
        __syncthreads();
        if (tid < SS) s_sc[tid] = expf(s_sc[tid] - s_red[0]);
        __syncthreads();
        if (tid == 0) {
            float sm = 0.0f;
            for (int s = 0; s < SS; s++) sm += s_sc[s];
            s_red[1] = 1.0f / sm;
        }
        __syncthreads();
        float inv = s_red[1];
        for (int h = tid; h < H2; h += 256) {
            const float* e = g_enc + (long)b*SS*H2 + h;
            float acc = 0.0f;
            #pragma unroll 8
            for (int s = 0; s < SS; s++) acc = fmaf(s_sc[s], e[(long)s*H2], acc);
            g_ctx[b*H2 + h] = acc * inv;
        }
    } else if (blk < 128) {
        int idx2 = blk - 32;
        int ntile = idx2 >> 2;
        int kc = idx2 & 3;
        int n0 = ntile * 64;
        int kbase = kc * 128;
        int r = tid >> 2, kq = (tid & 3) * 4;
        float acc[2][4] = {};
        float4 ra = make_float4(0,0,0,0), rw;
        if (tid < 128) ra = *(const float4*)&st_g[r*UU + kbase + kq];
        rw = *(const float4*)&Whh[(long)(n0+r)*UU + kbase + kq];
        int s = 0;
        #pragma unroll
        for (int it = 0; it < 8; it++) {
            if (tid < 128) {
                sA[s][kq+0][r] = ra.x; sA[s][kq+1][r] = ra.y;
                sA[s][kq+2][r] = ra.z; sA[s][kq+3][r] = ra.w;
            }
            sW[s][kq+0][r] = rw.x; sW[s][kq+1][r] = rw.y;
            sW[s][kq+2][r] = rw.z; sW[s][kq+3][r] = rw.w;
            __syncthreads();
            if (it < 7) {
                int k0 = kbase + (it + 1) * 16;
                if (tid < 128) ra = *(const float4*)&st_g[r*UU + k0 + kq];
                rw = *(const float4*)&Whh[(long)(n0+r)*UU + k0 + kq];
            }
            #pragma unroll
            for (int kk = 0; kk < 16; kk++) {
                float2 a2 = *reinterpret_cast<const float2*>(&sA[s][kk][tm*2]);
                float4 b4 = *reinterpret_cast<const float4*>(&sW[s][kk][tn*4]);
                acc[0][0] = fmaf(a2.x, b4.x, acc[0][0]);
                acc[0][1] = fmaf(a2.x, b4.y, acc[0][1]);
                acc[0][2] = fmaf(a2.x, b4.z, acc[0][2]);
                acc[0][3] = fmaf(a2.x, b4.w, acc[0][3]);
                acc[1][0] = fmaf(a2.y, b4.x, acc[1][0]);
                acc[1][1] = fmaf(a2.y, b4.y, acc[1][1]);
                acc[1][2] = fmaf(a2.y, b4.z, acc[1][2]);
                acc[1][3] = fmaf(a2.y, b4.w, acc[1][3]);
            }
            s ^= 1;
        }
        float* outp = &g_dgh[kc][0];
        #pragma unroll
        for (int i = 0; i < 2; i++) {
            int b = tm*2 + i;
            #pragma unroll
            for (int j = 0; j < 4; j++)
                outp[b*GG + n0 + tn*4 + j] = acc[i][j];
        }
    }
    gbar(&g_ctr[SS + 2*t], PBLK);

    // ---------- Phase 2: gi GEMM, 192 blocks (24 ntiles x 8 kc, K=166), reg-prefetch ----------
    {
        int ntile = blk >> 3;
        int kc = blk & 7;
        int n0 = ntile * 64;
        int kbeg = kc * 166;
        int kend = min(KX, kbeg + 166);
        const float* em = g_embt + (long)t*BB*EE;
        int r = tid >> 2, kq = (tid & 3) * 4;
        float acc[2][4] = {};
        float va[4] = {0,0,0,0}, vw[4] = {0,0,0,0};

        auto ldA = [&](int k0, float* v) {
            #pragma unroll
            for (int j = 0; j < 4; j++) {
                int k = k0 + kq + j;
                float x = 0.0f;
                if (k < kend)
                    x = (k < EE) ? em[r*EE + k] : __ldcg(&g_ctx[r*H2 + k - EE]);
                v[j] = x;
            }
        };
        auto ldW = [&](int k0, float* v) {
            #pragma unroll
            for (int j = 0; j < 4; j++) {
                int k = k0 + kq + j;
                v[j] = (k < kend) ? Wih[(long)(n0+r)*KX + k] : 0.0f;
            }
        };

        if (tid < 128) ldA(kbeg, va);
        ldW(kbeg, vw);

        int s = 0;
        for (int k0 = kbeg; k0 < kend; k0 += 16) {
            if (tid < 128) {
                sA[s][kq+0][r] = va[0]; sA[s][kq+1][r] = va[1];
                sA[s][kq+2][r] = va[2]; sA[s][kq+3][r] = va[3];
            }
            sW[s][kq+0][r] = vw[0]; sW[s][kq+1][r] = vw[1];
            sW[s][kq+2][r] = vw[2]; sW[s][kq+3][r] = vw[3];
            __syncthreads();
            if (k0 + 16 < kend) {
                if (tid < 128) ldA(k0 + 16, va);
                ldW(k0 + 16, vw);
            }
            #pragma unroll
            for (int kk = 0; kk < 16; kk++) {
                float2 a2 = *reinterpret_cast<const float2*>(&sA[s][kk][tm*2]);
                float4 b4 = *reinterpret_cast<const float4*>(&sW[s][kk][tn*4]);
                acc[0][0] = fmaf(a2.x, b4.x, acc[0][0]);
                acc[0][1] = fmaf(a2.x, b4.y, acc[0][1]);
                acc[0][2] = fmaf(a2.x, b4.z, acc[0][2]);
                acc[0][3] = fmaf(a2.x, b4.w, acc[0][3]);
                acc[1][0] = fmaf(a2.y, b4.x, acc[1][0]);
                acc[1][1] = fmaf(a2.y, b4.y, acc[1][1]);
                acc[1][2] = fmaf(a2.y, b4.z, acc[1][2]);
                acc[1][3] = fmaf(a2.y, b4.w, acc[1][3]);
            }
            s ^= 1;
        }
        float* outp = &g_dgi[kc][0];
        #pragma unroll
        for (int i = 0; i < 2; i++) {
            int b = tm*2 + i;
            #pragma unroll
            for (int j = 0; j < 4; j++)
                outp[b*GG + n0 + tn*4 + j] = acc[i][j];
        }
    }
    gbar(&g_ctr[SS + 2*t + 1], PBLK);

    for (int idx = blk*256 + tid; idx < BB*FF; idx += PBLK*256) {
        int f = idx % FF; int b = idx / FF;
        float* feat = g_feat + ((long)t*BB + b)*FF;
        if (f < UU) {
            int u = f;
            float gir = bih[u], giz = bih[u+UU], gin = bih[u+2*UU];
            float ghr = bhh[u], ghz = bhh[u+UU], ghn = bhh[u+2*UU];
            #pragma unroll
            for (int kc = 0; kc < 8; kc++) {
                const float* pi = &g_dgi[kc][b*GG];
                gir += __ldcg(&pi[u]); giz += __ldcg(&pi[u+UU]); gin += __ldcg(&pi[u+2*UU]);
            }
            #pragma unroll
            for (int kc = 0; kc < 4; kc++) {
                const float* ph = &g_dgh[kc][b*GG];
                ghr += __ldcg(&ph[u]); ghz += __ldcg(&ph[u+UU]); ghn += __ldcg(&ph[u+2*UU]);
            }
            float r = sigm(gir + ghr);
            float z = sigm(giz + ghz);
            float n = tanhf(gin + r*ghn);
            float hp = st_g[b*UU + u];
            float h2 = (1.0f - z)*n + z*hp;
            g_state[spar^1][b*UU + u] = h2;
            feat[u] = h2;
        } else if (f < UU + H2) {
            feat[f] = __ldcg(&g_ctx[b*H2 + f - UU]);
        } else {
            feat[f] = g_embt[((long)t*BB + b)*EE + f - UU - H2];
        }
    }
}

// ---------------- host: side stream for split_w overlap ----------------
static cudaStream_t g_s2 = nullptr;
static cudaEvent_t g_evf = nullptr, g_evd = nullptr;
namespace {
struct StreamInit {
    StreamInit() {
        cudaStreamCreateWithFlags(&g_s2, cudaStreamNonBlocking);
        cudaEventCreateWithFlags(&g_evf, cudaEventDisableTiming);
        cudaEventCreateWithFlags(&g_evd, cudaEventDisableTiming);
    }
};
StreamInit g_stream_init;
}

static float* symaddr(const void* sym) {
    void* p = nullptr;
    cudaGetSymbolAddress(&p, sym);
    return (float*)p;
}

extern "C" void kernel_launch(void* const* d_in, const int* in_sizes, int n_in,
                              void* d_out, int out_size)
{
    const float* emb_src   = (const float*)d_in[0];
    const float* emb_trg   = (const float*)d_in[1];
    const float* enc_Wih_f = (const float*)d_in[2];
    const float* enc_Whh_f = (const float*)d_in[3];
    const float* enc_bih_f = (const float*)d_in[4];
    const float* enc_bhh_f = (const float*)d_in[5];
    const float* enc_Wih_b = (const float*)d_in[6];
    const float* enc_Whh_b = (const float*)d_in[7];
    const float* enc_bih_b = (const float*)d_in[8];
    const float* enc_bhh_b = (const float*)d_in[9];
    const float* enc_Wfc   = (const float*)d_in[10];
    const float* enc_bfc   = (const float*)d_in[11];
    const float* attn_W    = (const float*)d_in[12];
    const float* attn_b    = (const float*)d_in[13];
    const float* dec_Wih   = (const float*)d_in[14];
    const float* dec_Whh   = (const float*)d_in[15];
    const float* dec_bih   = (const float*)d_in[16];
    const float* dec_bhh   = (const float*)d_in[17];
    const float* dec_Wfc   = (const float*)d_in[18];
    const float* dec_bfc   = (const float*)d_in[19];
    const int*   source    = (const int*)d_in[20];
    const int*   target    = (const int*)d_in[21];
    float* out = (float*)d_out;

    float* p_emb_s   = symaddr(g_emb_s);
    float* p_gi_f    = symaddr(g_gi_f);
    float* p_gi_b    = symaddr(g_gi_b);
    float* p_h       = symaddr(g_h);
    float* p_enc     = symaddr(g_enc);
    float* p_hfb     = symaddr(g_hfb);
    float* p_state   = symaddr(g_state);
    float* p_encproj = symaddr(g_encproj);
    float* p_ctr     = symaddr(g_ctr);

    static int attr_set = 0;
    if (!attr_set) {
        cudaFuncSetAttribute(k_logits_mma, cudaFuncAttributeMaxDynamicSharedMemorySize, LOG_SMEM);
        attr_set = 1;
    }

    // fork side stream: split_w overlaps the latency-bound step kernels
    cudaEventRecord(g_evf, 0);
    cudaStreamWaitEvent(g_s2, g_evf, 0);
    {
        long total = (long)NP * (KP/4);
        k_split_w4<<<(unsigned)((total + 255)/256), 256, 0, g_s2>>>(dec_Wfc);
    }
    cudaEventRecord(g_evd, g_s2);

    k_zero<<<1, 128>>>((float*)p_ctr, SS + 2*TM1);
    k_zero<<<(2*2*BB*UU + 255)/256, 256>>>(p_h, 2*2*BB*UU);
    k_gather_src<<<(SS*BB*EE + 255)/256, 256>>>(emb_src, source);
    {
        dim3 grid(GG/128, (SS*BB)/128);
        k_gemm<<<grid, 256>>>(p_emb_s, EE, enc_Wih_f, EE, 0, enc_bih_f,
                              p_gi_f, GG, SS*BB, GG, EE, 0);
        k_gemm<<<grid, 256>>>(p_emb_s, EE, enc_Wih_b, EE, 0, enc_bih_b,
                              p_gi_b, GG, SS*BB, GG, EE, 0);
    }

    // encoder recurrence
    for (int i = 0; i < SS; i++) {
        k_enc_step<<<PBLK, 256>>>(i, enc_Whh_f, enc_Whh_b, enc_bhh_f, enc_bhh_b);
    }

    k_concat_enc<<<(BB*SS*H2 + 255)/256, 256>>>();
    k_concat_hfb<<<(BB*H2 + 255)/256, 256>>>();

    {
        dim3 grid((UU + 127)/128, 1);
        k_gemm<<<grid, 256>>>(p_hfb, H2, enc_Wfc, H2, 0, enc_bfc,
                              p_state, UU, BB, UU, H2, 1);
    }
    {
        dim3 grid(AD/128, (BB*SS)/128);
        k_gemm<<<grid, 256>>>(p_enc, H2, attn_W, GG, UU, attn_b,
                              p_encproj, AD, BB*SS, AD, H2, 0);
    }

    k_gather_trg<<<(TM1*BB*EE + 255)/256, 256>>>(emb_trg, target);

    // decoder recurrence
    for (int t = 0; t < TM1; t++) {
        k_dec_step<<<PBLK, 256>>>(t, attn_W, dec_Wih, dec_Whh, dec_bih, dec_bhh);
    }

    {
        long na = (long)MP*KP;
        k_split_a<<<(unsigned)((na + 255)/256), 256>>>();
    }

    k_zero<<<(BB*VTT + 255)/256, 256>>>(out, BB*VTT);

    // join: logits needs g_whi/g_wlo from the side stream
    cudaStreamWaitEvent(0, g_evd, 0);

    {
        dim3 grid(MP/64, NP/128);
        k_logits_mma<<<grid, 256, LOG_SMEM>>>(dec_bfc, out + (long)BB*VTT);
    }
}

// round 16
// speedup vs baseline: 1.3637x; 1.0452x over previous
#include <cuda_runtime.h>
#include <cuda_bf16.h>
#include <math.h>
#include <stdint.h>

#define SS 64      // source length
#define BB 32      // batch
#define UU 512     // hidden
#define GG 1536    // 3*U
#define EE 300     // embed dim
#define AD 512     // attention dim
#define VTT 30000  // target vocab
#define TT 32      // target length
#define TM1 31     // T-1 decode steps
#define FF 1836    // 3U + E
#define KX 1324    // 2U + E
#define H2 1024    // 2U
#define MTOT (TM1*BB)   // 992
#define PBLK 192   // step-kernel block count (2 CTAs/SM co-resident)

// logits GEMM padded dims
#define KP 1856
#define NP 30080
#define MP 1024
#define KITER 29

// ---------------- device scratch ----------------
__device__ float g_emb_s[SS*BB*EE];
__device__ float g_gi_f[SS*BB*GG];
__device__ float g_gi_b[SS*BB*GG];
__device__ float g_h[2][2][BB*UU];
__device__ float g_ghp[2][4][BB*GG];        // encoder gh split-K partials (4 chunks)
__device__ float g_enc[BB*SS*H2];           // enc_bt (b,s,2U) — written directly by gate
__device__ float g_hfb[BB*H2];
__device__ float g_state[2][BB*UU];
__device__ float g_encproj[BB*SS*AD];
__device__ float g_embt[TM1*BB*EE];
__device__ float g_ctx[BB*H2];
__device__ float g_dgi[8][BB*GG];           // decoder gi partials (8 chunks)
__device__ float g_dgh[4][BB*GG];           // decoder gh partials (4 chunks)
__device__ int   g_ctr[SS + 2*TM1];         // per-phase barrier counters

// split-bf16 operands for the logits GEMM (A written directly by decoder phase 3)
__device__ __nv_bfloat16 g_whi[(long)NP*KP];
__device__ __nv_bfloat16 g_wlo[(long)NP*KP];
__device__ __nv_bfloat16 g_ahi[(long)MP*KP];
__device__ __nv_bfloat16 g_alo[(long)MP*KP];

__device__ __forceinline__ float sigm(float x) { return 1.0f / (1.0f + expf(-x)); }

__device__ __forceinline__ void gbar(int* ctr, int target) {
    __syncthreads();
    if (threadIdx.x == 0) {
        __threadfence();
        atomicAdd(ctr, 1);
        volatile int* v = ctr;
        while (*v < target) { __nanosleep(64); }
    }
    __syncthreads();
}

// ---- packed f32x2 helpers ----
__device__ __forceinline__ unsigned long long pk2(float x, float y) {
    unsigned long long r;
    asm("mov.b64 %0, {%1, %2};" : "=l"(r) : "f"(x), "f"(y));
    return r;
}
__device__ __forceinline__ void fma2(unsigned long long& d, unsigned long long a, unsigned long long b) {
    asm("fma.rn.f32x2 %0, %1, %2, %0;" : "+l"(d) : "l"(a), "l"(b));
}
__device__ __forceinline__ float2 upk2(unsigned long long v) {
    float2 f;
    asm("mov.b64 {%0, %1}, %2;" : "=f"(f.x), "=f"(f.y) : "l"(v));
    return f;
}

// ---------------- tiny utility kernels ----------------
__global__ void k_zero(float* p, int n) {
    int i = blockIdx.x * blockDim.x + threadIdx.x;
    if (i < n) p[i] = 0.0f;
}

// zero the pad regions of g_ahi/g_alo: cols [FF,KP) all rows; rows [MTOT,MP) cols [0,FF)
__global__ void k_pad_a() {
    int idx = blockIdx.x * blockDim.x + threadIdx.x;
    int padc = KP - FF;                 // 20
    int n1 = MP * padc;                 // col-pad region
    int n2 = (MP - MTOT) * FF;          // row-pad region
    if (idx < n1) {
        int m = idx / padc, c = FF + idx % padc;
        g_ahi[(long)m*KP + c] = __float2bfloat16(0.f);
        g_alo[(long)m*KP + c] = __float2bfloat16(0.f);
    } else if (idx < n1 + n2) {
        int j = idx - n1;
        int m = MTOT + j / FF, c = j % FF;
        g_ahi[(long)m*KP + c] = __float2bfloat16(0.f);
        g_alo[(long)m*KP + c] = __float2bfloat16(0.f);
    }
}

__global__ void k_gather_src(const float* __restrict__ emb, const int* __restrict__ src) {
    int idx = blockIdx.x * blockDim.x + threadIdx.x;
    if (idx >= SS*BB*EE) return;
    int e = idx % EE; int tb = idx / EE;
    g_emb_s[idx] = emb[(long)src[tb]*EE + e];
}

__global__ void k_gather_trg(const float* __restrict__ emb, const int* __restrict__ trg) {
    int idx = blockIdx.x * blockDim.x + threadIdx.x;
    if (idx >= TM1*BB*EE) return;
    int e = idx % EE; int tb = idx / EE;
    g_embt[idx] = emb[(long)trg[tb]*EE + e];
}

// hf = enc[b][S-1][0:U], hb = enc[b][0][U:2U]
__global__ void k_concat_hfb() {
    int idx = blockIdx.x * blockDim.x + threadIdx.x;
    if (idx >= BB*H2) return;
    int h = idx % H2; int b = idx / H2;
    float v = (h < UU) ? g_enc[((long)b*SS + (SS-1))*H2 + h]
                       : g_enc[((long)b*SS)*H2 + h];
    g_hfb[idx] = v;
}

// ---------------- W split kernel ----------------
__global__ void k_split_w4(const float* __restrict__ W) {
    long idx = (long)blockIdx.x * blockDim.x + threadIdx.x;
    long total = (long)NP * (KP/4);
    if (idx >= total) return;
    int kq = (int)(idx % (KP/4)) * 4;
    int n  = (int)(idx / (KP/4));
    float4 x = make_float4(0.f, 0.f, 0.f, 0.f);
    if (n < VTT) {
        if (kq + 4 <= FF) {
            x = *reinterpret_cast<const float4*>(&W[(long)n*FF + kq]);
        } else if (kq < FF) {
            const float* src = &W[(long)n*FF + kq];
            float t[4] = {0,0,0,0};
            for (int j = 0; j < 4; j++) if (kq + j < FF) t[j] = src[j];
            x = make_float4(t[0], t[1], t[2], t[3]);
        }
    }
    __nv_bfloat16 h0 = __float2bfloat16(x.x), h1 = __float2bfloat16(x.y);
    __nv_bfloat16 h2 = __float2bfloat16(x.z), h3 = __float2bfloat16(x.w);
    __nv_bfloat16 l0 = __float2bfloat16(x.x - __bfloat162float(h0));
    __nv_bfloat16 l1 = __float2bfloat16(x.y - __bfloat162float(h1));
    __nv_bfloat16 l2 = __float2bfloat16(x.z - __bfloat162float(h2));
    __nv_bfloat16 l3 = __float2bfloat16(x.w - __bfloat162float(h3));
    long o = (long)n*KP + kq;
    __nv_bfloat162 hA; hA.x = h0; hA.y = h1;
    __nv_bfloat162 hB; hB.x = h2; hB.y = h3;
    __nv_bfloat162 lA; lA.x = l0; lA.y = l1;
    __nv_bfloat162 lB; lB.x = l2; lB.y = l3;
    *reinterpret_cast<__nv_bfloat162*>(&g_whi[o])   = hA;
    *reinterpret_cast<__nv_bfloat162*>(&g_whi[o+2]) = hB;
    *reinterpret_cast<__nv_bfloat162*>(&g_wlo[o])   = lA;
    *reinterpret_cast<__nv_bfloat162*>(&g_wlo[o+2]) = lB;
}

// ---------------- fp32x2 tiled GEMM ----------------
__global__ void __launch_bounds__(256, 2)
k_gemm(const float* __restrict__ Ap, int lda,
       const float* __restrict__ Wp, int ldw, int woff,
       const float* __restrict__ bias,
       float* __restrict__ Cp, int ldc,
       int M, int N, int K, int act)
{
    __shared__ float sA[16][128];
    __shared__ float sW[16][128];
    int tid = threadIdx.x;
    int m0 = blockIdx.y * 128, n0 = blockIdx.x * 128;
    int tr = tid & 15, tc = tid >> 4;

    unsigned long long acc[8][4];
    #pragma unroll
    for (int i = 0; i < 8; i++)
        #pragma unroll
        for (int j = 0; j < 4; j++) acc[i][j] = 0ull;

    int r  = tid >> 2;
    int kq = (tid & 3) * 4;

    for (int k0 = 0; k0 < K; k0 += 16) {
        bool kok = (k0 + kq) < K;
        #pragma unroll
        for (int h = 0; h < 2; h++) {
            int row = r + h * 64;
            float4 va = make_float4(0.f, 0.f, 0.f, 0.f);
            int m = m0 + row;
            if (kok && m < M) va = *reinterpret_cast<const float4*>(&Ap[(long)m*lda + k0 + kq]);
            sA[kq+0][row] = va.x; sA[kq+1][row] = va.y;
            sA[kq+2][row] = va.z; sA[kq+3][row] = va.w;

            float4 vw = make_float4(0.f, 0.f, 0.f, 0.f);
            int n = n0 + row;
            if (kok && n < N) vw = *reinterpret_cast<const float4*>(&Wp[(long)n*ldw + woff + k0 + kq]);
            sW[kq+0][row] = vw.x; sW[kq+1][row] = vw.y;
            sW[kq+2][row] = vw.z; sW[kq+3][row] = vw.w;
        }
        __syncthreads();

        #pragma unroll
        for (int kk = 0; kk < 16; kk++) {
            float4 a0 = *reinterpret_cast<const float4*>(&sA[kk][tr*8]);
            float4 a1 = *reinterpret_cast<const float4*>(&sA[kk][tr*8 + 4]);
            unsigned long long bp[4];
            #pragma unroll
            for (int j = 0; j < 4; j++)
                bp[j] = *reinterpret_cast<const unsigned long long*>(&sW[kk][tc*8 + 2*j]);
            float av[8] = {a0.x, a0.y, a0.z, a0.w, a1.x, a1.y, a1.z, a1.w};
            #pragma unroll
            for (int i = 0; i < 8; i++) {
                unsigned long long ap = pk2(av[i], av[i]);
                #pragma unroll
                for (int j = 0; j < 4; j++) fma2(acc[i][j], ap, bp[j]);
            }
        }
        __syncthreads();
    }

    #pragma unroll
    for (int i = 0; i < 8; i++) {
        int m = m0 + tr*8 + i;
        if (m >= M) continue;
        #pragma unroll
        for (int j = 0; j < 4; j++) {
            float2 v = upk2(acc[i][j]);
            int n = n0 + tc*8 + 2*j;
            if (n < N) {
                float c = v.x + (bias ? bias[n] : 0.0f);
                if (act) c = tanhf(c);
                Cp[(long)m*ldc + n] = c;
            }
            if (n + 1 < N) {
                float c = v.y + (bias ? bias[n+1] : 0.0f);
                if (act) c = tanhf(c);
                Cp[(long)m*ldc + n + 1] = c;
            }
        }
    }
}

// ================= mma.sync bf16 logits GEMM (64x128 tile, 2 CTAs/SM) =================
__device__ __forceinline__ uint32_t smem_u32(const void* p) {
    uint32_t a;
    asm("{ .reg .u64 t; cvta.to.shared.u64 t, %1; cvt.u32.u64 %0, t; }" : "=r"(a) : "l"(p));
    return a;
}
__device__ __forceinline__ void cpa16(uint32_t dst, const void* src) {
    asm volatile("cp.async.cg.shared.global [%0], [%1], 16;" :: "r"(dst), "l"(src) : "memory");
}
__device__ __forceinline__ void cpa_commit() {
    asm volatile("cp.async.commit_group;" ::: "memory");
}
__device__ __forceinline__ void ldsm4(uint32_t* r, uint32_t addr) {
    asm volatile("ldmatrix.sync.aligned.m8n8.x4.shared.b16 {%0,%1,%2,%3}, [%4];"
        : "=r"(r[0]), "=r"(r[1]), "=r"(r[2]), "=r"(r[3]) : "r"(addr));
}
__device__ __forceinline__ void mma16816(float* d, const uint32_t* a, const uint32_t* b) {
    asm volatile("mma.sync.aligned.m16n8k16.row.col.f32.bf16.bf16.f32 "
        "{%0,%1,%2,%3}, {%4,%5,%6,%7}, {%8,%9}, {%0,%1,%2,%3};"
        : "+f"(d[0]), "+f"(d[1]), "+f"(d[2]), "+f"(d[3])
        : "r"(a[0]), "r"(a[1]), "r"(a[2]), "r"(a[3]), "r"(b[0]), "r"(b[1]));
}

#define LSTG 49152
#define LOG_SMEM (2*LSTG)

__global__ void __launch_bounds__(256, 2)
k_logits_mma(const float* __restrict__ bias, float* __restrict__ outp)
{
    extern __shared__ __align__(128) char smem[];
    uint32_t sb = smem_u32(smem);
    int tid = threadIdx.x;
    int wid = tid >> 5, lane = tid & 31;
    int wm = wid >> 2, wn = wid & 3;
    int grp = lane >> 3, lr = lane & 7;
    int m0 = blockIdx.x * 64;
    int n0 = blockIdx.y * 128;

    float acc[2][4][4];
    #pragma unroll
    for (int i = 0; i < 2; i++)
        #pragma unroll
        for (int j = 0; j < 4; j++)
            #pragma unroll
            for (int c = 0; c < 4; c++) acc[i][j][c] = 0.0f;

    auto load_stage = [&](int it, int s) {
        int k0 = it * 64;
        uint32_t base = sb + s * LSTG;
        #pragma unroll
        for (int q = 0; q < 2; q++) {
            int u = tid + q * 256;
            int row = u >> 3, c = u & 7;
            uint32_t off = row * 128 + (((uint32_t)(c ^ (row & 7))) << 4);
            long ga = (long)(m0 + row) * KP + k0 + c * 8;
            cpa16(base + off,         g_ahi + ga);
            cpa16(base + 8192 + off,  g_alo + ga);
        }
        #pragma unroll
        for (int q = 0; q < 4; q++) {
            int u = tid + q * 256;
            int row = u >> 3, c = u & 7;
            uint32_t off = row * 128 + (((uint32_t)(c ^ (row & 7))) << 4);
            long gb = (long)(n0 + row) * KP + k0 + c * 8;
            cpa16(base + 16384 + off, g_whi + gb);
            cpa16(base + 32768 + off, g_wlo + gb);
        }
    };

    load_stage(0, 0);
    cpa_commit();

    for (int it = 0; it < KITER; it++) {
        int s = it & 1;
        if (it < KITER - 1) {
            load_stage(it + 1, s ^ 1);
            cpa_commit();
            asm volatile("cp.async.wait_group 1;" ::: "memory");
        } else {
            asm volatile("cp.async.wait_group 0;" ::: "memory");
        }
        __syncthreads();

        uint32_t aAhi = sb + s*LSTG;
        uint32_t aAlo = aAhi + 8192;
        uint32_t aBhi = aAhi + 16384;
        uint32_t aBlo = aAhi + 32768;

        #pragma unroll
        for (int ks = 0; ks < 4; ks++) {
            uint32_t fa_hi[2][4], fa_lo[2][4];
            #pragma unroll
            for (int mt = 0; mt < 2; mt++) {
                int row = wm*32 + mt*16 + lr + (grp & 1) * 8;
                int c = 2*ks + (grp >> 1);
                uint32_t off = row * 128 + (((uint32_t)(c ^ (row & 7))) << 4);
                ldsm4(fa_hi[mt], aAhi + off);
                ldsm4(fa_lo[mt], aAlo + off);
            }
            uint32_t fb_hi[2][4], fb_lo[2][4];
            #pragma unroll
            for (int p = 0; p < 2; p++) {
                int nrow = wn*32 + p*16 + lr + (grp >> 1) * 8;
                int c = 2*ks + (grp & 1);
                uint32_t off = nrow * 128 + (((uint32_t)(c ^ (nrow & 7))) << 4);
                ldsm4(fb_hi[p], aBhi + off);
                ldsm4(fb_lo[p], aBlo + off);
            }
            #pragma unroll
            for (int mt = 0; mt < 2; mt++) {
                #pragma unroll
                for (int nt = 0; nt < 4; nt++) {
                    const uint32_t* bh = &fb_hi[nt >> 1][(nt & 1) * 2];
                    const uint32_t* bl = &fb_lo[nt >> 1][(nt & 1) * 2];
                    mma16816(acc[mt][nt], fa_hi[mt], bh);
                    mma16816(acc[mt][nt], fa_lo[mt], bh);
                    mma16816(acc[mt][nt], fa_hi[mt], bl);
                }
            }
        }
        __syncthreads();
    }

    int mrow = (lane >> 2);
    int ncol = (lane & 3) * 2;
    #pragma unroll
    for (int mt = 0; mt < 2; mt++) {
        #pragma unroll
        for (int nt = 0; nt < 4; nt++) {
            int n = n0 + wn*32 + nt*8 + ncol;
            if (n >= VTT) continue;
            float2 bv = *reinterpret_cast<const float2*>(&bias[n]);
            int m1 = m0 + wm*32 + mt*16 + mrow;
            int m2 = m1 + 8;
            if (m1 < MTOT) {
                float2 v = make_float2(acc[mt][nt][0] + bv.x, acc[mt][nt][1] + bv.y);
                *reinterpret_cast<float2*>(&outp[(long)m1*VTT + n]) = v;
            }
            if (m2 < MTOT) {
                float2 v = make_float2(acc[mt][nt][2] + bv.x, acc[mt][nt][3] + bv.y);
                *reinterpret_cast<float2*>(&outp[(long)m2*VTT + n]) = v;
            }
        }
    }
}

// ================= encoder step kernel: 192 blocks, pipelined gh GEMM =================
__global__ void __launch_bounds__(256, 2)
k_enc_step(int step,
           const float* __restrict__ Whh_f, const float* __restrict__ Whh_b,
           const float* __restrict__ bhh_f, const float* __restrict__ bhh_b)
{
    __shared__ float sA[2][16][32];
    __shared__ float sW[2][16][64];
    int blk = blockIdx.x, tid = threadIdx.x;
    int par = step & 1;
    int dir = blk >= 96;
    int rem = dir ? blk - 96 : blk;
    int ntile = rem >> 2;
    int kc = rem & 3;
    int n0 = ntile * 64;
    int kbase = kc * 128;
    const float* W = dir ? Whh_b : Whh_f;
    const float* h = g_h[dir][par];
    int tm = tid & 15, tn = tid >> 4;
    int r = tid >> 2, kq = (tid & 3) * 4;
    float acc[2][4] = {};
    float4 ra = make_float4(0,0,0,0), rw;

    if (tid < 128) ra = *(const float4*)&h[r*UU + kbase + kq];
    rw = *(const float4*)&W[(long)(n0+r)*UU + kbase + kq];

    int s = 0;
    #pragma unroll
    for (int it = 0; it < 8; it++) {
        if (tid < 128) {
            sA[s][kq+0][r] = ra.x; sA[s][kq+1][r] = ra.y;
            sA[s][kq+2][r] = ra.z; sA[s][kq+3][r] = ra.w;
        }
        sW[s][kq+0][r] = rw.x; sW[s][kq+1][r] = rw.y;
        sW[s][kq+2][r] = rw.z; sW[s][kq+3][r] = rw.w;
        __syncthreads();
        if (it < 7) {
            int k0 = kbase + (it + 1) * 16;
            if (tid < 128) ra = *(const float4*)&h[r*UU + k0 + kq];
            rw = *(const float4*)&W[(long)(n0+r)*UU + k0 + kq];
        }
        #pragma unroll
        for (int kk = 0; kk < 16; kk++) {
            float2 a2 = *reinterpret_cast<const float2*>(&sA[s][kk][tm*2]);
            float4 b4 = *reinterpret_cast<const float4*>(&sW[s][kk][tn*4]);
            acc[0][0] = fmaf(a2.x, b4.x, acc[0][0]);
            acc[0][1] = fmaf(a2.x, b4.y, acc[0][1]);
            acc[0][2] = fmaf(a2.x, b4.z, acc[0][2]);
            acc[0][3] = fmaf(a2.x, b4.w, acc[0][3]);
            acc[1][0] = fmaf(a2.y, b4.x, acc[1][0]);
            acc[1][1] = fmaf(a2.y, b4.y, acc[1][1]);
            acc[1][2] = fmaf(a2.y, b4.z, acc[1][2]);
            acc[1][3] = fmaf(a2.y, b4.w, acc[1][3]);
        }
        s ^= 1;
    }
    float* outp = &g_ghp[dir][kc][0];
    #pragma unroll
    for (int i = 0; i < 2; i++) {
        int b = tm*2 + i;
        #pragma unroll
        for (int j = 0; j < 4; j++)
            outp[b*GG + n0 + tn*4 + j] = acc[i][j];
    }

    gbar(&g_ctr[step], PBLK);

    // gate: write h directly into g_enc layout (b, s, dir*UU + u)
    int tf = step, tb = SS-1-step;
    for (int idx = blk*256 + tid; idx < 2*BB*UU; idx += PBLK*256) {
        int u = idx & 511;
        int b = (idx >> 9) & 31;
        int d2 = idx >> 14;
        const float* gi = d2 ? (g_gi_b + (long)tb*BB*GG) : (g_gi_f + (long)tf*BB*GG);
        const float* bhh = d2 ? bhh_b : bhh_f;
        float ghr = bhh[u], ghz = bhh[u+UU], ghn = bhh[u+2*UU];
        #pragma unroll
        for (int kc2 = 0; kc2 < 4; kc2++) {
            const float* p = &g_ghp[d2][kc2][b*GG];
            ghr += __ldcg(&p[u]); ghz += __ldcg(&p[u+UU]); ghn += __ldcg(&p[u+2*UU]);
        }
        float ir = gi[b*GG + u], iz = gi[b*GG + u + UU], inn = gi[b*GG + u + 2*UU];
        float r2 = sigm(ir + ghr);
        float z = sigm(iz + ghz);
        float n = tanhf(inn + r2*ghn);
        float hp = g_h[d2][par][b*UU + u];
        float hn_ = (1.0f - z)*n + z*hp;
        g_h[d2][par^1][b*UU + u] = hn_;
        int sidx = d2 ? tb : tf;
        g_enc[((long)b*SS + sidx)*H2 + d2*UU + u] = hn_;
    }
}

// ================= decoder step kernel: 192 blocks =================
__global__ void __launch_bounds__(256, 2)
k_dec_step(int t,
           const float* __restrict__ attn_W,
           const float* __restrict__ Wih, const float* __restrict__ Whh,
           const float* __restrict__ bih, const float* __restrict__ bhh)
{
    __shared__ float sA[2][16][32];
    __shared__ float sW[2][16][64];
    __shared__ float s_st[UU];
    __shared__ float s_sc[SS];
    __shared__ float s_red[2];

    int blk = blockIdx.x, tid = threadIdx.x;
    int tm = tid & 15, tn = tid >> 4;
    int spar = t & 1;
    const float* st_g = g_state[spar];

    if (blk < 32) {
        int b = blk;
        float* s_tp = &sW[0][0][0];
        const float* st = &st_g[b*UU];
        for (int i = tid; i < UU; i += 256) s_st[i] = st[i];
        __syncthreads();
        for (int a = tid; a < AD; a += 256) {
            const float* w = attn_W + (long)a*GG;
            float acc = 0.0f;
            #pragma unroll 4
            for (int k = 0; k < UU; k += 4) {
                float4 wv = *reinterpret_cast<const float4*>(w + k);
                acc = fmaf(s_st[k],   wv.x, acc);
                acc = fmaf(s_st[k+1], wv.y, acc);
                acc = fmaf(s_st[k+2], wv.z, acc);
                acc = fmaf(s_st[k+3], wv.w, acc);
            }
            s_tp[a] = acc;
        }
        __syncthreads();
        {
            int s = tid >> 2, q = tid & 3;
            const float* ep = g_encproj + ((long)b*SS + s)*AD + q*128;
            const float* tp = s_tp + q*128;
            float partial = 0.0f;
            for (int a = 0; a < 128; a++) partial += tanhf(tp[a] + ep[a]);
            partial += __shfl_down_sync(0xffffffffu, partial, 2);
            partial += __shfl_down_sync(0xffffffffu, partial, 1);
            if (q == 0) s_sc[s] = partial;
        }
        __syncthreads();
        if (tid == 0) {
            float mx = s_sc[0];
            for (int s = 1; s < SS; s++) mx = fmaxf(mx, s_sc[s]);
            s_red[0] = mx;
        }
        __syncthreads();
        if (tid < SS) s_sc[tid] = expf(s_sc[tid] - s_red[0]);
        __syncthreads();
        if (tid == 0) {
            float sm = 0.0f;
            for (int s = 0; s < SS; s++) sm += s_sc[s];
            s_red[1] = 1.0f / sm;
        }
        __syncthreads();
        float inv = s_red[1];
        for (int h = tid; h < H2; h += 256) {
            const float* e = g_enc + (long)b*SS*H2 + h;
            float acc = 0.0f;
            #pragma unroll 8
            for (int s = 0; s < SS; s++) acc = fmaf(s_sc[s], e[(long)s*H2], acc);
            g_ctx[b*H2 + h] = acc * inv;
        }
    } else if (blk < 128) {
        int idx2 = blk - 32;
        int ntile = idx2 >> 2;
        int kc = idx2 & 3;
        int n0 = ntile * 64;
        int kbase = kc * 128;
        int r = tid >> 2, kq = (tid & 3) * 4;
        float acc[2][4] = {};
        float4 ra = make_float4(0,0,0,0), rw;
        if (tid < 128) ra = *(const float4*)&st_g[r*UU + kbase + kq];
        rw = *(const float4*)&Whh[(long)(n0+r)*UU + kbase + kq];
        int s = 0;
        #pragma unroll
        for (int it = 0; it < 8; it++) {
            if (tid < 128) {
                sA[s][kq+0][r] = ra.x; sA[s][kq+1][r] = ra.y;
                sA[s][kq+2][r] = ra.z; sA[s][kq+3][r] = ra.w;
            }
            sW[s][kq+0][r] = rw.x; sW[s][kq+1][r] = rw.y;
            sW[s][kq+2][r] = rw.z; sW[s][kq+3][r] = rw.w;
            __syncthreads();
            if (it < 7) {
                int k0 = kbase + (it + 1) * 16;
                if (tid < 128) ra = *(const float4*)&st_g[r*UU + k0 + kq];
                rw = *(const float4*)&Whh[(long)(n0+r)*UU + k0 + kq];
            }
            #pragma unroll
            for (int kk = 0; kk < 16; kk++) {
                float2 a2 = *reinterpret_cast<const float2*>(&sA[s][kk][tm*2]);
                float4 b4 = *reinterpret_cast<const float4*>(&sW[s][kk][tn*4]);
                acc[0][0] = fmaf(a2.x, b4.x, acc[0][0]);
                acc[0][1] = fmaf(a2.x, b4.y, acc[0][1]);
                acc[0][2] = fmaf(a2.x, b4.z, acc[0][2]);
                acc[0][3] = fmaf(a2.x, b4.w, acc[0][3]);
                acc[1][0] = fmaf(a2.y, b4.x, acc[1][0]);
                acc[1][1] = fmaf(a2.y, b4.y, acc[1][1]);
                acc[1][2] = fmaf(a2.y, b4.z, acc[1][2]);
                acc[1][3] = fmaf(a2.y, b4.w, acc[1][3]);
            }
            s ^= 1;
        }
        float* outp = &g_dgh[kc][0];
        #pragma unroll
        for (int i = 0; i < 2; i++) {
            int b = tm*2 + i;
            #pragma unroll
            for (int j = 0; j < 4; j++)
                outp[b*GG + n0 + tn*4 + j] = acc[i][j];
        }
    }
    gbar(&g_ctr[SS + 2*t], PBLK);

    // ---------- Phase 2: gi GEMM (24 ntiles x 8 kc, K=166), reg-prefetch ----------
    {
        int ntile = blk >> 3;
        int kc = blk & 7;
        int n0 = ntile * 64;
        int kbeg = kc * 166;
        int kend = min(KX, kbeg + 166);
        const float* em = g_embt + (long)t*BB*EE;
        int r = tid >> 2, kq = (tid & 3) * 4;
        float acc[2][4] = {};
        float va[4] = {0,0,0,0}, vw[4] = {0,0,0,0};

        auto ldA = [&](int k0, float* v) {
            #pragma unroll
            for (int j = 0; j < 4; j++) {
                int k = k0 + kq + j;
                float x = 0.0f;
                if (k < kend)
                    x = (k < EE) ? em[r*EE + k] : __ldcg(&g_ctx[r*H2 + k - EE]);
                v[j] = x;
            }
        };
        auto ldW = [&](int k0, float* v) {
            #pragma unroll
            for (int j = 0; j < 4; j++) {
                int k = k0 + kq + j;
                v[j] = (k < kend) ? Wih[(long)(n0+r)*KX + k] : 0.0f;
            }
        };

        if (tid < 128) ldA(kbeg, va);
        ldW(kbeg, vw);

        int s = 0;
        for (int k0 = kbeg; k0 < kend; k0 += 16) {
            if (tid < 128) {
                sA[s][kq+0][r] = va[0]; sA[s][kq+1][r] = va[1];
                sA[s][kq+2][r] = va[2]; sA[s][kq+3][r] = va[3];
            }
            sW[s][kq+0][r] = vw[0]; sW[s][kq+1][r] = vw[1];
            sW[s][kq+2][r] = vw[2]; sW[s][kq+3][r] = vw[3];
            __syncthreads();
            if (k0 + 16 < kend) {
                if (tid < 128) ldA(k0 + 16, va);
                ldW(k0 + 16, vw);
            }
            #pragma unroll
            for (int kk = 0; kk < 16; kk++) {
                float2 a2 = *reinterpret_cast<const float2*>(&sA[s][kk][tm*2]);
                float4 b4 = *reinterpret_cast<const float4*>(&sW[s][kk][tn*4]);
                acc[0][0] = fmaf(a2.x, b4.x, acc[0][0]);
                acc[0][1] = fmaf(a2.x, b4.y, acc[0][1]);
                acc[0][2] = fmaf(a2.x, b4.z, acc[0][2]);
                acc[0][3] = fmaf(a2.x, b4.w, acc[0][3]);
                acc[1][0] = fmaf(a2.y, b4.x, acc[1][0]);
                acc[1][1] = fmaf(a2.y, b4.y, acc[1][1]);
                acc[1][2] = fmaf(a2.y, b4.z, acc[1][2]);
                acc[1][3] = fmaf(a2.y, b4.w, acc[1][3]);
            }
            s ^= 1;
        }
        float* outp = &g_dgi[kc][0];
        #pragma unroll
        for (int i = 0; i < 2; i++) {
            int b = tm*2 + i;
            #pragma unroll
            for (int j = 0; j < 4; j++)
                outp[b*GG + n0 + tn*4 + j] = acc[i][j];
        }
    }
    gbar(&g_ctr[SS + 2*t + 1], PBLK);

    // ---------- Phase 3: gate + DIRECT bf16 hi/lo feature writes ----------
    for (int idx = blk*256 + tid; idx < BB*FF; idx += PBLK*256) {
        int f = idx % FF; int b = idx / FF;
        long m = (long)t*BB + b;
        float x;
        if (f < UU) {
            int u = f;
            float gir = bih[u], giz = bih[u+UU], gin = bih[u+2*UU];
            float ghr = bhh[u], ghz = bhh[u+UU], ghn = bhh[u+2*UU];
            #pragma unroll
            for (int kc = 0; kc < 8; kc++) {
                const float* pi = &g_dgi[kc][b*GG];
                gir += __ldcg(&pi[u]); giz += __ldcg(&pi[u+UU]); gin += __ldcg(&pi[u+2*UU]);
            }
            #pragma unroll
            for (int kc = 0; kc < 4; kc++) {
                const float* ph = &g_dgh[kc][b*GG];
                ghr += __ldcg(&ph[u]); ghz += __ldcg(&ph[u+UU]); ghn += __ldcg(&ph[u+2*UU]);
            }
            float r = sigm(gir + ghr);
            float z = sigm(giz + ghz);
            float n = tanhf(gin + r*ghn);
            float hp = st_g[b*UU + u];
            float h2 = (1.0f - z)*n + z*hp;
            g_state[spar^1][b*UU + u] = h2;
            x = h2;
        } else if (f < UU + H2) {
            x = __ldcg(&g_ctx[b*H2 + f - UU]);
        } else {
            x = g_embt[((long)t*BB + b)*EE + f - UU - H2];
        }
        __nv_bfloat16 h = __float2bfloat16(x);
        g_ahi[m*KP + f] = h;
        g_alo[m*KP + f] = __float2bfloat16(x - __bfloat162float(h));
    }
}

// ---------------- host: streams (created at load; not device mem) ----------------
static cudaStream_t g_s2 = nullptr, g_s3 = nullptr;
static cudaEvent_t g_evf = nullptr, g_evd = nullptr, g_evsrc = nullptr,
                   g_evgib = nullptr, g_evenc = nullptr, g_evprj = nullptr;
namespace {
struct StreamInit {
    StreamInit() {
        cudaStreamCreateWithFlags(&g_s2, cudaStreamNonBlocking);
        cudaStreamCreateWithFlags(&g_s3, cudaStreamNonBlocking);
        cudaEventCreateWithFlags(&g_evf,  cudaEventDisableTiming);
        cudaEventCreateWithFlags(&g_evd,  cudaEventDisableTiming);
        cudaEventCreateWithFlags(&g_evsrc, cudaEventDisableTiming);
        cudaEventCreateWithFlags(&g_evgib, cudaEventDisableTiming);
        cudaEventCreateWithFlags(&g_evenc, cudaEventDisableTiming);
        cudaEventCreateWithFlags(&g_evprj, cudaEventDisableTiming);
    }
};
StreamInit g_stream_init;
}

static float* symaddr(const void* sym) {
    void* p = nullptr;
    cudaGetSymbolAddress(&p, sym);
    return (float*)p;
}

extern "C" void kernel_launch(void* const* d_in, const int* in_sizes, int n_in,
                              void* d_out, int out_size)
{
    const float* emb_src   = (const float*)d_in[0];
    const float* emb_trg   = (const float*)d_in[1];
    const float* enc_Wih_f = (const float*)d_in[2];
    const float* enc_Whh_f = (const float*)d_in[3];
    const float* enc_bih_f = (const float*)d_in[4];
    const float* enc_bhh_f = (const float*)d_in[5];
    const float* enc_Wih_b = (const float*)d_in[6];
    const float* enc_Whh_b = (const float*)d_in[7];
    const float* enc_bih_b = (const float*)d_in[8];
    const float* enc_bhh_b = (const float*)d_in[9];
    const float* enc_Wfc   = (const float*)d_in[10];
    const float* enc_bfc   = (const float*)d_in[11];
    const float* attn_W    = (const float*)d_in[12];
    const float* attn_b    = (const float*)d_in[13];
    const float* dec_Wih   = (const float*)d_in[14];
    const float* dec_Whh   = (const float*)d_in[15];
    const float* dec_bih   = (const float*)d_in[16];
    const float* dec_bhh   = (const float*)d_in[17];
    const float* dec_Wfc   = (const float*)d_in[18];
    const float* dec_bfc   = (const float*)d_in[19];
    const int*   source    = (const int*)d_in[20];
    const int*   target    = (const int*)d_in[21];
    float* out = (float*)d_out;

    float* p_emb_s   = symaddr(g_emb_s);
    float* p_gi_f    = symaddr(g_gi_f);
    float* p_gi_b    = symaddr(g_gi_b);
    float* p_h       = symaddr(g_h);
    float* p_enc     = symaddr(g_enc);
    float* p_hfb     = symaddr(g_hfb);
    float* p_state   = symaddr(g_state);
    float* p_encproj = symaddr(g_encproj);
    float* p_ctr     = symaddr(g_ctr);

    static int attr_set = 0;
    if (!attr_set) {
        cudaFuncSetAttribute(k_logits_mma, cudaFuncAttributeMaxDynamicSharedMemorySize, LOG_SMEM);
        attr_set = 1;
    }

    // fork s2: split_w (needs only dec_Wfc), joins before logits
    cudaEventRecord(g_evf, 0);
    cudaStreamWaitEvent(g_s2, g_evf, 0);
    {
        long total = (long)NP * (KP/4);
        k_split_w4<<<(unsigned)((total + 255)/256), 256, 0, g_s2>>>(dec_Wfc);
    }
    cudaEventRecord(g_evd, g_s2);

    // front (main stream)
    k_zero<<<1, 128>>>((float*)p_ctr, SS + 2*TM1);
    k_zero<<<(2*2*BB*UU + 255)/256, 256>>>(p_h, 2*2*BB*UU);
    {
        int padn = MP*(KP-FF) + (MP-MTOT)*FF;
        k_pad_a<<<(padn + 255)/256, 256>>>();
    }
    k_zero<<<(BB*VTT + 255)/256, 256>>>(out, BB*VTT);   // output row 0
    k_gather_src<<<(SS*BB*EE + 255)/256, 256>>>(emb_src, source);
    cudaEventRecord(g_evsrc, 0);
    k_gather_trg<<<(TM1*BB*EE + 255)/256, 256>>>(emb_trg, target);

    // gi_b on s3 (after gather_src), gi_f on main — run concurrently
    cudaStreamWaitEvent(g_s3, g_evsrc, 0);
    {
        dim3 grid(GG/128, (SS*BB)/128);
        k_gemm<<<grid, 256, 0, g_s3>>>(p_emb_s, EE, enc_Wih_b, EE, 0, enc_bih_b,
                                       p_gi_b, GG, SS*BB, GG, EE, 0);
    }
    cudaEventRecord(g_evgib, g_s3);
    {
        dim3 grid(GG/128, (SS*BB)/128);
        k_gemm<<<grid, 256>>>(p_emb_s, EE, enc_Wih_f, EE, 0, enc_bih_f,
                              p_gi_f, GG, SS*BB, GG, EE, 0);
    }
    cudaStreamWaitEvent(0, g_evgib, 0);

    // encoder recurrence
    for (int i = 0; i < SS; i++) {
        k_enc_step<<<PBLK, 256>>>(i, enc_Whh_f, enc_Whh_b, enc_bhh_f, enc_bhh_b);
    }
    cudaEventRecord(g_evenc, 0);

    // encproj on s3 (reads g_enc), concurrent with hfb + dec-init on main
    cudaStreamWaitEvent(g_s3, g_evenc, 0);
    {
        dim3 grid(AD/128, (BB*SS)/128);
        k_gemm<<<grid, 256, 0, g_s3>>>(p_enc, H2, attn_W, GG, UU, attn_b,
                                       p_encproj, AD, BB*SS, AD, H2, 0);
    }
    cudaEventRecord(g_evprj, g_s3);

    k_concat_hfb<<<(BB*H2 + 255)/256, 256>>>();
    {
        dim3 grid((UU + 127)/128, 1);
        k_gemm<<<grid, 256>>>(p_hfb, H2, enc_Wfc, H2, 0, enc_bfc,
                              p_state, UU, BB, UU, H2, 1);
    }
    cudaStreamWaitEvent(0, g_evprj, 0);

    // decoder recurrence (phase 3 writes bf16 A directly)
    for (int t = 0; t < TM1; t++) {
        k_dec_step<<<PBLK, 256>>>(t, attn_W, dec_Wih, dec_Whh, dec_bih, dec_bhh);
    }

    // join split_w, then logits
    cudaStreamWaitEvent(0, g_evd, 0);
    {
        dim3 grid(MP/64, NP/128);
        k_logits_mma<<<grid, 256, LOG_SMEM>>>(dec_bfc, out + (long)BB*VTT);
    }
}

// round 17
// speedup vs baseline: 1.4023x; 1.0283x over previous
#include <cuda_runtime.h>
#include <cuda_bf16.h>
#include <math.h>
#include <stdint.h>

#define SS 64      // source length
#define BB 32      // batch
#define UU 512     // hidden
#define GG 1536    // 3*U
#define EE 300     // embed dim
#define AD 512     // attention dim
#define VTT 30000  // target vocab
#define TT 32      // target length
#define TM1 31     // T-1 decode steps
#define FF 1836    // 3U + E
#define KX 1324    // 2U + E
#define H2 1024    // 2U
#define MTOT (TM1*BB)   // 992
#define PBLK 192   // step-kernel block count (2 CTAs/SM co-resident)

// logits GEMM padded dims
#define KP 1856
#define NP 30080
#define MP 1024
#define KITER 29

// ---------------- device scratch ----------------
__device__ float g_emb_s[SS*BB*EE];
__device__ float g_gi_f[SS*BB*GG];
__device__ float g_gi_b[SS*BB*GG];
__device__ float g_h[2][2][BB*UU];
__device__ float g_ghp[2][4][BB*GG];        // encoder gh split-K partials (4 chunks)
__device__ float g_enc[BB*SS*H2];           // enc_bt (b,s,2U) — written directly by gate
__device__ float g_hfb[BB*H2];
__device__ float g_state[2][BB*UU];
__device__ float g_encproj[BB*SS*AD];
__device__ float g_embt[TM1*BB*EE];
__device__ float g_gie[(long)TM1*BB*GG];    // precomputed gi embedding part
__device__ float g_ctx[BB*H2];
__device__ float g_dgi[8][BB*GG];           // decoder gi(ctx) partials (8 chunks)
__device__ float g_dgh[4][BB*GG];           // decoder gh partials (4 chunks)
__device__ int   g_ctr[SS + 2*TM1];         // per-phase barrier counters

// split-bf16 operands for the logits GEMM (A written directly by decoder phase 3)
__device__ __nv_bfloat16 g_whi[(long)NP*KP];
__device__ __nv_bfloat16 g_wlo[(long)NP*KP];
__device__ __nv_bfloat16 g_ahi[(long)MP*KP];
__device__ __nv_bfloat16 g_alo[(long)MP*KP];

// fast activations via MUFU.EX2 (error ~1e-6, far under 1e-3 budget)
__device__ __forceinline__ float fsigm(float x) { return 1.0f / (1.0f + __expf(-x)); }
__device__ __forceinline__ float ftanh(float x) { return 1.0f - 2.0f / (__expf(2.0f*x) + 1.0f); }

__device__ __forceinline__ void gbar(int* ctr, int target) {
    __syncthreads();
    if (threadIdx.x == 0) {
        __threadfence();
        atomicAdd(ctr, 1);
        volatile int* v = ctr;
        while (*v < target) { __nanosleep(64); }
    }
    __syncthreads();
}

// ---- packed f32x2 helpers ----
__device__ __forceinline__ unsigned long long pk2(float x, float y) {
    unsigned long long r;
    asm("mov.b64 %0, {%1, %2};" : "=l"(r) : "f"(x), "f"(y));
    return r;
}
__device__ __forceinline__ void fma2(unsigned long long& d, unsigned long long a, unsigned long long b) {
    asm("fma.rn.f32x2 %0, %1, %2, %0;" : "+l"(d) : "l"(a), "l"(b));
}
__device__ __forceinline__ float2 upk2(unsigned long long v) {
    float2 f;
    asm("mov.b64 {%0, %1}, %2;" : "=f"(f.x), "=f"(f.y) : "l"(v));
    return f;
}

// ---------------- tiny utility kernels ----------------
__global__ void k_zero(float* p, int n) {
    int i = blockIdx.x * blockDim.x + threadIdx.x;
    if (i < n) p[i] = 0.0f;
}

// zero the pad regions of g_ahi/g_alo
__global__ void k_pad_a() {
    int idx = blockIdx.x * blockDim.x + threadIdx.x;
    int padc = KP - FF;
    int n1 = MP * padc;
    int n2 = (MP - MTOT) * FF;
    if (idx < n1) {
        int m = idx / padc, c = FF + idx % padc;
        g_ahi[(long)m*KP + c] = __float2bfloat16(0.f);
        g_alo[(long)m*KP + c] = __float2bfloat16(0.f);
    } else if (idx < n1 + n2) {
        int j = idx - n1;
        int m = MTOT + j / FF, c = j % FF;
        g_ahi[(long)m*KP + c] = __float2bfloat16(0.f);
        g_alo[(long)m*KP + c] = __float2bfloat16(0.f);
    }
}

__global__ void k_gather_src(const float* __restrict__ emb, const int* __restrict__ src) {
    int idx = blockIdx.x * blockDim.x + threadIdx.x;
    if (idx >= SS*BB*EE) return;
    int e = idx % EE; int tb = idx / EE;
    g_emb_s[idx] = emb[(long)src[tb]*EE + e];
}

__global__ void k_gather_trg(const float* __restrict__ emb, const int* __restrict__ trg) {
    int idx = blockIdx.x * blockDim.x + threadIdx.x;
    if (idx >= TM1*BB*EE) return;
    int e = idx % EE; int tb = idx / EE;
    g_embt[idx] = emb[(long)trg[tb]*EE + e];
}

__global__ void k_concat_hfb() {
    int idx = blockIdx.x * blockDim.x + threadIdx.x;
    if (idx >= BB*H2) return;
    int h = idx % H2; int b = idx / H2;
    float v = (h < UU) ? g_enc[((long)b*SS + (SS-1))*H2 + h]
                       : g_enc[((long)b*SS)*H2 + h];
    g_hfb[idx] = v;
}

// ---------------- W split kernel ----------------
__global__ void k_split_w4(const float* __restrict__ W) {
    long idx = (long)blockIdx.x * blockDim.x + threadIdx.x;
    long total = (long)NP * (KP/4);
    if (idx >= total) return;
    int kq = (int)(idx % (KP/4)) * 4;
    int n  = (int)(idx / (KP/4));
    float4 x = make_float4(0.f, 0.f, 0.f, 0.f);
    if (n < VTT) {
        if (kq + 4 <= FF) {
            x = *reinterpret_cast<const float4*>(&W[(long)n*FF + kq]);
        } else if (kq < FF) {
            const float* src = &W[(long)n*FF + kq];
            float t[4] = {0,0,0,0};
            for (int j = 0; j < 4; j++) if (kq + j < FF) t[j] = src[j];
            x = make_float4(t[0], t[1], t[2], t[3]);
        }
    }
    __nv_bfloat16 h0 = __float2bfloat16(x.x), h1 = __float2bfloat16(x.y);
    __nv_bfloat16 h2 = __float2bfloat16(x.z), h3 = __float2bfloat16(x.w);
    __nv_bfloat16 l0 = __float2bfloat16(x.x - __bfloat162float(h0));
    __nv_bfloat16 l1 = __float2bfloat16(x.y - __bfloat162float(h1));
    __nv_bfloat16 l2 = __float2bfloat16(x.z - __bfloat162float(h2));
    __nv_bfloat16 l3 = __float2bfloat16(x.w - __bfloat162float(h3));
    long o = (long)n*KP + kq;
    __nv_bfloat162 hA; hA.x = h0; hA.y = h1;
    __nv_bfloat162 hB; hB.x = h2; hB.y = h3;
    __nv_bfloat162 lA; lA.x = l0; lA.y = l1;
    __nv_bfloat162 lB; lB.x = l2; lB.y = l3;
    *reinterpret_cast<__nv_bfloat162*>(&g_whi[o])   = hA;
    *reinterpret_cast<__nv_bfloat162*>(&g_whi[o+2]) = hB;
    *reinterpret_cast<__nv_bfloat162*>(&g_wlo[o])   = lA;
    *reinterpret_cast<__nv_bfloat162*>(&g_wlo[o+2]) = lB;
}

// ---------------- fp32x2 tiled GEMM ----------------
__global__ void __launch_bounds__(256, 2)
k_gemm(const float* __restrict__ Ap, int lda,
       const float* __restrict__ Wp, int ldw, int woff,
       const float* __restrict__ bias,
       float* __restrict__ Cp, int ldc,
       int M, int N, int K, int act)
{
    __shared__ float sA[16][128];
    __shared__ float sW[16][128];
    int tid = threadIdx.x;
    int m0 = blockIdx.y * 128, n0 = blockIdx.x * 128;
    int tr = tid & 15, tc = tid >> 4;

    unsigned long long acc[8][4];
    #pragma unroll
    for (int i = 0; i < 8; i++)
        #pragma unroll
        for (int j = 0; j < 4; j++) acc[i][j] = 0ull;

    int r  = tid >> 2;
    int kq = (tid & 3) * 4;

    for (int k0 = 0; k0 < K; k0 += 16) {
        bool kok = (k0 + kq) < K;
        #pragma unroll
        for (int h = 0; h < 2; h++) {
            int row = r + h * 64;
            float4 va = make_float4(0.f, 0.f, 0.f, 0.f);
            int m = m0 + row;
            if (kok && m < M) va = *reinterpret_cast<const float4*>(&Ap[(long)m*lda + k0 + kq]);
            sA[kq+0][row] = va.x; sA[kq+1][row] = va.y;
            sA[kq+2][row] = va.z; sA[kq+3][row] = va.w;

            float4 vw = make_float4(0.f, 0.f, 0.f, 0.f);
            int n = n0 + row;
            if (kok && n < N) vw = *reinterpret_cast<const float4*>(&Wp[(long)n*ldw + woff + k0 + kq]);
            sW[kq+0][row] = vw.x; sW[kq+1][row] = vw.y;
            sW[kq+2][row] = vw.z; sW[kq+3][row] = vw.w;
        }
        __syncthreads();

        #pragma unroll
        for (int kk = 0; kk < 16; kk++) {
            float4 a0 = *reinterpret_cast<const float4*>(&sA[kk][tr*8]);
            float4 a1 = *reinterpret_cast<const float4*>(&sA[kk][tr*8 + 4]);
            unsigned long long bp[4];
            #pragma unroll
            for (int j = 0; j < 4; j++)
                bp[j] = *reinterpret_cast<const unsigned long long*>(&sW[kk][tc*8 + 2*j]);
            float av[8] = {a0.x, a0.y, a0.z, a0.w, a1.x, a1.y, a1.z, a1.w};
            #pragma unroll
            for (int i = 0; i < 8; i++) {
                unsigned long long ap = pk2(av[i], av[i]);
                #pragma unroll
                for (int j = 0; j < 4; j++) fma2(acc[i][j], ap, bp[j]);
            }
        }
        __syncthreads();
    }

    #pragma unroll
    for (int i = 0; i < 8; i++) {
        int m = m0 + tr*8 + i;
        if (m >= M) continue;
        #pragma unroll
        for (int j = 0; j < 4; j++) {
            float2 v = upk2(acc[i][j]);
            int n = n0 + tc*8 + 2*j;
            if (n < N) {
                float c = v.x + (bias ? bias[n] : 0.0f);
                if (act) c = tanhf(c);
                Cp[(long)m*ldc + n] = c;
            }
            if (n + 1 < N) {
                float c = v.y + (bias ? bias[n+1] : 0.0f);
                if (act) c = tanhf(c);
                Cp[(long)m*ldc + n + 1] = c;
            }
        }
    }
}

// ================= mma.sync bf16 logits GEMM (64x128 tile, 2 CTAs/SM) =================
__device__ __forceinline__ uint32_t smem_u32(const void* p) {
    uint32_t a;
    asm("{ .reg .u64 t; cvta.to.shared.u64 t, %1; cvt.u32.u64 %0, t; }" : "=r"(a) : "l"(p));
    return a;
}
__device__ __forceinline__ void cpa16(uint32_t dst, const void* src) {
    asm volatile("cp.async.cg.shared.global [%0], [%1], 16;" :: "r"(dst), "l"(src) : "memory");
}
__device__ __forceinline__ void cpa_commit() {
    asm volatile("cp.async.commit_group;" ::: "memory");
}
__device__ __forceinline__ void ldsm4(uint32_t* r, uint32_t addr) {
    asm volatile("ldmatrix.sync.aligned.m8n8.x4.shared.b16 {%0,%1,%2,%3}, [%4];"
        : "=r"(r[0]), "=r"(r[1]), "=r"(r[2]), "=r"(r[3]) : "r"(addr));
}
__device__ __forceinline__ void mma16816(float* d, const uint32_t* a, const uint32_t* b) {
    asm volatile("mma.sync.aligned.m16n8k16.row.col.f32.bf16.bf16.f32 "
        "{%0,%1,%2,%3}, {%4,%5,%6,%7}, {%8,%9}, {%0,%1,%2,%3};"
        : "+f"(d[0]), "+f"(d[1]), "+f"(d[2]), "+f"(d[3])
        : "r"(a[0]), "r"(a[1]), "r"(a[2]), "r"(a[3]), "r"(b[0]), "r"(b[1]));
}

#define LSTG 49152
#define LOG_SMEM (2*LSTG)

__global__ void __launch_bounds__(256, 2)
k_logits_mma(const float* __restrict__ bias, float* __restrict__ outp)
{
    extern __shared__ __align__(128) char smem[];
    uint32_t sb = smem_u32(smem);
    int tid = threadIdx.x;
    int wid = tid >> 5, lane = tid & 31;
    int wm = wid >> 2, wn = wid & 3;
    int grp = lane >> 3, lr = lane & 7;
    int m0 = blockIdx.x * 64;
    int n0 = blockIdx.y * 128;

    float acc[2][4][4];
    #pragma unroll
    for (int i = 0; i < 2; i++)
        #pragma unroll
        for (int j = 0; j < 4; j++)
            #pragma unroll
            for (int c = 0; c < 4; c++) acc[i][j][c] = 0.0f;

    auto load_stage = [&](int it, int s) {
        int k0 = it * 64;
        uint32_t base = sb + s * LSTG;
        #pragma unroll
        for (int q = 0; q < 2; q++) {
            int u = tid + q * 256;
            int row = u >> 3, c = u & 7;
            uint32_t off = row * 128 + (((uint32_t)(c ^ (row & 7))) << 4);
            long ga = (long)(m0 + row) * KP + k0 + c * 8;
            cpa16(base + off,         g_ahi + ga);
            cpa16(base + 8192 + off,  g_alo + ga);
        }
        #pragma unroll
        for (int q = 0; q < 4; q++) {
            int u = tid + q * 256;
            int row = u >> 3, c = u & 7;
            uint32_t off = row * 128 + (((uint32_t)(c ^ (row & 7))) << 4);
            long gb = (long)(n0 + row) * KP + k0 + c * 8;
            cpa16(base + 16384 + off, g_whi + gb);
            cpa16(base + 32768 + off, g_wlo + gb);
        }
    };

    load_stage(0, 0);
    cpa_commit();

    for (int it = 0; it < KITER; it++) {
        int s = it & 1;
        if (it < KITER - 1) {
            load_stage(it + 1, s ^ 1);
            cpa_commit();
            asm volatile("cp.async.wait_group 1;" ::: "memory");
        } else {
            asm volatile("cp.async.wait_group 0;" ::: "memory");
        }
        __syncthreads();

        uint32_t aAhi = sb + s*LSTG;
        uint32_t aAlo = aAhi + 8192;
        uint32_t aBhi = aAhi + 16384;
        uint32_t aBlo = aAhi + 32768;

        #pragma unroll
        for (int ks = 0; ks < 4; ks++) {
            uint32_t fa_hi[2][4], fa_lo[2][4];
            #pragma unroll
            for (int mt = 0; mt < 2; mt++) {
                int row = wm*32 + mt*16 + lr + (grp & 1) * 8;
                int c = 2*ks + (grp >> 1);
                uint32_t off = row * 128 + (((uint32_t)(c ^ (row & 7))) << 4);
                ldsm4(fa_hi[mt], aAhi + off);
                ldsm4(fa_lo[mt], aAlo + off);
            }
            uint32_t fb_hi[2][4], fb_lo[2][4];
            #pragma unroll
            for (int p = 0; p < 2; p++) {
                int nrow = wn*32 + p*16 + lr + (grp >> 1) * 8;
                int c = 2*ks + (grp & 1);
                uint32_t off = nrow * 128 + (((uint32_t)(c ^ (nrow & 7))) << 4);
                ldsm4(fb_hi[p], aBhi + off);
                ldsm4(fb_lo[p], aBlo + off);
            }
            #pragma unroll
            for (int mt = 0; mt < 2; mt++) {
                #pragma unroll
                for (int nt = 0; nt < 4; nt++) {
                    const uint32_t* bh = &fb_hi[nt >> 1][(nt & 1) * 2];
                    const uint32_t* bl = &fb_lo[nt >> 1][(nt & 1) * 2];
                    mma16816(acc[mt][nt], fa_hi[mt], bh);
                    mma16816(acc[mt][nt], fa_lo[mt], bh);
                    mma16816(acc[mt][nt], fa_hi[mt], bl);
                }
            }
        }
        __syncthreads();
    }

    int mrow = (lane >> 2);
    int ncol = (lane & 3) * 2;
    #pragma unroll
    for (int mt = 0; mt < 2; mt++) {
        #pragma unroll
        for (int nt = 0; nt < 4; nt++) {
            int n = n0 + wn*32 + nt*8 + ncol;
            if (n >= VTT) continue;
            float2 bv = *reinterpret_cast<const float2*>(&bias[n]);
            int m1 = m0 + wm*32 + mt*16 + mrow;
            int m2 = m1 + 8;
            if (m1 < MTOT) {
                float2 v = make_float2(acc[mt][nt][0] + bv.x, acc[mt][nt][1] + bv.y);
                *reinterpret_cast<float2*>(&outp[(long)m1*VTT + n]) = v;
            }
            if (m2 < MTOT) {
                float2 v = make_float2(acc[mt][nt][2] + bv.x, acc[mt][nt][3] + bv.y);
                *reinterpret_cast<float2*>(&outp[(long)m2*VTT + n]) = v;
            }
        }
    }
}

// ================= encoder step kernel =================
__global__ void __launch_bounds__(256, 2)
k_enc_step(int step,
           const float* __restrict__ Whh_f, const float* __restrict__ Whh_b,
           const float* __restrict__ bhh_f, const float* __restrict__ bhh_b)
{
    __shared__ float sA[2][16][32];
    __shared__ float sW[2][16][64];
    int blk = blockIdx.x, tid = threadIdx.x;
    int par = step & 1;
    int dir = blk >= 96;
    int rem = dir ? blk - 96 : blk;
    int ntile = rem >> 2;
    int kc = rem & 3;
    int n0 = ntile * 64;
    int kbase = kc * 128;
    const float* W = dir ? Whh_b : Whh_f;
    const float* h = g_h[dir][par];
    int tm = tid & 15, tn = tid >> 4;
    int r = tid >> 2, kq = (tid & 3) * 4;
    float acc[2][4] = {};
    float4 ra = make_float4(0,0,0,0), rw;

    if (tid < 128) ra = *(const float4*)&h[r*UU + kbase + kq];
    rw = *(const float4*)&W[(long)(n0+r)*UU + kbase + kq];

    int s = 0;
    #pragma unroll
    for (int it = 0; it < 8; it++) {
        if (tid < 128) {
            sA[s][kq+0][r] = ra.x; sA[s][kq+1][r] = ra.y;
            sA[s][kq+2][r] = ra.z; sA[s][kq+3][r] = ra.w;
        }
        sW[s][kq+0][r] = rw.x; sW[s][kq+1][r] = rw.y;
        sW[s][kq+2][r] = rw.z; sW[s][kq+3][r] = rw.w;
        __syncthreads();
        if (it < 7) {
            int k0 = kbase + (it + 1) * 16;
            if (tid < 128) ra = *(const float4*)&h[r*UU + k0 + kq];
            rw = *(const float4*)&W[(long)(n0+r)*UU + k0 + kq];
        }
        #pragma unroll
        for (int kk = 0; kk < 16; kk++) {
            float2 a2 = *reinterpret_cast<const float2*>(&sA[s][kk][tm*2]);
            float4 b4 = *reinterpret_cast<const float4*>(&sW[s][kk][tn*4]);
            acc[0][0] = fmaf(a2.x, b4.x, acc[0][0]);
            acc[0][1] = fmaf(a2.x, b4.y, acc[0][1]);
            acc[0][2] = fmaf(a2.x, b4.z, acc[0][2]);
            acc[0][3] = fmaf(a2.x, b4.w, acc[0][3]);
            acc[1][0] = fmaf(a2.y, b4.x, acc[1][0]);
            acc[1][1] = fmaf(a2.y, b4.y, acc[1][1]);
            acc[1][2] = fmaf(a2.y, b4.z, acc[1][2]);
            acc[1][3] = fmaf(a2.y, b4.w, acc[1][3]);
        }
        s ^= 1;
    }
    float* outp = &g_ghp[dir][kc][0];
    #pragma unroll
    for (int i = 0; i < 2; i++) {
        int b = tm*2 + i;
        #pragma unroll
        for (int j = 0; j < 4; j++)
            outp[b*GG + n0 + tn*4 + j] = acc[i][j];
    }

    gbar(&g_ctr[step], PBLK);

    int tf = step, tb = SS-1-step;
    for (int idx = blk*256 + tid; idx < 2*BB*UU; idx += PBLK*256) {
        int u = idx & 511;
        int b = (idx >> 9) & 31;
        int d2 = idx >> 14;
        const float* gi = d2 ? (g_gi_b + (long)tb*BB*GG) : (g_gi_f + (long)tf*BB*GG);
        const float* bhh = d2 ? bhh_b : bhh_f;
        float ghr = bhh[u], ghz = bhh[u+UU], ghn = bhh[u+2*UU];
        #pragma unroll
        for (int kc2 = 0; kc2 < 4; kc2++) {
            const float* p = &g_ghp[d2][kc2][b*GG];
            ghr += __ldcg(&p[u]); ghz += __ldcg(&p[u+UU]); ghn += __ldcg(&p[u+2*UU]);
        }
        float ir = gi[b*GG + u], iz = gi[b*GG + u + UU], inn = gi[b*GG + u + 2*UU];
        float r2 = fsigm(ir + ghr);
        float z = fsigm(iz + ghz);
        float n = ftanh(inn + r2*ghn);
        float hp = g_h[d2][par][b*UU + u];
        float hn_ = (1.0f - z)*n + z*hp;
        g_h[d2][par^1][b*UU + u] = hn_;
        int sidx = d2 ? tb : tf;
        g_enc[((long)b*SS + sidx)*H2 + d2*UU + u] = hn_;
    }
}

// ================= decoder step kernel =================
__global__ void __launch_bounds__(256, 2)
k_dec_step(int t,
           const float* __restrict__ attn_W,
           const float* __restrict__ Wih, const float* __restrict__ Whh,
           const float* __restrict__ bih, const float* __restrict__ bhh)
{
    __shared__ float sA[2][16][32];
    __shared__ float sW[2][16][64];
    __shared__ float s_st[UU];
    __shared__ float s_sc[SS];
    __shared__ float s_red[2];

    int blk = blockIdx.x, tid = threadIdx.x;
    int tm = tid & 15, tn = tid >> 4;
    int spar = t & 1;
    const float* st_g = g_state[spar];

    if (blk < 32) {
        int b = blk;
        float* s_tp = &sW[0][0][0];
        const float* st = &st_g[b*UU];
        for (int i = tid; i < UU; i += 256) s_st[i] = st[i];
        __syncthreads();
        for (int a = tid; a < AD; a += 256) {
            const float* w = attn_W + (long)a*GG;
            float acc = 0.0f;
            #pragma unroll 4
            for (int k = 0; k < UU; k += 4) {
                float4 wv = *reinterpret_cast<const float4*>(w + k);
                acc = fmaf(s_st[k],   wv.x, acc);
                acc = fmaf(s_st[k+1], wv.y, acc);
                acc = fmaf(s_st[k+2], wv.z, acc);
                acc = fmaf(s_st[k+3], wv.w, acc);
            }
            s_tp[a] = acc;
        }
        __syncthreads();
        {
            int s = tid >> 2, q = tid & 3;
            const float* ep = g_encproj + ((long)b*SS + s)*AD + q*128;
            const float* tp = s_tp + q*128;
            float partial = 0.0f;
            for (int a = 0; a < 128; a++) partial += ftanh(tp[a] + ep[a]);
            partial += __shfl_down_sync(0xffffffffu, partial, 2);
            partial += __shfl_down_sync(0xffffffffu, partial, 1);
            if (q == 0) s_sc[s] = partial;
        }
        __syncthreads();
        if (tid == 0) {
            float mx = s_sc[0];
            for (int s = 1; s < SS; s++) mx = fmaxf(mx, s_sc[s]);
            s_red[0] = mx;
        }
        __syncthreads();
        if (tid < SS) s_sc[tid] = __expf(s_sc[tid] - s_red[0]);
        __syncthreads();
        if (tid == 0) {
            float sm = 0.0f;
            for (int s = 0; s < SS; s++) sm += s_sc[s];
            s_red[1] = 1.0f / sm;
        }
        __syncthreads();
        float inv = s_red[1];
        for (int h = tid; h < H2; h += 256) {
            const float* e = g_enc + (long)b*SS*H2 + h;
            float acc = 0.0f;
            #pragma unroll 8
            for (int s = 0; s < SS; s++) acc = fmaf(s_sc[s], e[(long)s*H2], acc);
            g_ctx[b*H2 + h] = acc * inv;
        }
    } else if (blk < 128) {
        int idx2 = blk - 32;
        int ntile = idx2 >> 2;
        int kc = idx2 & 3;
        int n0 = ntile * 64;
        int kbase = kc * 128;
        int r = tid >> 2, kq = (tid & 3) * 4;
        float acc[2][4] = {};
        float4 ra = make_float4(0,0,0,0), rw;
        if (tid < 128) ra = *(const float4*)&st_g[r*UU + kbase + kq];
        rw = *(const float4*)&Whh[(long)(n0+r)*UU + kbase + kq];
        int s = 0;
        #pragma unroll
        for (int it = 0; it < 8; it++) {
            if (tid < 128) {
                sA[s][kq+0][r] = ra.x; sA[s][kq+1][r] = ra.y;
                sA[s][kq+2][r] = ra.z; sA[s][kq+3][r] = ra.w;
            }
            sW[s][kq+0][r] = rw.x; sW[s][kq+1][r] = rw.y;
            sW[s][kq+2][r] = rw.z; sW[s][kq+3][r] = rw.w;
            __syncthreads();
            if (it < 7) {
                int k0 = kbase + (it + 1) * 16;
                if (tid < 128) ra = *(const float4*)&st_g[r*UU + k0 + kq];
                rw = *(const float4*)&Whh[(long)(n0+r)*UU + k0 + kq];
            }
            #pragma unroll
            for (int kk = 0; kk < 16; kk++) {
                float2 a2 = *reinterpret_cast<const float2*>(&sA[s][kk][tm*2]);
                float4 b4 = *reinterpret_cast<const float4*>(&sW[s][kk][tn*4]);
                acc[0][0] = fmaf(a2.x, b4.x, acc[0][0]);
                acc[0][1] = fmaf(a2.x, b4.y, acc[0][1]);
                acc[0][2] = fmaf(a2.x, b4.z, acc[0][2]);
                acc[0][3] = fmaf(a2.x, b4.w, acc[0][3]);
                acc[1][0] = fmaf(a2.y, b4.x, acc[1][0]);
                acc[1][1] = fmaf(a2.y, b4.y, acc[1][1]);
                acc[1][2] = fmaf(a2.y, b4.z, acc[1][2]);
                acc[1][3] = fmaf(a2.y, b4.w, acc[1][3]);
            }
            s ^= 1;
        }
        float* outp = &g_dgh[kc][0];
        #pragma unroll
        for (int i = 0; i < 2; i++) {
            int b = tm*2 + i;
            #pragma unroll
            for (int j = 0; j < 4; j++)
                outp[b*GG + n0 + tn*4 + j] = acc[i][j];
        }
    }
    gbar(&g_ctr[SS + 2*t], PBLK);

    // ---------- Phase 2: gi ctx-part GEMM (24 ntiles x 8 kc, K=128 each, pipelined) ----------
    {
        int ntile = blk >> 3;
        int kc = blk & 7;
        int n0 = ntile * 64;
        int kbase = kc * 128;           // within ctx's 1024 cols
        int woff = EE + kbase;          // Wih column offset
        int r = tid >> 2, kq = (tid & 3) * 4;
        float acc[2][4] = {};
        float4 ra = make_float4(0,0,0,0), rw;
        if (tid < 128) ra = __ldcg((const float4*)&g_ctx[r*H2 + kbase + kq]);
        rw = *(const float4*)&Wih[(long)(n0+r)*KX + woff + kq];
        int s = 0;
        #pragma unroll
        for (int it = 0; it < 8; it++) {
            if (tid < 128) {
                sA[s][kq+0][r] = ra.x; sA[s][kq+1][r] = ra.y;
                sA[s][kq+2][r] = ra.z; sA[s][kq+3][r] = ra.w;
            }
            sW[s][kq+0][r] = rw.x; sW[s][kq+1][r] = rw.y;
            sW[s][kq+2][r] = rw.z; sW[s][kq+3][r] = rw.w;
            __syncthreads();
            if (it < 7) {
                int k0 = (it + 1) * 16;
                if (tid < 128) ra = __ldcg((const float4*)&g_ctx[r*H2 + kbase + k0 + kq]);
                rw = *(const float4*)&Wih[(long)(n0+r)*KX + woff + k0 + kq];
            }
            #pragma unroll
            for (int kk = 0; kk < 16; kk++) {
                float2 a2 = *reinterpret_cast<const float2*>(&sA[s][kk][tm*2]);
                float4 b4 = *reinterpret_cast<const float4*>(&sW[s][kk][tn*4]);
                acc[0][0] = fmaf(a2.x, b4.x, acc[0][0]);
                acc[0][1] = fmaf(a2.x, b4.y, acc[0][1]);
                acc[0][2] = fmaf(a2.x, b4.z, acc[0][2]);
                acc[0][3] = fmaf(a2.x, b4.w, acc[0][3]);
                acc[1][0] = fmaf(a2.y, b4.x, acc[1][0]);
                acc[1][1] = fmaf(a2.y, b4.y, acc[1][1]);
                acc[1][2] = fmaf(a2.y, b4.z, acc[1][2]);
                acc[1][3] = fmaf(a2.y, b4.w, acc[1][3]);
            }
            s ^= 1;
        }
        float* outp = &g_dgi[kc][0];
        #pragma unroll
        for (int i = 0; i < 2; i++) {
            int b = tm*2 + i;
            #pragma unroll
            for (int j = 0; j < 4; j++)
                outp[b*GG + n0 + tn*4 + j] = acc[i][j];
        }
    }
    gbar(&g_ctr[SS + 2*t + 1], PBLK);

    // ---------- Phase 3: gate + DIRECT bf16 hi/lo feature writes ----------
    for (int idx = blk*256 + tid; idx < BB*FF; idx += PBLK*256) {
        int f = idx % FF; int b = idx / FF;
        long m = (long)t*BB + b;
        float x;
        if (f < UU) {
            int u = f;
            const float* gie = &g_gie[m*GG];
            float gir = bih[u]      + gie[u];
            float giz = bih[u+UU]   + gie[u+UU];
            float gin = bih[u+2*UU] + gie[u+2*UU];
            float ghr = bhh[u], ghz = bhh[u+UU], ghn = bhh[u+2*UU];
            #pragma unroll
            for (int kc = 0; kc < 8; kc++) {
                const float* pi = &g_dgi[kc][b*GG];
                gir += __ldcg(&pi[u]); giz += __ldcg(&pi[u+UU]); gin += __ldcg(&pi[u+2*UU]);
            }
            #pragma unroll
            for (int kc = 0; kc < 4; kc++) {
                const float* ph = &g_dgh[kc][b*GG];
                ghr += __ldcg(&ph[u]); ghz += __ldcg(&ph[u+UU]); ghn += __ldcg(&ph[u+2*UU]);
            }
            float r = fsigm(gir + ghr);
            float z = fsigm(giz + ghz);
            float n = ftanh(gin + r*ghn);
            float hp = st_g[b*UU + u];
            float h2 = (1.0f - z)*n + z*hp;
            g_state[spar^1][b*UU + u] = h2;
            x = h2;
        } else if (f < UU + H2) {
            x = __ldcg(&g_ctx[b*H2 + f - UU]);
        } else {
            x = g_embt[((long)t*BB + b)*EE + f - UU - H2];
        }
        __nv_bfloat16 h = __float2bfloat16(x);
        g_ahi[m*KP + f] = h;
        g_alo[m*KP + f] = __float2bfloat16(x - __bfloat162float(h));
    }
}

// ---------------- host: streams (created at load; not device mem) ----------------
static cudaStream_t g_s2 = nullptr, g_s3 = nullptr;
static cudaEvent_t g_evf = nullptr, g_evd = nullptr, g_evsrc = nullptr, g_evtrg = nullptr,
                   g_evgib = nullptr, g_evenc = nullptr, g_evprj = nullptr;
namespace {
struct StreamInit {
    StreamInit() {
        cudaStreamCreateWithFlags(&g_s2, cudaStreamNonBlocking);
        cudaStreamCreateWithFlags(&g_s3, cudaStreamNonBlocking);
        cudaEventCreateWithFlags(&g_evf,  cudaEventDisableTiming);
        cudaEventCreateWithFlags(&g_evd,  cudaEventDisableTiming);
        cudaEventCreateWithFlags(&g_evsrc, cudaEventDisableTiming);
        cudaEventCreateWithFlags(&g_evtrg, cudaEventDisableTiming);
        cudaEventCreateWithFlags(&g_evgib, cudaEventDisableTiming);
        cudaEventCreateWithFlags(&g_evenc, cudaEventDisableTiming);
        cudaEventCreateWithFlags(&g_evprj, cudaEventDisableTiming);
    }
};
StreamInit g_stream_init;
}

static float* symaddr(const void* sym) {
    void* p = nullptr;
    cudaGetSymbolAddress(&p, sym);
    return (float*)p;
}

extern "C" void kernel_launch(void* const* d_in, const int* in_sizes, int n_in,
                              void* d_out, int out_size)
{
    const float* emb_src   = (const float*)d_in[0];
    const float* emb_trg   = (const float*)d_in[1];
    const float* enc_Wih_f = (const float*)d_in[2];
    const float* enc_Whh_f = (const float*)d_in[3];
    const float* enc_bih_f = (const float*)d_in[4];
    const float* enc_bhh_f = (const float*)d_in[5];
    const float* enc_Wih_b = (const float*)d_in[6];
    const float* enc_Whh_b = (const float*)d_in[7];
    const float* enc_bih_b = (const float*)d_in[8];
    const float* enc_bhh_b = (const float*)d_in[9];
    const float* enc_Wfc   = (const float*)d_in[10];
    const float* enc_bfc   = (const float*)d_in[11];
    const float* attn_W    = (const float*)d_in[12];
    const float* attn_b    = (const float*)d_in[13];
    const float* dec_Wih   = (const float*)d_in[14];
    const float* dec_Whh   = (const float*)d_in[15];
    const float* dec_bih   = (const float*)d_in[16];
    const float* dec_bhh   = (const float*)d_in[17];
    const float* dec_Wfc   = (const float*)d_in[18];
    const float* dec_bfc   = (const float*)d_in[19];
    const int*   source    = (const int*)d_in[20];
    const int*   target    = (const int*)d_in[21];
    float* out = (float*)d_out;

    float* p_emb_s   = symaddr(g_emb_s);
    float* p_gi_f    = symaddr(g_gi_f);
    float* p_gi_b    = symaddr(g_gi_b);
    float* p_h       = symaddr(g_h);
    float* p_enc     = symaddr(g_enc);
    float* p_hfb     = symaddr(g_hfb);
    float* p_state   = symaddr(g_state);
    float* p_encproj = symaddr(g_encproj);
    float* p_embt    = symaddr(g_embt);
    float* p_gie     = symaddr(g_gie);
    float* p_ctr     = symaddr(g_ctr);

    static int attr_set = 0;
    if (!attr_set) {
        cudaFuncSetAttribute(k_logits_mma, cudaFuncAttributeMaxDynamicSharedMemorySize, LOG_SMEM);
        attr_set = 1;
    }

    // fork s2: pad_a, out-zero, split_w (all independent of main chain until logits)
    cudaEventRecord(g_evf, 0);
    cudaStreamWaitEvent(g_s2, g_evf, 0);
    {
        int padn = MP*(KP-FF) + (MP-MTOT)*FF;
        k_pad_a<<<(padn + 255)/256, 256, 0, g_s2>>>();
    }
    k_zero<<<(BB*VTT + 255)/256, 256, 0, g_s2>>>(out, BB*VTT);
    {
        long total = (long)NP * (KP/4);
        k_split_w4<<<(unsigned)((total + 255)/256), 256, 0, g_s2>>>(dec_Wfc);
    }
    cudaEventRecord(g_evd, g_s2);

    // front (main stream)
    k_zero<<<1, 128>>>((float*)p_ctr, SS + 2*TM1);
    k_zero<<<(2*2*BB*UU + 255)/256, 256>>>(p_h, 2*2*BB*UU);
    k_gather_src<<<(SS*BB*EE + 255)/256, 256>>>(emb_src, source);
    cudaEventRecord(g_evsrc, 0);
    k_gather_trg<<<(TM1*BB*EE + 255)/256, 256>>>(emb_trg, target);
    cudaEventRecord(g_evtrg, 0);

    // s3: gi_b (after src gather), then gi_emb precompute (after trg gather)
    cudaStreamWaitEvent(g_s3, g_evsrc, 0);
    {
        dim3 grid(GG/128, (SS*BB)/128);
        k_gemm<<<grid, 256, 0, g_s3>>>(p_emb_s, EE, enc_Wih_b, EE, 0, enc_bih_b,
                                       p_gi_b, GG, SS*BB, GG, EE, 0);
    }
    cudaEventRecord(g_evgib, g_s3);
    cudaStreamWaitEvent(g_s3, g_evtrg, 0);
    {
        dim3 grid(GG/128, (MTOT + 127)/128);
        k_gemm<<<grid, 256, 0, g_s3>>>(p_embt, EE, dec_Wih, KX, 0, nullptr,
                                       p_gie, GG, MTOT, GG, EE, 0);
    }
    {
        dim3 grid(GG/128, (SS*BB)/128);
        k_gemm<<<grid, 256>>>(p_emb_s, EE, enc_Wih_f, EE, 0, enc_bih_f,
                              p_gi_f, GG, SS*BB, GG, EE, 0);
    }
    cudaStreamWaitEvent(0, g_evgib, 0);

    // encoder recurrence
    for (int i = 0; i < SS; i++) {
        k_enc_step<<<PBLK, 256>>>(i, enc_Whh_f, enc_Whh_b, enc_bhh_f, enc_bhh_b);
    }
    cudaEventRecord(g_evenc, 0);

    // encproj on s3 (reads g_enc)
    cudaStreamWaitEvent(g_s3, g_evenc, 0);
    {
        dim3 grid(AD/128, (BB*SS)/128);
        k_gemm<<<grid, 256, 0, g_s3>>>(p_enc, H2, attn_W, GG, UU, attn_b,
                                       p_encproj, AD, BB*SS, AD, H2, 0);
    }
    cudaEventRecord(g_evprj, g_s3);

    k_concat_hfb<<<(BB*H2 + 255)/256, 256>>>();
    {
        dim3 grid((UU + 127)/128, 1);
        k_gemm<<<grid, 256>>>(p_hfb, H2, enc_Wfc, H2, 0, enc_bfc,
                              p_state, UU, BB, UU, H2, 1);
    }
    cudaStreamWaitEvent(0, g_evprj, 0);   // also implies g_gie done (same stream, earlier)

    // decoder recurrence
    for (int t = 0; t < TM1; t++) {
        k_dec_step<<<PBLK, 256>>>(t, attn_W, dec_Wih, dec_Whh, dec_bih, dec_bhh);
    }

    // join split_w (+ pad_a + out zero), then logits
    cudaStreamWaitEvent(0, g_evd, 0);
    {
        dim3 grid(MP/64, NP/128);
        k_logits_mma<<<grid, 256, LOG_SMEM>>>(dec_bfc, out + (long)BB*VTT);
    }
}